// round 5
// baseline (speedup 1.0000x reference)
#include <cuda_runtime.h>
#include <cuda_bf16.h>
#include <cstdint>
#include <math.h>

#define SEQLEN 2048
#define DIM    4096
#define NH     32
#define HD     128
#define NKV    8
#define QKV_N  6144
#define KV_ROW 1024
#define WIN    4096
#define SCALE  0.08838834764831845f
#define K3     12288

// ---------------- scratch (device globals) ----------------------------------
__device__ float g_xqkv[SEQLEN * QKV_N];
__device__ float g_q   [SEQLEN * NH * HD];
__device__ float g_attn[SEQLEN * NH * HD];
__device__ __nv_bfloat16 g_xc   [(size_t)SEQLEN * K3];
__device__ __nv_bfloat16 g_attnc[(size_t)SEQLEN * K3];
__device__ __nv_bfloat16 g_wqkvc[(size_t)QKV_N * K3];
__device__ __nv_bfloat16 g_woc  [(size_t)DIM * K3];
__device__ __nv_bfloat16 g_qhi[(size_t)NH  * SEQLEN * HD];
__device__ __nv_bfloat16 g_qlo[(size_t)NH  * SEQLEN * HD];
__device__ __nv_bfloat16 g_khi[(size_t)NKV * SEQLEN * HD];
__device__ __nv_bfloat16 g_klo[(size_t)NKV * SEQLEN * HD];
__device__ __nv_bfloat16 g_vhi[(size_t)NKV * SEQLEN * HD];
__device__ __nv_bfloat16 g_vlo[(size_t)NKV * SEQLEN * HD];

// ---------------- common PTX helpers ----------------------------------------
__device__ __forceinline__ void cp16(uint32_t d, const void* g) {
    asm volatile("cp.async.cg.shared.global [%0], [%1], 16;\n"
                 :: "r"(d), "l"(__cvta_generic_to_global(g)) : "memory");
}
__device__ __forceinline__ void ldm4(uint32_t& r0, uint32_t& r1,
                                     uint32_t& r2, uint32_t& r3, uint32_t a) {
    asm volatile("ldmatrix.sync.aligned.m8n8.x4.shared.b16 {%0,%1,%2,%3}, [%4];"
                 : "=r"(r0), "=r"(r1), "=r"(r2), "=r"(r3) : "r"(a));
}
__device__ __forceinline__ void ldm4t(uint32_t& r0, uint32_t& r1,
                                      uint32_t& r2, uint32_t& r3, uint32_t a) {
    asm volatile("ldmatrix.sync.aligned.m8n8.x4.trans.shared.b16 {%0,%1,%2,%3}, [%4];"
                 : "=r"(r0), "=r"(r1), "=r"(r2), "=r"(r3) : "r"(a));
}
__device__ __forceinline__ void mma16816(float* c, const uint32_t* a,
                                         const uint32_t* b) {
    asm volatile(
        "mma.sync.aligned.m16n8k16.row.col.f32.bf16.bf16.f32 "
        "{%0,%1,%2,%3}, {%4,%5,%6,%7}, {%8,%9}, {%0,%1,%2,%3};"
        : "+f"(c[0]), "+f"(c[1]), "+f"(c[2]), "+f"(c[3])
        : "r"(a[0]), "r"(a[1]), "r"(a[2]), "r"(a[3]), "r"(b[0]), "r"(b[1]));
}
__device__ __forceinline__ void split2(float x, float y, uint32_t& hi, uint32_t& lo) {
    __nv_bfloat162 h = __floats2bfloat162_rn(x, y);
    float rx = x - __bfloat162float(h.x);
    float ry = y - __bfloat162float(h.y);
    __nv_bfloat162 r = __floats2bfloat162_rn(rx, ry);
    hi = *(uint32_t*)&h; lo = *(uint32_t*)&r;
}

// ---------------- fp32 -> split-bf16 (tripled-K GEMM operands) --------------
__global__ __launch_bounds__(256) void convert_split(
    const float* __restrict__ in, __nv_bfloat16* __restrict__ out,
    int K, int isA, long long total4)
{
    long long i = (long long)blockIdx.x * 256 + threadIdx.x;
    if (i >= total4) return;
    int k4 = K >> 2;
    long long row = i / k4;
    int c = (int)(i - row * k4);
    float4 v = ((const float4*)in)[i];
    float vv[4] = {v.x, v.y, v.z, v.w};
    union { unsigned long long u; __nv_bfloat16 h[4]; } hi, lo;
#pragma unroll
    for (int j = 0; j < 4; j++) {
        __nv_bfloat16 h = __float2bfloat16(vv[j]);
        hi.h[j] = h;
        lo.h[j] = __float2bfloat16(vv[j] - __bfloat162float(h));
    }
    size_t base = (size_t)row * (3 * K) + (size_t)c * 4;
    *(unsigned long long*)(out + base)         = hi.u;
    *(unsigned long long*)(out + base + K)     = isA ? lo.u : hi.u;
    *(unsigned long long*)(out + base + 2 * K) = isA ? hi.u : lo.u;
}

// ---------------- mma.sync bf16 GEMM: CTA 128x256, warp 64x64 ---------------
#define KC       32
#define NCHUNK   (K3 / KC)               // 384
#define RSTRIDE  80                      // 64B data + 16B pad
#define A_ROWS   128
#define B_ROWS   256
#define ATILEB   (A_ROWS * RSTRIDE)      // 10240
#define BTILEB   (B_ROWS * RSTRIDE)      // 20480
#define STAGEB   (ATILEB + BTILEB)       // 30720
#define GSTAGES  4
#define GEMM_SMEM (GSTAGES * STAGEB)     // 122880

__global__ __launch_bounds__(256, 1) void gemm_mma(
    const __nv_bfloat16* __restrict__ A, const __nv_bfloat16* __restrict__ B,
    float* __restrict__ C, int N)
{
    extern __shared__ __align__(128) char smraw[];
    const uint32_t sb = (uint32_t)__cvta_generic_to_shared(smraw);

    const int tid = threadIdx.x;
    const int w   = tid >> 5;
    const int l   = tid & 31;
    const int wm  = w & 1;          // 0-1 : 64-row slab
    const int wn  = w >> 1;         // 0-3 : 64-col slab

    const char* Ab = (const char*)(A + (size_t)blockIdx.y * 128 * K3);
    const char* Bb = (const char*)(B + (size_t)blockIdx.x * 256 * K3);

    auto load_chunk = [&](int t, int stg) {
        const size_t gk = (size_t)t * 64;
        uint32_t sa  = sb + stg * STAGEB;
        uint32_t sbB = sa + ATILEB;
#pragma unroll
        for (int j = 0; j < 2; j++) {           // A: 512 slots
            int slot = tid + j * 256;
            int r = slot >> 2, c = (slot & 3) * 16;
            cp16(sa + r * RSTRIDE + c, Ab + (size_t)r * (K3 * 2) + gk + c);
        }
#pragma unroll
        for (int j = 0; j < 4; j++) {           // B: 1024 slots
            int slot = tid + j * 256;
            int r = slot >> 2, c = (slot & 3) * 16;
            cp16(sbB + r * RSTRIDE + c, Bb + (size_t)r * (K3 * 2) + gk + c);
        }
    };

    // ldmatrix lane offsets
    const uint32_t aoff = (uint32_t)((wm * 64 + (l & 15)) * RSTRIDE + (l >> 4) * 16);
    const int l2 = l & 7, sel = l >> 3;
    const uint32_t boff = (uint32_t)(ATILEB + (wn * 64 + (sel >> 1) * 8 + l2) * RSTRIDE
                                     + (sel & 1) * 16);

    float acc[4][8][4];
#pragma unroll
    for (int mt = 0; mt < 4; mt++)
#pragma unroll
        for (int nt = 0; nt < 8; nt++)
#pragma unroll
            for (int i = 0; i < 4; i++) acc[mt][nt][i] = 0.f;

    for (int t = 0; t < GSTAGES - 1; t++) {
        load_chunk(t, t);
        asm volatile("cp.async.commit_group;" ::: "memory");
    }

    for (int k = 0; k < NCHUNK; k++) {
        asm volatile("cp.async.wait_group 2;" ::: "memory");
        __syncthreads();

        int t = k + GSTAGES - 1;
        if (t < NCHUNK) load_chunk(t, t & (GSTAGES - 1));
        asm volatile("cp.async.commit_group;" ::: "memory");

        const uint32_t stage = sb + (k & (GSTAGES - 1)) * STAGEB;
#pragma unroll
        for (int ks = 0; ks < 2; ks++) {
            uint32_t a[4][4], b[8][2];
#pragma unroll
            for (int mt = 0; mt < 4; mt++)
                ldm4(a[mt][0], a[mt][1], a[mt][2], a[mt][3],
                     stage + aoff + mt * (16 * RSTRIDE) + ks * 32);
#pragma unroll
            for (int np = 0; np < 4; np++)
                ldm4(b[2*np][0], b[2*np][1], b[2*np+1][0], b[2*np+1][1],
                     stage + boff + np * (16 * RSTRIDE) + ks * 32);
#pragma unroll
            for (int mt = 0; mt < 4; mt++)
#pragma unroll
                for (int nt = 0; nt < 8; nt++)
                    mma16816(acc[mt][nt], a[mt], b[nt]);
        }
    }

    const int crow = blockIdx.y * 128 + wm * 64 + (l >> 2);
    const int ccol = blockIdx.x * 256 + wn * 64 + (l & 3) * 2;
#pragma unroll
    for (int mt = 0; mt < 4; mt++) {
#pragma unroll
        for (int nt = 0; nt < 8; nt++) {
            float* p0 = C + (size_t)(crow + mt * 16)     * N + ccol + nt * 8;
            float* p1 = C + (size_t)(crow + mt * 16 + 8) * N + ccol + nt * 8;
            *(float2*)p0 = make_float2(acc[mt][nt][0], acc[mt][nt][1]);
            *(float2*)p1 = make_float2(acc[mt][nt][2], acc[mt][nt][3]);
        }
    }
}

// ---------------- RoPE + scale-fold + cache write ---------------------------
__global__ __launch_bounds__(256) void rope_kernel(
    const float* __restrict__ xqkv,
    const float* __restrict__ cosf_, const float* __restrict__ sinf_,
    float* __restrict__ qout, float* __restrict__ kcache, float* __restrict__ vcache)
{
    const int s   = blockIdx.x;
    const int tid = threadIdx.x;
    const float* row = xqkv + (size_t)s * QKV_N;

    for (int p = tid; p < NH * 64; p += 256) {
        int h = p >> 6, f = p & 63;
        float c  = cosf_[s * 64 + f];
        float sn = sinf_[s * 64 + f];
        float x1 = row[h * HD + 2 * f];
        float x2 = row[h * HD + 2 * f + 1];
        qout[(size_t)s * (NH * HD) + h * HD + 2 * f]     = (x1 * c - x2 * sn) * SCALE;
        qout[(size_t)s * (NH * HD) + h * HD + 2 * f + 1] = (x1 * sn + x2 * c) * SCALE;
    }
    for (int p = tid; p < NKV * 64; p += 256) {
        int h = p >> 6, f = p & 63;
        float c  = cosf_[s * 64 + f];
        float sn = sinf_[s * 64 + f];
        float x1 = row[DIM + h * HD + 2 * f];
        float x2 = row[DIM + h * HD + 2 * f + 1];
        kcache[(size_t)s * KV_ROW + h * HD + 2 * f]     = x1 * c - x2 * sn;
        kcache[(size_t)s * KV_ROW + h * HD + 2 * f + 1] = x1 * sn + x2 * c;
    }
    for (int i = tid; i < KV_ROW; i += 256)
        vcache[(size_t)s * KV_ROW + i] = row[DIM + NKV * HD + i];
}

// ---------------- q / kv split-bf16 prep for attention ----------------------
__global__ __launch_bounds__(256) void qsplit(
    const float* __restrict__ q,
    __nv_bfloat16* __restrict__ qhi, __nv_bfloat16* __restrict__ qlo)
{
    const int s = blockIdx.x, tid = threadIdx.x;
    for (int i = tid; i < NH * HD; i += 256) {
        int h = i >> 7, d = i & 127;
        float v = q[(size_t)s * (NH * HD) + i];
        __nv_bfloat16 hv = __float2bfloat16(v);
        size_t o = ((size_t)h * SEQLEN + s) * HD + d;
        qhi[o] = hv;
        qlo[o] = __float2bfloat16(v - __bfloat162float(hv));
    }
}
__global__ __launch_bounds__(256) void kvsplit(
    const float* __restrict__ kc, const float* __restrict__ vc,
    __nv_bfloat16* __restrict__ khi, __nv_bfloat16* __restrict__ klo,
    __nv_bfloat16* __restrict__ vhi, __nv_bfloat16* __restrict__ vlo)
{
    const int s = blockIdx.x, tid = threadIdx.x;
    for (int i = tid; i < NKV * HD; i += 256) {
        int h = i >> 7, d = i & 127;
        size_t o = ((size_t)h * SEQLEN + s) * HD + d;
        float kv = kc[(size_t)s * KV_ROW + i];
        __nv_bfloat16 kh = __float2bfloat16(kv);
        khi[o] = kh;
        klo[o] = __float2bfloat16(kv - __bfloat162float(kh));
        float vv = vc[(size_t)s * KV_ROW + i];
        __nv_bfloat16 vh = __float2bfloat16(vv);
        vhi[o] = vh;
        vlo[o] = __float2bfloat16(vv - __bfloat162float(vh));
    }
}

// ---------------- tensor-core causal flash attention (double-buffered) ------
#define ASTRIDE 272
#define ATILE   (64 * ASTRIDE)             // 17408 per operand tile
#define ABUF    (4 * ATILE)                // Khi|Klo|Vhi|Vlo = 69632
#define ATTN_SMEM (2 * ABUF)               // 139264

__global__ __launch_bounds__(256, 1) void attn_tc(
    const __nv_bfloat16* __restrict__ Qh, const __nv_bfloat16* __restrict__ Ql,
    const __nv_bfloat16* __restrict__ Kh, const __nv_bfloat16* __restrict__ Kl,
    const __nv_bfloat16* __restrict__ Vh, const __nv_bfloat16* __restrict__ Vl,
    float* __restrict__ O)
{
    extern __shared__ __align__(128) char smraw[];
    const uint32_t sb = (uint32_t)__cvta_generic_to_shared(smraw);
    const int tid = threadIdx.x, w = tid >> 5, l = tid & 31;
    const int qt  = (int)gridDim.x - 1 - (int)blockIdx.x;
    const int h   = blockIdx.y;
    const int kvh = h >> 2;

    // ---- Q tile (hi, lo) -> registers via smem staging ----------------------
    uint32_t qh_[8][4], ql_[8][4];
    {
        const uint32_t aoff = sb + (uint32_t)((w * 16 + (l & 15)) * ASTRIDE
                                              + (l >> 4) * 16);
        for (int part = 0; part < 2; part++) {
            const __nv_bfloat16* src = part ? Ql : Qh;
            const char* g0 = (const char*)(src + ((size_t)h * SEQLEN + qt * 128) * HD);
            for (int i = tid; i < 2048; i += 256)
                cp16(sb + (uint32_t)((i >> 4) * ASTRIDE + (i & 15) * 16),
                     g0 + (size_t)i * 16);
            asm volatile("cp.async.commit_group;" ::: "memory");
            asm volatile("cp.async.wait_group 0;" ::: "memory");
            __syncthreads();
            uint32_t (*dst)[4] = part ? ql_ : qh_;
#pragma unroll
            for (int g = 0; g < 8; g++)
                ldm4(dst[g][0], dst[g][1], dst[g][2], dst[g][3], aoff + g * 32);
            __syncthreads();
        }
    }

    float o[16][4];
#pragma unroll
    for (int t = 0; t < 16; t++)
#pragma unroll
        for (int i = 0; i < 4; i++) o[t][i] = 0.f;
    float m0 = -1e30f, m1 = -1e30f, l0 = 0.f, l1 = 0.f;

    const int row0 = qt * 128 + w * 16 + (l >> 2);
    const int l2 = l & 7, sel = l >> 3;
    const int nkb = 2 * qt + 2;

    auto load_kv = [&](int kb, uint32_t bufbase) {
        const size_t gbase = (((size_t)kvh * SEQLEN + (size_t)kb * 64) * HD) * 2;
        for (int i = tid; i < 1024; i += 256) {
            uint32_t soff = (uint32_t)((i >> 4) * ASTRIDE + (i & 15) * 16);
            size_t goff = gbase + (size_t)i * 16;
            cp16(bufbase + 0 * ATILE + soff, (const char*)Kh + goff);
            cp16(bufbase + 1 * ATILE + soff, (const char*)Kl + goff);
            cp16(bufbase + 2 * ATILE + soff, (const char*)Vh + goff);
            cp16(bufbase + 3 * ATILE + soff, (const char*)Vl + goff);
        }
        asm volatile("cp.async.commit_group;" ::: "memory");
    };

    int buf = 0;
    load_kv(0, sb);

    for (int kb = 0; kb < nkb; kb++) {
        if (kb + 1 < nkb) {
            load_kv(kb + 1, sb + (buf ^ 1) * ABUF);
            asm volatile("cp.async.wait_group 1;" ::: "memory");
        } else {
            asm volatile("cp.async.wait_group 0;" ::: "memory");
        }
        __syncthreads();
        const uint32_t bbase = sb + buf * ABUF;

        // ---- scores: S = Q K^T (3-term split) -------------------------------
        float sc[8][4];
#pragma unroll
        for (int t = 0; t < 8; t++)
#pragma unroll
            for (int i = 0; i < 4; i++) sc[t][i] = 0.f;

#pragma unroll
        for (int g = 0; g < 8; g++) {
#pragma unroll
            for (int n16 = 0; n16 < 4; n16++) {
                uint32_t kaddr = bbase + (uint32_t)((n16 * 16 + (sel >> 1) * 8 + l2)
                                                    * ASTRIDE + (sel & 1) * 16 + g * 32);
                uint32_t bh[2][2], bl[2][2];
                ldm4(bh[0][0], bh[0][1], bh[1][0], bh[1][1], kaddr);
                ldm4(bl[0][0], bl[0][1], bl[1][0], bl[1][1], kaddr + ATILE);
#pragma unroll
                for (int j = 0; j < 2; j++) {
                    int t = n16 * 2 + j;
                    mma16816(sc[t], qh_[g], bh[j]);
                    mma16816(sc[t], ql_[g], bh[j]);
                    mma16816(sc[t], qh_[g], bl[j]);
                }
            }
        }

        if (kb >= 2 * qt) {
#pragma unroll
            for (int t = 0; t < 8; t++) {
                int col = kb * 64 + t * 8 + 2 * (l & 3);
                if (col     > row0)     sc[t][0] = -1e30f;
                if (col + 1 > row0)     sc[t][1] = -1e30f;
                if (col     > row0 + 8) sc[t][2] = -1e30f;
                if (col + 1 > row0 + 8) sc[t][3] = -1e30f;
            }
        }

        // ---- online softmax --------------------------------------------------
        float r0m = -1e30f, r1m = -1e30f;
#pragma unroll
        for (int t = 0; t < 8; t++) {
            r0m = fmaxf(r0m, fmaxf(sc[t][0], sc[t][1]));
            r1m = fmaxf(r1m, fmaxf(sc[t][2], sc[t][3]));
        }
        r0m = fmaxf(r0m, __shfl_xor_sync(0xffffffffu, r0m, 1));
        r0m = fmaxf(r0m, __shfl_xor_sync(0xffffffffu, r0m, 2));
        r1m = fmaxf(r1m, __shfl_xor_sync(0xffffffffu, r1m, 1));
        r1m = fmaxf(r1m, __shfl_xor_sync(0xffffffffu, r1m, 2));
        float nm0 = fmaxf(m0, r0m), nm1 = fmaxf(m1, r1m);
        float a0 = __expf(m0 - nm0), a1 = __expf(m1 - nm1);

        float s0 = 0.f, s1 = 0.f;
#pragma unroll
        for (int t = 0; t < 8; t++) {
            sc[t][0] = __expf(sc[t][0] - nm0); s0 += sc[t][0];
            sc[t][1] = __expf(sc[t][1] - nm0); s0 += sc[t][1];
            sc[t][2] = __expf(sc[t][2] - nm1); s1 += sc[t][2];
            sc[t][3] = __expf(sc[t][3] - nm1); s1 += sc[t][3];
        }
        s0 += __shfl_xor_sync(0xffffffffu, s0, 1);
        s0 += __shfl_xor_sync(0xffffffffu, s0, 2);
        s1 += __shfl_xor_sync(0xffffffffu, s1, 1);
        s1 += __shfl_xor_sync(0xffffffffu, s1, 2);
        l0 = l0 * a0 + s0;
        l1 = l1 * a1 + s1;
        m0 = nm0; m1 = nm1;
#pragma unroll
        for (int t = 0; t < 16; t++) {
            o[t][0] *= a0; o[t][1] *= a0;
            o[t][2] *= a1; o[t][3] *= a1;
        }

        // ---- O += P V (3-term split, P from registers) ----------------------
#pragma unroll
        for (int g = 0; g < 4; g++) {
            uint32_t aph[4], apl[4];
            split2(sc[2*g][0],   sc[2*g][1],   aph[0], apl[0]);
            split2(sc[2*g][2],   sc[2*g][3],   aph[1], apl[1]);
            split2(sc[2*g+1][0], sc[2*g+1][1], aph[2], apl[2]);
            split2(sc[2*g+1][2], sc[2*g+1][3], aph[3], apl[3]);
#pragma unroll
            for (int n16 = 0; n16 < 8; n16++) {
                uint32_t vaddr = bbase + 2 * ATILE
                    + (uint32_t)((g * 16 + (l & 15)) * ASTRIDE
                                 + n16 * 32 + (l >> 4) * 16);
                uint32_t bvh[2][2], bvl[2][2];
                ldm4t(bvh[0][0], bvh[0][1], bvh[1][0], bvh[1][1], vaddr);
                ldm4t(bvl[0][0], bvl[0][1], bvl[1][0], bvl[1][1], vaddr + ATILE);
#pragma unroll
                for (int j = 0; j < 2; j++) {
                    int t = n16 * 2 + j;
                    mma16816(o[t], aph, bvh[j]);
                    mma16816(o[t], apl, bvh[j]);
                    mma16816(o[t], aph, bvl[j]);
                }
            }
        }
        __syncthreads();
        buf ^= 1;
    }

    float i0 = 1.f / l0, i1 = 1.f / l1;
    const int colb = h * HD + 2 * (l & 3);
#pragma unroll
    for (int t = 0; t < 16; t++) {
        float* p0 = O + (size_t)row0 * (NH * HD) + colb + t * 8;
        float* p1 = O + (size_t)(row0 + 8) * (NH * HD) + colb + t * 8;
        *(float2*)p0 = make_float2(o[t][0] * i0, o[t][1] * i0);
        *(float2*)p1 = make_float2(o[t][2] * i1, o[t][3] * i1);
    }
}

// ---------------- launch ----------------------------------------------------
extern "C" void kernel_launch(void* const* d_in, const int* in_sizes, int n_in,
                              void* d_out, int out_size)
{
    const float* x     = (const float*)d_in[0];
    const float* cosf_ = (const float*)d_in[1];
    const float* sinf_ = (const float*)d_in[2];
    const float* in_ck = (const float*)d_in[5];
    const float* in_cv = (const float*)d_in[6];
    const float* Wqkv  = (const float*)d_in[7];
    const float* Wo    = (const float*)d_in[8];

    float* out     = (float*)d_out;
    float* cache_k = out + (size_t)SEQLEN * DIM;
    float* cache_v = cache_k + (size_t)WIN * KV_ROW;

    float *xqkv_p, *q_p, *attn_p;
    __nv_bfloat16 *xc_p, *attnc_p, *wqkvc_p, *woc_p;
    __nv_bfloat16 *qhi_p, *qlo_p, *khi_p, *klo_p, *vhi_p, *vlo_p;
    cudaGetSymbolAddress((void**)&xqkv_p,  g_xqkv);
    cudaGetSymbolAddress((void**)&q_p,     g_q);
    cudaGetSymbolAddress((void**)&attn_p,  g_attn);
    cudaGetSymbolAddress((void**)&xc_p,    g_xc);
    cudaGetSymbolAddress((void**)&attnc_p, g_attnc);
    cudaGetSymbolAddress((void**)&wqkvc_p, g_wqkvc);
    cudaGetSymbolAddress((void**)&woc_p,   g_woc);
    cudaGetSymbolAddress((void**)&qhi_p,   g_qhi);
    cudaGetSymbolAddress((void**)&qlo_p,   g_qlo);
    cudaGetSymbolAddress((void**)&khi_p,   g_khi);
    cudaGetSymbolAddress((void**)&klo_p,   g_klo);
    cudaGetSymbolAddress((void**)&vhi_p,   g_vhi);
    cudaGetSymbolAddress((void**)&vlo_p,   g_vlo);

    size_t cache_bytes = (size_t)WIN * KV_ROW * sizeof(float);
    cudaMemcpyAsync(cache_k, in_ck, cache_bytes, cudaMemcpyDeviceToDevice, 0);
    cudaMemcpyAsync(cache_v, in_cv, cache_bytes, cudaMemcpyDeviceToDevice, 0);

    cudaFuncSetAttribute(gemm_mma, cudaFuncAttributeMaxDynamicSharedMemorySize,
                         GEMM_SMEM);
    cudaFuncSetAttribute(attn_tc, cudaFuncAttributeMaxDynamicSharedMemorySize,
                         ATTN_SMEM);

    {
        long long t4;
        t4 = (long long)SEQLEN * DIM / 4;
        convert_split<<<(unsigned)((t4 + 255) / 256), 256>>>(x, xc_p, DIM, 1, t4);
        t4 = (long long)QKV_N * DIM / 4;
        convert_split<<<(unsigned)((t4 + 255) / 256), 256>>>(Wqkv, wqkvc_p, DIM, 0, t4);
        t4 = (long long)DIM * DIM / 4;
        convert_split<<<(unsigned)((t4 + 255) / 256), 256>>>(Wo, woc_p, DIM, 0, t4);
    }

    // 1) QKV projection (tensor cores): 6144/256 x 2048/128
    gemm_mma<<<dim3(QKV_N / 256, SEQLEN / 128), 256, GEMM_SMEM>>>(
        xc_p, wqkvc_p, xqkv_p, QKV_N);

    // 2) RoPE + cache writes
    rope_kernel<<<SEQLEN, 256>>>(xqkv_p, cosf_, sinf_, q_p, cache_k, cache_v);

    // 3) split q/k/v to bf16 hi/lo, head-major
    qsplit<<<SEQLEN, 256>>>(q_p, qhi_p, qlo_p);
    kvsplit<<<SEQLEN, 256>>>(cache_k, cache_v, khi_p, klo_p, vhi_p, vlo_p);

    // 4) tensor-core causal flash attention
    attn_tc<<<dim3(SEQLEN / 128, NH), 256, ATTN_SMEM>>>(
        qhi_p, qlo_p, khi_p, klo_p, vhi_p, vlo_p, attn_p);

    // 5) output projection (tensor cores)
    {
        long long t4 = (long long)SEQLEN * DIM / 4;
        convert_split<<<(unsigned)((t4 + 255) / 256), 256>>>(attn_p, attnc_p, DIM, 1, t4);
    }
    gemm_mma<<<dim3(DIM / 256, SEQLEN / 128), 256, GEMM_SMEM>>>(
        attnc_p, woc_p, out, DIM);
}

// round 6
// speedup vs baseline: 1.2256x; 1.2256x over previous
#include <cuda_runtime.h>
#include <cuda_bf16.h>
#include <cstdint>
#include <math.h>

#define SEQLEN 2048
#define DIM    4096
#define NH     32
#define HD     128
#define NKV    8
#define QKV_N  6144
#define KV_ROW 1024
#define WIN    4096
#define SCALE  0.08838834764831845f

// ---------------- scratch (device globals) ----------------------------------
__device__ float g_xqkv[SEQLEN * QKV_N];
__device__ float g_q   [SEQLEN * NH * HD];
__device__ float g_attn[SEQLEN * NH * HD];
// hi/lo split operands (K = 4096 each)
__device__ __nv_bfloat16 g_xh [(size_t)SEQLEN * DIM];
__device__ __nv_bfloat16 g_xl [(size_t)SEQLEN * DIM];
__device__ __nv_bfloat16 g_ah [(size_t)SEQLEN * DIM];
__device__ __nv_bfloat16 g_al [(size_t)SEQLEN * DIM];
__device__ __nv_bfloat16 g_wqh[(size_t)QKV_N * DIM];
__device__ __nv_bfloat16 g_wql[(size_t)QKV_N * DIM];
__device__ __nv_bfloat16 g_woh[(size_t)DIM * DIM];
__device__ __nv_bfloat16 g_wol[(size_t)DIM * DIM];
// attention split q/k/v: [head][seq][HD]
__device__ __nv_bfloat16 g_qhi[(size_t)NH  * SEQLEN * HD];
__device__ __nv_bfloat16 g_qlo[(size_t)NH  * SEQLEN * HD];
__device__ __nv_bfloat16 g_khi[(size_t)NKV * SEQLEN * HD];
__device__ __nv_bfloat16 g_klo[(size_t)NKV * SEQLEN * HD];
__device__ __nv_bfloat16 g_vhi[(size_t)NKV * SEQLEN * HD];
__device__ __nv_bfloat16 g_vlo[(size_t)NKV * SEQLEN * HD];

// ---------------- common PTX helpers ----------------------------------------
__device__ __forceinline__ void cp16(uint32_t d, const void* g) {
    asm volatile("cp.async.cg.shared.global [%0], [%1], 16;\n"
                 :: "r"(d), "l"(__cvta_generic_to_global(g)) : "memory");
}
__device__ __forceinline__ void ldm4(uint32_t& r0, uint32_t& r1,
                                     uint32_t& r2, uint32_t& r3, uint32_t a) {
    asm volatile("ldmatrix.sync.aligned.m8n8.x4.shared.b16 {%0,%1,%2,%3}, [%4];"
                 : "=r"(r0), "=r"(r1), "=r"(r2), "=r"(r3) : "r"(a));
}
__device__ __forceinline__ void ldm4t(uint32_t& r0, uint32_t& r1,
                                      uint32_t& r2, uint32_t& r3, uint32_t a) {
    asm volatile("ldmatrix.sync.aligned.m8n8.x4.trans.shared.b16 {%0,%1,%2,%3}, [%4];"
                 : "=r"(r0), "=r"(r1), "=r"(r2), "=r"(r3) : "r"(a));
}
__device__ __forceinline__ void mma16816(float* c, const uint32_t* a,
                                         const uint32_t* b) {
    asm volatile(
        "mma.sync.aligned.m16n8k16.row.col.f32.bf16.bf16.f32 "
        "{%0,%1,%2,%3}, {%4,%5,%6,%7}, {%8,%9}, {%0,%1,%2,%3};"
        : "+f"(c[0]), "+f"(c[1]), "+f"(c[2]), "+f"(c[3])
        : "r"(a[0]), "r"(a[1]), "r"(a[2]), "r"(a[3]), "r"(b[0]), "r"(b[1]));
}
__device__ __forceinline__ void split2(float x, float y, uint32_t& hi, uint32_t& lo) {
    __nv_bfloat162 h = __floats2bfloat162_rn(x, y);
    float rx = x - __bfloat162float(h.x);
    float ry = y - __bfloat162float(h.y);
    __nv_bfloat162 r = __floats2bfloat162_rn(rx, ry);
    hi = *(uint32_t*)&h; lo = *(uint32_t*)&r;
}

// ---------------- fp32 -> (hi, lo) bf16 arrays -------------------------------
__global__ __launch_bounds__(256) void convert_hilo(
    const float* __restrict__ in, __nv_bfloat16* __restrict__ hi,
    __nv_bfloat16* __restrict__ lo, long long total4)
{
    long long i = (long long)blockIdx.x * 256 + threadIdx.x;
    if (i >= total4) return;
    float4 v = ((const float4*)in)[i];
    float vv[4] = {v.x, v.y, v.z, v.w};
    union { unsigned long long u; __nv_bfloat16 h[4]; } H, L;
#pragma unroll
    for (int j = 0; j < 4; j++) {
        __nv_bfloat16 h = __float2bfloat16(vv[j]);
        H.h[j] = h;
        L.h[j] = __float2bfloat16(vv[j] - __bfloat162float(h));
    }
    ((unsigned long long*)hi)[i] = H.u;
    ((unsigned long long*)lo)[i] = L.u;
}

// ---------------- 3-term hi/lo mma.sync GEMM: C = A * B^T --------------------
// CTA 128x128, 8 warps (2x4), warp 64x32. K = 4096, KC = 32.
#define GK       4096
#define KC       32
#define NCHUNK   (GK / KC)               // 128
#define RSTRIDE  80                      // 64B data + 16B pad
#define PTILEB   (128 * RSTRIDE)         // 10240 per part-tile
#define STAGEB   (4 * PTILEB)            // Ah Al Bh Bl = 40960
#define GSTAGES  2
#define GEMM_SMEM (GSTAGES * STAGEB)     // 81920

__global__ __launch_bounds__(256, 2) void gemm_mma(
    const __nv_bfloat16* __restrict__ Ah, const __nv_bfloat16* __restrict__ Al,
    const __nv_bfloat16* __restrict__ Bh, const __nv_bfloat16* __restrict__ Bl,
    float* __restrict__ C, int N)
{
    extern __shared__ __align__(128) char smraw[];
    const uint32_t sb = (uint32_t)__cvta_generic_to_shared(smraw);

    const int tid = threadIdx.x;
    const int w   = tid >> 5;
    const int l   = tid & 31;
    const int wm  = w & 1;          // 0-1 : 64-row slab
    const int wn  = w >> 1;         // 0-3 : 32-col slab

    const size_t arow = (size_t)blockIdx.y * 128 * GK;
    const size_t brow = (size_t)blockIdx.x * 128 * GK;
    const char* gp[4] = { (const char*)(Ah + arow), (const char*)(Al + arow),
                          (const char*)(Bh + brow), (const char*)(Bl + brow) };

    auto load_chunk = [&](int t, int stg) {
        const size_t gk = (size_t)t * 64;      // byte offset along K
        const uint32_t st = sb + stg * STAGEB;
#pragma unroll
        for (int part = 0; part < 4; part++) {
#pragma unroll
            for (int j = 0; j < 2; j++) {
                int slot = tid + j * 256;      // 512 slots = 128 rows x 4
                int r = slot >> 2, c = (slot & 3) * 16;
                cp16(st + part * PTILEB + r * RSTRIDE + c,
                     gp[part] + (size_t)r * (GK * 2) + gk + c);
            }
        }
    };

    const uint32_t aoff = (uint32_t)((wm * 64 + (l & 15)) * RSTRIDE + (l >> 4) * 16);
    const int l2 = l & 7, sel = l >> 3;
    const uint32_t boff = (uint32_t)((wn * 32 + (sel >> 1) * 8 + l2) * RSTRIDE
                                     + (sel & 1) * 16);

    float acc[4][4][4];
#pragma unroll
    for (int mt = 0; mt < 4; mt++)
#pragma unroll
        for (int nt = 0; nt < 4; nt++)
#pragma unroll
            for (int i = 0; i < 4; i++) acc[mt][nt][i] = 0.f;

    load_chunk(0, 0);
    asm volatile("cp.async.commit_group;" ::: "memory");

    for (int k = 0; k < NCHUNK; k++) {
        if (k + 1 < NCHUNK) {
            load_chunk(k + 1, (k + 1) & 1);
            asm volatile("cp.async.commit_group;" ::: "memory");
            asm volatile("cp.async.wait_group 1;" ::: "memory");
        } else {
            asm volatile("cp.async.wait_group 0;" ::: "memory");
        }
        __syncthreads();

        const uint32_t st = sb + (k & 1) * STAGEB;
#pragma unroll
        for (int ks = 0; ks < 2; ks++) {
            uint32_t ah[4][4], bh[4][2];
#pragma unroll
            for (int mt = 0; mt < 4; mt++)
                ldm4(ah[mt][0], ah[mt][1], ah[mt][2], ah[mt][3],
                     st + aoff + mt * (16 * RSTRIDE) + ks * 32);
#pragma unroll
            for (int np = 0; np < 2; np++)
                ldm4(bh[2*np][0], bh[2*np][1], bh[2*np+1][0], bh[2*np+1][1],
                     st + 2 * PTILEB + boff + np * (16 * RSTRIDE) + ks * 32);
#pragma unroll
            for (int mt = 0; mt < 4; mt++)
#pragma unroll
                for (int nt = 0; nt < 4; nt++)
                    mma16816(acc[mt][nt], ah[mt], bh[nt]);

            uint32_t al[4][4];
#pragma unroll
            for (int mt = 0; mt < 4; mt++)
                ldm4(al[mt][0], al[mt][1], al[mt][2], al[mt][3],
                     st + PTILEB + aoff + mt * (16 * RSTRIDE) + ks * 32);
#pragma unroll
            for (int mt = 0; mt < 4; mt++)
#pragma unroll
                for (int nt = 0; nt < 4; nt++)
                    mma16816(acc[mt][nt], al[mt], bh[nt]);

            uint32_t bl[4][2];
#pragma unroll
            for (int np = 0; np < 2; np++)
                ldm4(bl[2*np][0], bl[2*np][1], bl[2*np+1][0], bl[2*np+1][1],
                     st + 3 * PTILEB + boff + np * (16 * RSTRIDE) + ks * 32);
#pragma unroll
            for (int mt = 0; mt < 4; mt++)
#pragma unroll
                for (int nt = 0; nt < 4; nt++)
                    mma16816(acc[mt][nt], ah[mt], bl[nt]);
        }
        __syncthreads();   // before next iter's cp.async overwrites the other stage
    }

    const int crow = blockIdx.y * 128 + wm * 64 + (l >> 2);
    const int ccol = blockIdx.x * 128 + wn * 32 + (l & 3) * 2;
#pragma unroll
    for (int mt = 0; mt < 4; mt++) {
#pragma unroll
        for (int nt = 0; nt < 4; nt++) {
            float* p0 = C + (size_t)(crow + mt * 16)     * N + ccol + nt * 8;
            float* p1 = C + (size_t)(crow + mt * 16 + 8) * N + ccol + nt * 8;
            *(float2*)p0 = make_float2(acc[mt][nt][0], acc[mt][nt][1]);
            *(float2*)p1 = make_float2(acc[mt][nt][2], acc[mt][nt][3]);
        }
    }
}

// ---------------- RoPE + scale-fold + cache write ---------------------------
__global__ __launch_bounds__(256) void rope_kernel(
    const float* __restrict__ xqkv,
    const float* __restrict__ cosf_, const float* __restrict__ sinf_,
    float* __restrict__ qout, float* __restrict__ kcache, float* __restrict__ vcache)
{
    const int s   = blockIdx.x;
    const int tid = threadIdx.x;
    const float* row = xqkv + (size_t)s * QKV_N;

    for (int p = tid; p < NH * 64; p += 256) {
        int h = p >> 6, f = p & 63;
        float c  = cosf_[s * 64 + f];
        float sn = sinf_[s * 64 + f];
        float x1 = row[h * HD + 2 * f];
        float x2 = row[h * HD + 2 * f + 1];
        qout[(size_t)s * (NH * HD) + h * HD + 2 * f]     = (x1 * c - x2 * sn) * SCALE;
        qout[(size_t)s * (NH * HD) + h * HD + 2 * f + 1] = (x1 * sn + x2 * c) * SCALE;
    }
    for (int p = tid; p < NKV * 64; p += 256) {
        int h = p >> 6, f = p & 63;
        float c  = cosf_[s * 64 + f];
        float sn = sinf_[s * 64 + f];
        float x1 = row[DIM + h * HD + 2 * f];
        float x2 = row[DIM + h * HD + 2 * f + 1];
        kcache[(size_t)s * KV_ROW + h * HD + 2 * f]     = x1 * c - x2 * sn;
        kcache[(size_t)s * KV_ROW + h * HD + 2 * f + 1] = x1 * sn + x2 * c;
    }
    for (int i = tid; i < KV_ROW; i += 256)
        vcache[(size_t)s * KV_ROW + i] = row[DIM + NKV * HD + i];
}

// ---------------- q / kv split-bf16 prep for attention ----------------------
__global__ __launch_bounds__(256) void qsplit(
    const float* __restrict__ q,
    __nv_bfloat16* __restrict__ qhi, __nv_bfloat16* __restrict__ qlo)
{
    const int s = blockIdx.x, tid = threadIdx.x;
    for (int i = tid; i < NH * HD; i += 256) {
        int h = i >> 7, d = i & 127;
        float v = q[(size_t)s * (NH * HD) + i];
        __nv_bfloat16 hv = __float2bfloat16(v);
        size_t o = ((size_t)h * SEQLEN + s) * HD + d;
        qhi[o] = hv;
        qlo[o] = __float2bfloat16(v - __bfloat162float(hv));
    }
}
__global__ __launch_bounds__(256) void kvsplit(
    const float* __restrict__ kc, const float* __restrict__ vc,
    __nv_bfloat16* __restrict__ khi, __nv_bfloat16* __restrict__ klo,
    __nv_bfloat16* __restrict__ vhi, __nv_bfloat16* __restrict__ vlo)
{
    const int s = blockIdx.x, tid = threadIdx.x;
    for (int i = tid; i < NKV * HD; i += 256) {
        int h = i >> 7, d = i & 127;
        size_t o = ((size_t)h * SEQLEN + s) * HD + d;
        float kv = kc[(size_t)s * KV_ROW + i];
        __nv_bfloat16 kh = __float2bfloat16(kv);
        khi[o] = kh;
        klo[o] = __float2bfloat16(kv - __bfloat162float(kh));
        float vv = vc[(size_t)s * KV_ROW + i];
        __nv_bfloat16 vh = __float2bfloat16(vv);
        vhi[o] = vh;
        vlo[o] = __float2bfloat16(vv - __bfloat162float(vh));
    }
}

// ---------------- tensor-core causal flash attention (double-buffered) ------
#define ASTRIDE 272
#define ATILE   (64 * ASTRIDE)
#define ABUF    (4 * ATILE)
#define ATTN_SMEM (2 * ABUF)

__global__ __launch_bounds__(256, 1) void attn_tc(
    const __nv_bfloat16* __restrict__ Qh, const __nv_bfloat16* __restrict__ Ql,
    const __nv_bfloat16* __restrict__ Kh, const __nv_bfloat16* __restrict__ Kl,
    const __nv_bfloat16* __restrict__ Vh, const __nv_bfloat16* __restrict__ Vl,
    float* __restrict__ O)
{
    extern __shared__ __align__(128) char smraw[];
    const uint32_t sb = (uint32_t)__cvta_generic_to_shared(smraw);
    const int tid = threadIdx.x, w = tid >> 5, l = tid & 31;
    const int qt  = (int)gridDim.x - 1 - (int)blockIdx.x;
    const int h   = blockIdx.y;
    const int kvh = h >> 2;

    uint32_t qh_[8][4], ql_[8][4];
    {
        const uint32_t aoff = sb + (uint32_t)((w * 16 + (l & 15)) * ASTRIDE
                                              + (l >> 4) * 16);
        for (int part = 0; part < 2; part++) {
            const __nv_bfloat16* src = part ? Ql : Qh;
            const char* g0 = (const char*)(src + ((size_t)h * SEQLEN + qt * 128) * HD);
            for (int i = tid; i < 2048; i += 256)
                cp16(sb + (uint32_t)((i >> 4) * ASTRIDE + (i & 15) * 16),
                     g0 + (size_t)i * 16);
            asm volatile("cp.async.commit_group;" ::: "memory");
            asm volatile("cp.async.wait_group 0;" ::: "memory");
            __syncthreads();
            uint32_t (*dst)[4] = part ? ql_ : qh_;
#pragma unroll
            for (int g = 0; g < 8; g++)
                ldm4(dst[g][0], dst[g][1], dst[g][2], dst[g][3], aoff + g * 32);
            __syncthreads();
        }
    }

    float o[16][4];
#pragma unroll
    for (int t = 0; t < 16; t++)
#pragma unroll
        for (int i = 0; i < 4; i++) o[t][i] = 0.f;
    float m0 = -1e30f, m1 = -1e30f, l0 = 0.f, l1 = 0.f;

    const int row0 = qt * 128 + w * 16 + (l >> 2);
    const int l2 = l & 7, sel = l >> 3;
    const int nkb = 2 * qt + 2;

    auto load_kv = [&](int kb, uint32_t bufbase) {
        const size_t gbase = (((size_t)kvh * SEQLEN + (size_t)kb * 64) * HD) * 2;
        for (int i = tid; i < 1024; i += 256) {
            uint32_t soff = (uint32_t)((i >> 4) * ASTRIDE + (i & 15) * 16);
            size_t goff = gbase + (size_t)i * 16;
            cp16(bufbase + 0 * ATILE + soff, (const char*)Kh + goff);
            cp16(bufbase + 1 * ATILE + soff, (const char*)Kl + goff);
            cp16(bufbase + 2 * ATILE + soff, (const char*)Vh + goff);
            cp16(bufbase + 3 * ATILE + soff, (const char*)Vl + goff);
        }
        asm volatile("cp.async.commit_group;" ::: "memory");
    };

    int buf = 0;
    load_kv(0, sb);

    for (int kb = 0; kb < nkb; kb++) {
        if (kb + 1 < nkb) {
            load_kv(kb + 1, sb + (buf ^ 1) * ABUF);
            asm volatile("cp.async.wait_group 1;" ::: "memory");
        } else {
            asm volatile("cp.async.wait_group 0;" ::: "memory");
        }
        __syncthreads();
        const uint32_t bbase = sb + buf * ABUF;

        float sc[8][4];
#pragma unroll
        for (int t = 0; t < 8; t++)
#pragma unroll
            for (int i = 0; i < 4; i++) sc[t][i] = 0.f;

#pragma unroll
        for (int g = 0; g < 8; g++) {
#pragma unroll
            for (int n16 = 0; n16 < 4; n16++) {
                uint32_t kaddr = bbase + (uint32_t)((n16 * 16 + (sel >> 1) * 8 + l2)
                                                    * ASTRIDE + (sel & 1) * 16 + g * 32);
                uint32_t bh[2][2], bl[2][2];
                ldm4(bh[0][0], bh[0][1], bh[1][0], bh[1][1], kaddr);
                ldm4(bl[0][0], bl[0][1], bl[1][0], bl[1][1], kaddr + ATILE);
#pragma unroll
                for (int j = 0; j < 2; j++) {
                    int t = n16 * 2 + j;
                    mma16816(sc[t], qh_[g], bh[j]);
                    mma16816(sc[t], ql_[g], bh[j]);
                    mma16816(sc[t], qh_[g], bl[j]);
                }
            }
        }

        if (kb >= 2 * qt) {
#pragma unroll
            for (int t = 0; t < 8; t++) {
                int col = kb * 64 + t * 8 + 2 * (l & 3);
                if (col     > row0)     sc[t][0] = -1e30f;
                if (col + 1 > row0)     sc[t][1] = -1e30f;
                if (col     > row0 + 8) sc[t][2] = -1e30f;
                if (col + 1 > row0 + 8) sc[t][3] = -1e30f;
            }
        }

        float r0m = -1e30f, r1m = -1e30f;
#pragma unroll
        for (int t = 0; t < 8; t++) {
            r0m = fmaxf(r0m, fmaxf(sc[t][0], sc[t][1]));
            r1m = fmaxf(r1m, fmaxf(sc[t][2], sc[t][3]));
        }
        r0m = fmaxf(r0m, __shfl_xor_sync(0xffffffffu, r0m, 1));
        r0m = fmaxf(r0m, __shfl_xor_sync(0xffffffffu, r0m, 2));
        r1m = fmaxf(r1m, __shfl_xor_sync(0xffffffffu, r1m, 1));
        r1m = fmaxf(r1m, __shfl_xor_sync(0xffffffffu, r1m, 2));
        float nm0 = fmaxf(m0, r0m), nm1 = fmaxf(m1, r1m);
        float a0 = __expf(m0 - nm0), a1 = __expf(m1 - nm1);

        float s0 = 0.f, s1 = 0.f;
#pragma unroll
        for (int t = 0; t < 8; t++) {
            sc[t][0] = __expf(sc[t][0] - nm0); s0 += sc[t][0];
            sc[t][1] = __expf(sc[t][1] - nm0); s0 += sc[t][1];
            sc[t][2] = __expf(sc[t][2] - nm1); s1 += sc[t][2];
            sc[t][3] = __expf(sc[t][3] - nm1); s1 += sc[t][3];
        }
        s0 += __shfl_xor_sync(0xffffffffu, s0, 1);
        s0 += __shfl_xor_sync(0xffffffffu, s0, 2);
        s1 += __shfl_xor_sync(0xffffffffu, s1, 1);
        s1 += __shfl_xor_sync(0xffffffffu, s1, 2);
        l0 = l0 * a0 + s0;
        l1 = l1 * a1 + s1;
        m0 = nm0; m1 = nm1;
#pragma unroll
        for (int t = 0; t < 16; t++) {
            o[t][0] *= a0; o[t][1] *= a0;
            o[t][2] *= a1; o[t][3] *= a1;
        }

#pragma unroll
        for (int g = 0; g < 4; g++) {
            uint32_t aph[4], apl[4];
            split2(sc[2*g][0],   sc[2*g][1],   aph[0], apl[0]);
            split2(sc[2*g][2],   sc[2*g][3],   aph[1], apl[1]);
            split2(sc[2*g+1][0], sc[2*g+1][1], aph[2], apl[2]);
            split2(sc[2*g+1][2], sc[2*g+1][3], aph[3], apl[3]);
#pragma unroll
            for (int n16 = 0; n16 < 8; n16++) {
                uint32_t vaddr = bbase + 2 * ATILE
                    + (uint32_t)((g * 16 + (l & 15)) * ASTRIDE
                                 + n16 * 32 + (l >> 4) * 16);
                uint32_t bvh[2][2], bvl[2][2];
                ldm4t(bvh[0][0], bvh[0][1], bvh[1][0], bvh[1][1], vaddr);
                ldm4t(bvl[0][0], bvl[0][1], bvl[1][0], bvl[1][1], vaddr + ATILE);
#pragma unroll
                for (int j = 0; j < 2; j++) {
                    int t = n16 * 2 + j;
                    mma16816(o[t], aph, bvh[j]);
                    mma16816(o[t], apl, bvh[j]);
                    mma16816(o[t], aph, bvl[j]);
                }
            }
        }
        __syncthreads();
        buf ^= 1;
    }

    float i0 = 1.f / l0, i1 = 1.f / l1;
    const int colb = h * HD + 2 * (l & 3);
#pragma unroll
    for (int t = 0; t < 16; t++) {
        float* p0 = O + (size_t)row0 * (NH * HD) + colb + t * 8;
        float* p1 = O + (size_t)(row0 + 8) * (NH * HD) + colb + t * 8;
        *(float2*)p0 = make_float2(o[t][0] * i0, o[t][1] * i0);
        *(float2*)p1 = make_float2(o[t][2] * i1, o[t][3] * i1);
    }
}

// ---------------- launch ----------------------------------------------------
extern "C" void kernel_launch(void* const* d_in, const int* in_sizes, int n_in,
                              void* d_out, int out_size)
{
    const float* x     = (const float*)d_in[0];
    const float* cosf_ = (const float*)d_in[1];
    const float* sinf_ = (const float*)d_in[2];
    const float* in_ck = (const float*)d_in[5];
    const float* in_cv = (const float*)d_in[6];
    const float* Wqkv  = (const float*)d_in[7];
    const float* Wo    = (const float*)d_in[8];

    float* out     = (float*)d_out;
    float* cache_k = out + (size_t)SEQLEN * DIM;
    float* cache_v = cache_k + (size_t)WIN * KV_ROW;

    float *xqkv_p, *q_p, *attn_p;
    __nv_bfloat16 *xh_p, *xl_p, *ah_p, *al_p, *wqh_p, *wql_p, *woh_p, *wol_p;
    __nv_bfloat16 *qhi_p, *qlo_p, *khi_p, *klo_p, *vhi_p, *vlo_p;
    cudaGetSymbolAddress((void**)&xqkv_p, g_xqkv);
    cudaGetSymbolAddress((void**)&q_p,    g_q);
    cudaGetSymbolAddress((void**)&attn_p, g_attn);
    cudaGetSymbolAddress((void**)&xh_p,   g_xh);
    cudaGetSymbolAddress((void**)&xl_p,   g_xl);
    cudaGetSymbolAddress((void**)&ah_p,   g_ah);
    cudaGetSymbolAddress((void**)&al_p,   g_al);
    cudaGetSymbolAddress((void**)&wqh_p,  g_wqh);
    cudaGetSymbolAddress((void**)&wql_p,  g_wql);
    cudaGetSymbolAddress((void**)&woh_p,  g_woh);
    cudaGetSymbolAddress((void**)&wol_p,  g_wol);
    cudaGetSymbolAddress((void**)&qhi_p,  g_qhi);
    cudaGetSymbolAddress((void**)&qlo_p,  g_qlo);
    cudaGetSymbolAddress((void**)&khi_p,  g_khi);
    cudaGetSymbolAddress((void**)&klo_p,  g_klo);
    cudaGetSymbolAddress((void**)&vhi_p,  g_vhi);
    cudaGetSymbolAddress((void**)&vlo_p,  g_vlo);

    size_t cache_bytes = (size_t)WIN * KV_ROW * sizeof(float);
    cudaMemcpyAsync(cache_k, in_ck, cache_bytes, cudaMemcpyDeviceToDevice, 0);
    cudaMemcpyAsync(cache_v, in_cv, cache_bytes, cudaMemcpyDeviceToDevice, 0);

    cudaFuncSetAttribute(gemm_mma, cudaFuncAttributeMaxDynamicSharedMemorySize,
                         GEMM_SMEM);
    cudaFuncSetAttribute(attn_tc, cudaFuncAttributeMaxDynamicSharedMemorySize,
                         ATTN_SMEM);

    // hi/lo conversions
    {
        long long t4;
        t4 = (long long)SEQLEN * DIM / 4;
        convert_hilo<<<(unsigned)((t4 + 255) / 256), 256>>>(x, xh_p, xl_p, t4);
        t4 = (long long)QKV_N * DIM / 4;
        convert_hilo<<<(unsigned)((t4 + 255) / 256), 256>>>(Wqkv, wqh_p, wql_p, t4);
        t4 = (long long)DIM * DIM / 4;
        convert_hilo<<<(unsigned)((t4 + 255) / 256), 256>>>(Wo, woh_p, wol_p, t4);
    }

    // 1) QKV projection
    gemm_mma<<<dim3(QKV_N / 128, SEQLEN / 128), 256, GEMM_SMEM>>>(
        xh_p, xl_p, wqh_p, wql_p, xqkv_p, QKV_N);

    // 2) RoPE + cache writes
    rope_kernel<<<SEQLEN, 256>>>(xqkv_p, cosf_, sinf_, q_p, cache_k, cache_v);

    // 3) split q/k/v
    qsplit<<<SEQLEN, 256>>>(q_p, qhi_p, qlo_p);
    kvsplit<<<SEQLEN, 256>>>(cache_k, cache_v, khi_p, klo_p, vhi_p, vlo_p);

    // 4) tensor-core causal flash attention
    attn_tc<<<dim3(SEQLEN / 128, NH), 256, ATTN_SMEM>>>(
        qhi_p, qlo_p, khi_p, klo_p, vhi_p, vlo_p, attn_p);

    // 5) output projection
    {
        long long t4 = (long long)SEQLEN * DIM / 4;
        convert_hilo<<<(unsigned)((t4 + 255) / 256), 256>>>(attn_p, ah_p, al_p, t4);
    }
    gemm_mma<<<dim3(DIM / 128, SEQLEN / 128), 256, GEMM_SMEM>>>(
        ah_p, al_p, woh_p, wol_p, out, DIM);
}

// round 7
// speedup vs baseline: 1.3508x; 1.1021x over previous
#include <cuda_runtime.h>
#include <cuda_bf16.h>
#include <cstdint>
#include <math.h>

#define SEQLEN 2048
#define DIM    4096
#define NH     32
#define HD     128
#define NKV    8
#define QKV_N  6144
#define KV_ROW 1024
#define WIN    4096
#define SCALE  0.08838834764831845f

// ---------------- scratch (device globals) ----------------------------------
__device__ float g_xqkv[SEQLEN * QKV_N];
__device__ float g_q   [SEQLEN * NH * HD];
__device__ float g_attn[SEQLEN * NH * HD];
__device__ __nv_bfloat16 g_xh [(size_t)SEQLEN * DIM];
__device__ __nv_bfloat16 g_xl [(size_t)SEQLEN * DIM];
__device__ __nv_bfloat16 g_ah [(size_t)SEQLEN * DIM];
__device__ __nv_bfloat16 g_al [(size_t)SEQLEN * DIM];
__device__ __nv_bfloat16 g_wqh[(size_t)QKV_N * DIM];
__device__ __nv_bfloat16 g_wql[(size_t)QKV_N * DIM];
__device__ __nv_bfloat16 g_woh[(size_t)DIM * DIM];
__device__ __nv_bfloat16 g_wol[(size_t)DIM * DIM];
__device__ __nv_bfloat16 g_qhi[(size_t)NH  * SEQLEN * HD];
__device__ __nv_bfloat16 g_qlo[(size_t)NH  * SEQLEN * HD];
__device__ __nv_bfloat16 g_khi[(size_t)NKV * SEQLEN * HD];
__device__ __nv_bfloat16 g_klo[(size_t)NKV * SEQLEN * HD];
__device__ __nv_bfloat16 g_vhi[(size_t)NKV * SEQLEN * HD];
__device__ __nv_bfloat16 g_vlo[(size_t)NKV * SEQLEN * HD];

// ---------------- common PTX helpers ----------------------------------------
__device__ __forceinline__ void cp16(uint32_t d, const void* g) {
    asm volatile("cp.async.cg.shared.global [%0], [%1], 16;\n"
                 :: "r"(d), "l"(__cvta_generic_to_global(g)) : "memory");
}
__device__ __forceinline__ void ldm4(uint32_t& r0, uint32_t& r1,
                                     uint32_t& r2, uint32_t& r3, uint32_t a) {
    asm volatile("ldmatrix.sync.aligned.m8n8.x4.shared.b16 {%0,%1,%2,%3}, [%4];"
                 : "=r"(r0), "=r"(r1), "=r"(r2), "=r"(r3) : "r"(a));
}
__device__ __forceinline__ void ldm4t(uint32_t& r0, uint32_t& r1,
                                      uint32_t& r2, uint32_t& r3, uint32_t a) {
    asm volatile("ldmatrix.sync.aligned.m8n8.x4.trans.shared.b16 {%0,%1,%2,%3}, [%4];"
                 : "=r"(r0), "=r"(r1), "=r"(r2), "=r"(r3) : "r"(a));
}
__device__ __forceinline__ void mma16816(float* c, const uint32_t* a,
                                         const uint32_t* b) {
    asm volatile(
        "mma.sync.aligned.m16n8k16.row.col.f32.bf16.bf16.f32 "
        "{%0,%1,%2,%3}, {%4,%5,%6,%7}, {%8,%9}, {%0,%1,%2,%3};"
        : "+f"(c[0]), "+f"(c[1]), "+f"(c[2]), "+f"(c[3])
        : "r"(a[0]), "r"(a[1]), "r"(a[2]), "r"(a[3]), "r"(b[0]), "r"(b[1]));
}
__device__ __forceinline__ void split2(float x, float y, uint32_t& hi, uint32_t& lo) {
    __nv_bfloat162 h = __floats2bfloat162_rn(x, y);
    float rx = x - __bfloat162float(h.x);
    float ry = y - __bfloat162float(h.y);
    __nv_bfloat162 r = __floats2bfloat162_rn(rx, ry);
    hi = *(uint32_t*)&h; lo = *(uint32_t*)&r;
}

// ---------------- fp32 -> (hi, lo) bf16 arrays -------------------------------
__global__ __launch_bounds__(256) void convert_hilo(
    const float* __restrict__ in, __nv_bfloat16* __restrict__ hi,
    __nv_bfloat16* __restrict__ lo, long long total4)
{
    long long i = (long long)blockIdx.x * 256 + threadIdx.x;
    if (i >= total4) return;
    float4 v = ((const float4*)in)[i];
    float vv[4] = {v.x, v.y, v.z, v.w};
    union { unsigned long long u; __nv_bfloat16 h[4]; } H, L;
#pragma unroll
    for (int j = 0; j < 4; j++) {
        __nv_bfloat16 h = __float2bfloat16(vv[j]);
        H.h[j] = h;
        L.h[j] = __float2bfloat16(vv[j] - __bfloat162float(h));
    }
    ((unsigned long long*)hi)[i] = H.u;
    ((unsigned long long*)lo)[i] = L.u;
}

// ---------------- 3-term hi/lo mma.sync GEMM: C = A * B^T --------------------
// CTA 128x128, 8 warps (2x4), warp 64x32. K = 4096, KC = 32.
// smem: tight 64B rows + XOR swizzle (chunk ^= (row>>1)&3), 3 stages.
#define GK       4096
#define KC       32
#define NCHUNK   (GK / KC)               // 128
#define PTILEB   (128 * 64)              // 8192 per part-tile
#define STAGEB   (4 * PTILEB)            // Ah Al Bh Bl = 32768
#define GSTAGES  3
#define GEMM_SMEM (GSTAGES * STAGEB)     // 98304

__global__ __launch_bounds__(256, 2) void gemm_mma(
    const __nv_bfloat16* __restrict__ Ah, const __nv_bfloat16* __restrict__ Al,
    const __nv_bfloat16* __restrict__ Bh, const __nv_bfloat16* __restrict__ Bl,
    float* __restrict__ C, int N)
{
    extern __shared__ __align__(128) char smraw[];
    const uint32_t sb = (uint32_t)__cvta_generic_to_shared(smraw);

    const int tid = threadIdx.x;
    const int w   = tid >> 5;
    const int l   = tid & 31;
    const int wm  = w & 1;          // 0-1 : 64-row slab
    const int wn  = w >> 1;         // 0-3 : 32-col slab

    const size_t arow_g = (size_t)blockIdx.y * 128 * GK;
    const size_t brow_g = (size_t)blockIdx.x * 128 * GK;
    const char* gp[4] = { (const char*)(Ah + arow_g), (const char*)(Al + arow_g),
                          (const char*)(Bh + brow_g), (const char*)(Bl + brow_g) };

    // write slots: 512 per part (128 rows x 4 chunks of 16B), swizzled dst
    const int wr = tid >> 1;                    // rows: 2 threads per row? no:
    // slot mapping: slot = tid + j*256; r = slot>>2; c = slot&3
    auto load_chunk = [&](int t, uint32_t st) {
        const size_t gk = (size_t)t * 64;      // byte offset along K
#pragma unroll
        for (int part = 0; part < 4; part++) {
#pragma unroll
            for (int j = 0; j < 2; j++) {
                int slot = tid + j * 256;
                int r = slot >> 2, c = slot & 3;
                uint32_t dc = (uint32_t)((c * 16) ^ (((r >> 1) & 3) * 16));
                cp16(st + part * PTILEB + r * 64 + dc,
                     gp[part] + (size_t)r * (GK * 2) + gk + c * 16);
            }
        }
    };
    (void)wr;

    // ldsm lane geometry
    const int arow = wm * 64 + (l & 15);
    const uint32_t arb  = (uint32_t)(arow * 64);
    const uint32_t axor = (uint32_t)(((arow >> 1) & 3) * 16);
    const int ac0 = (l >> 4);                       // A chunk low bit
    const int l2 = l & 7, sel = l >> 3;
    const int brow = wn * 32 + (sel >> 1) * 8 + l2;
    const uint32_t brb  = (uint32_t)(brow * 64);
    const uint32_t bxor = (uint32_t)(((brow >> 1) & 3) * 16);
    const int bc0 = (sel & 1);                      // B chunk low bit

    float acc[4][4][4];
#pragma unroll
    for (int mt = 0; mt < 4; mt++)
#pragma unroll
        for (int nt = 0; nt < 4; nt++)
#pragma unroll
            for (int i = 0; i < 4; i++) acc[mt][nt][i] = 0.f;

    // prefill stages 0,1
    load_chunk(0, sb);
    asm volatile("cp.async.commit_group;" ::: "memory");
    load_chunk(1, sb + STAGEB);
    asm volatile("cp.async.commit_group;" ::: "memory");

    int cs = 0, ls = 2;
    for (int k = 0; k < NCHUNK; k++) {
        if (k + 1 < NCHUNK)
            asm volatile("cp.async.wait_group 1;" ::: "memory");
        else
            asm volatile("cp.async.wait_group 0;" ::: "memory");
        __syncthreads();

        if (k + 2 < NCHUNK) {
            load_chunk(k + 2, sb + ls * STAGEB);
            asm volatile("cp.async.commit_group;" ::: "memory");
        }

        const uint32_t st = sb + cs * STAGEB;
#pragma unroll
        for (int ks = 0; ks < 2; ks++) {
            const uint32_t ach = (uint32_t)(((ks * 2 + ac0) * 16)) ^ axor;
            const uint32_t bch = (uint32_t)(((ks * 2 + bc0) * 16)) ^ bxor;

            uint32_t ah[4][4], bh[4][2];
#pragma unroll
            for (int mt = 0; mt < 4; mt++)
                ldm4(ah[mt][0], ah[mt][1], ah[mt][2], ah[mt][3],
                     st + arb + mt * 1024 + ach);
#pragma unroll
            for (int np = 0; np < 2; np++)
                ldm4(bh[2*np][0], bh[2*np][1], bh[2*np+1][0], bh[2*np+1][1],
                     st + 2 * PTILEB + brb + np * 1024 + bch);
#pragma unroll
            for (int mt = 0; mt < 4; mt++)
#pragma unroll
                for (int nt = 0; nt < 4; nt++)
                    mma16816(acc[mt][nt], ah[mt], bh[nt]);

            uint32_t al[4][4];
#pragma unroll
            for (int mt = 0; mt < 4; mt++)
                ldm4(al[mt][0], al[mt][1], al[mt][2], al[mt][3],
                     st + PTILEB + arb + mt * 1024 + ach);
#pragma unroll
            for (int mt = 0; mt < 4; mt++)
#pragma unroll
                for (int nt = 0; nt < 4; nt++)
                    mma16816(acc[mt][nt], al[mt], bh[nt]);

            uint32_t bl[4][2];
#pragma unroll
            for (int np = 0; np < 2; np++)
                ldm4(bl[2*np][0], bl[2*np][1], bl[2*np+1][0], bl[2*np+1][1],
                     st + 3 * PTILEB + brb + np * 1024 + bch);
#pragma unroll
            for (int mt = 0; mt < 4; mt++)
#pragma unroll
                for (int nt = 0; nt < 4; nt++)
                    mma16816(acc[mt][nt], ah[mt], bl[nt]);
        }
        cs = (cs == 2) ? 0 : cs + 1;
        ls = (ls == 2) ? 0 : ls + 1;
    }

    const int crow = blockIdx.y * 128 + wm * 64 + (l >> 2);
    const int ccol = blockIdx.x * 128 + wn * 32 + (l & 3) * 2;
#pragma unroll
    for (int mt = 0; mt < 4; mt++) {
#pragma unroll
        for (int nt = 0; nt < 4; nt++) {
            float* p0 = C + (size_t)(crow + mt * 16)     * N + ccol + nt * 8;
            float* p1 = C + (size_t)(crow + mt * 16 + 8) * N + ccol + nt * 8;
            *(float2*)p0 = make_float2(acc[mt][nt][0], acc[mt][nt][1]);
            *(float2*)p1 = make_float2(acc[mt][nt][2], acc[mt][nt][3]);
        }
    }
}

// ---------------- RoPE + scale-fold + cache write ---------------------------
__global__ __launch_bounds__(256) void rope_kernel(
    const float* __restrict__ xqkv,
    const float* __restrict__ cosf_, const float* __restrict__ sinf_,
    float* __restrict__ qout, float* __restrict__ kcache, float* __restrict__ vcache)
{
    const int s   = blockIdx.x;
    const int tid = threadIdx.x;
    const float* row = xqkv + (size_t)s * QKV_N;

    for (int p = tid; p < NH * 64; p += 256) {
        int h = p >> 6, f = p & 63;
        float c  = cosf_[s * 64 + f];
        float sn = sinf_[s * 64 + f];
        float x1 = row[h * HD + 2 * f];
        float x2 = row[h * HD + 2 * f + 1];
        qout[(size_t)s * (NH * HD) + h * HD + 2 * f]     = (x1 * c - x2 * sn) * SCALE;
        qout[(size_t)s * (NH * HD) + h * HD + 2 * f + 1] = (x1 * sn + x2 * c) * SCALE;
    }
    for (int p = tid; p < NKV * 64; p += 256) {
        int h = p >> 6, f = p & 63;
        float c  = cosf_[s * 64 + f];
        float sn = sinf_[s * 64 + f];
        float x1 = row[DIM + h * HD + 2 * f];
        float x2 = row[DIM + h * HD + 2 * f + 1];
        kcache[(size_t)s * KV_ROW + h * HD + 2 * f]     = x1 * c - x2 * sn;
        kcache[(size_t)s * KV_ROW + h * HD + 2 * f + 1] = x1 * sn + x2 * c;
    }
    for (int i = tid; i < KV_ROW; i += 256)
        vcache[(size_t)s * KV_ROW + i] = row[DIM + NKV * HD + i];
}

// ---------------- q / kv split-bf16 prep for attention ----------------------
__global__ __launch_bounds__(256) void qsplit(
    const float* __restrict__ q,
    __nv_bfloat16* __restrict__ qhi, __nv_bfloat16* __restrict__ qlo)
{
    const int s = blockIdx.x, tid = threadIdx.x;
    for (int i = tid; i < NH * HD; i += 256) {
        int h = i >> 7, d = i & 127;
        float v = q[(size_t)s * (NH * HD) + i];
        __nv_bfloat16 hv = __float2bfloat16(v);
        size_t o = ((size_t)h * SEQLEN + s) * HD + d;
        qhi[o] = hv;
        qlo[o] = __float2bfloat16(v - __bfloat162float(hv));
    }
}
__global__ __launch_bounds__(256) void kvsplit(
    const float* __restrict__ kc, const float* __restrict__ vc,
    __nv_bfloat16* __restrict__ khi, __nv_bfloat16* __restrict__ klo,
    __nv_bfloat16* __restrict__ vhi, __nv_bfloat16* __restrict__ vlo)
{
    const int s = blockIdx.x, tid = threadIdx.x;
    for (int i = tid; i < NKV * HD; i += 256) {
        int h = i >> 7, d = i & 127;
        size_t o = ((size_t)h * SEQLEN + s) * HD + d;
        float kv = kc[(size_t)s * KV_ROW + i];
        __nv_bfloat16 kh = __float2bfloat16(kv);
        khi[o] = kh;
        klo[o] = __float2bfloat16(kv - __bfloat162float(kh));
        float vv = vc[(size_t)s * KV_ROW + i];
        __nv_bfloat16 vh = __float2bfloat16(vv);
        vhi[o] = vh;
        vlo[o] = __float2bfloat16(vv - __bfloat162float(vh));
    }
}

// ---------------- tensor-core causal flash attention (double-buffered) ------
#define ASTRIDE 272
#define ATILE   (64 * ASTRIDE)
#define ABUF    (4 * ATILE)
#define ATTN_SMEM (2 * ABUF)

__global__ __launch_bounds__(256, 1) void attn_tc(
    const __nv_bfloat16* __restrict__ Qh, const __nv_bfloat16* __restrict__ Ql,
    const __nv_bfloat16* __restrict__ Kh, const __nv_bfloat16* __restrict__ Kl,
    const __nv_bfloat16* __restrict__ Vh, const __nv_bfloat16* __restrict__ Vl,
    float* __restrict__ O)
{
    extern __shared__ __align__(128) char smraw[];
    const uint32_t sb = (uint32_t)__cvta_generic_to_shared(smraw);
    const int tid = threadIdx.x, w = tid >> 5, l = tid & 31;
    const int qt  = (int)gridDim.x - 1 - (int)blockIdx.x;
    const int h   = blockIdx.y;
    const int kvh = h >> 2;

    uint32_t qh_[8][4], ql_[8][4];
    {
        const uint32_t aoff = sb + (uint32_t)((w * 16 + (l & 15)) * ASTRIDE
                                              + (l >> 4) * 16);
        for (int part = 0; part < 2; part++) {
            const __nv_bfloat16* src = part ? Ql : Qh;
            const char* g0 = (const char*)(src + ((size_t)h * SEQLEN + qt * 128) * HD);
            for (int i = tid; i < 2048; i += 256)
                cp16(sb + (uint32_t)((i >> 4) * ASTRIDE + (i & 15) * 16),
                     g0 + (size_t)i * 16);
            asm volatile("cp.async.commit_group;" ::: "memory");
            asm volatile("cp.async.wait_group 0;" ::: "memory");
            __syncthreads();
            uint32_t (*dst)[4] = part ? ql_ : qh_;
#pragma unroll
            for (int g = 0; g < 8; g++)
                ldm4(dst[g][0], dst[g][1], dst[g][2], dst[g][3], aoff + g * 32);
            __syncthreads();
        }
    }

    float o[16][4];
#pragma unroll
    for (int t = 0; t < 16; t++)
#pragma unroll
        for (int i = 0; i < 4; i++) o[t][i] = 0.f;
    float m0 = -1e30f, m1 = -1e30f, l0 = 0.f, l1 = 0.f;

    const int row0 = qt * 128 + w * 16 + (l >> 2);
    const int l2 = l & 7, sel = l >> 3;
    const int nkb = 2 * qt + 2;

    auto load_kv = [&](int kb, uint32_t bufbase) {
        const size_t gbase = (((size_t)kvh * SEQLEN + (size_t)kb * 64) * HD) * 2;
        for (int i = tid; i < 1024; i += 256) {
            uint32_t soff = (uint32_t)((i >> 4) * ASTRIDE + (i & 15) * 16);
            size_t goff = gbase + (size_t)i * 16;
            cp16(bufbase + 0 * ATILE + soff, (const char*)Kh + goff);
            cp16(bufbase + 1 * ATILE + soff, (const char*)Kl + goff);
            cp16(bufbase + 2 * ATILE + soff, (const char*)Vh + goff);
            cp16(bufbase + 3 * ATILE + soff, (const char*)Vl + goff);
        }
        asm volatile("cp.async.commit_group;" ::: "memory");
    };

    int buf = 0;
    load_kv(0, sb);

    for (int kb = 0; kb < nkb; kb++) {
        if (kb + 1 < nkb) {
            load_kv(kb + 1, sb + (buf ^ 1) * ABUF);
            asm volatile("cp.async.wait_group 1;" ::: "memory");
        } else {
            asm volatile("cp.async.wait_group 0;" ::: "memory");
        }
        __syncthreads();
        const uint32_t bbase = sb + buf * ABUF;

        float sc[8][4];
#pragma unroll
        for (int t = 0; t < 8; t++)
#pragma unroll
            for (int i = 0; i < 4; i++) sc[t][i] = 0.f;

#pragma unroll
        for (int g = 0; g < 8; g++) {
#pragma unroll
            for (int n16 = 0; n16 < 4; n16++) {
                uint32_t kaddr = bbase + (uint32_t)((n16 * 16 + (sel >> 1) * 8 + l2)
                                                    * ASTRIDE + (sel & 1) * 16 + g * 32);
                uint32_t bh[2][2], bl[2][2];
                ldm4(bh[0][0], bh[0][1], bh[1][0], bh[1][1], kaddr);
                ldm4(bl[0][0], bl[0][1], bl[1][0], bl[1][1], kaddr + ATILE);
#pragma unroll
                for (int j = 0; j < 2; j++) {
                    int t = n16 * 2 + j;
                    mma16816(sc[t], qh_[g], bh[j]);
                    mma16816(sc[t], ql_[g], bh[j]);
                    mma16816(sc[t], qh_[g], bl[j]);
                }
            }
        }

        if (kb >= 2 * qt) {
#pragma unroll
            for (int t = 0; t < 8; t++) {
                int col = kb * 64 + t * 8 + 2 * (l & 3);
                if (col     > row0)     sc[t][0] = -1e30f;
                if (col + 1 > row0)     sc[t][1] = -1e30f;
                if (col     > row0 + 8) sc[t][2] = -1e30f;
                if (col + 1 > row0 + 8) sc[t][3] = -1e30f;
            }
        }

        float r0m = -1e30f, r1m = -1e30f;
#pragma unroll
        for (int t = 0; t < 8; t++) {
            r0m = fmaxf(r0m, fmaxf(sc[t][0], sc[t][1]));
            r1m = fmaxf(r1m, fmaxf(sc[t][2], sc[t][3]));
        }
        r0m = fmaxf(r0m, __shfl_xor_sync(0xffffffffu, r0m, 1));
        r0m = fmaxf(r0m, __shfl_xor_sync(0xffffffffu, r0m, 2));
        r1m = fmaxf(r1m, __shfl_xor_sync(0xffffffffu, r1m, 1));
        r1m = fmaxf(r1m, __shfl_xor_sync(0xffffffffu, r1m, 2));
        float nm0 = fmaxf(m0, r0m), nm1 = fmaxf(m1, r1m);
        float a0 = __expf(m0 - nm0), a1 = __expf(m1 - nm1);

        float s0 = 0.f, s1 = 0.f;
#pragma unroll
        for (int t = 0; t < 8; t++) {
            sc[t][0] = __expf(sc[t][0] - nm0); s0 += sc[t][0];
            sc[t][1] = __expf(sc[t][1] - nm0); s0 += sc[t][1];
            sc[t][2] = __expf(sc[t][2] - nm1); s1 += sc[t][2];
            sc[t][3] = __expf(sc[t][3] - nm1); s1 += sc[t][3];
        }
        s0 += __shfl_xor_sync(0xffffffffu, s0, 1);
        s0 += __shfl_xor_sync(0xffffffffu, s0, 2);
        s1 += __shfl_xor_sync(0xffffffffu, s1, 1);
        s1 += __shfl_xor_sync(0xffffffffu, s1, 2);
        l0 = l0 * a0 + s0;
        l1 = l1 * a1 + s1;
        m0 = nm0; m1 = nm1;
#pragma unroll
        for (int t = 0; t < 16; t++) {
            o[t][0] *= a0; o[t][1] *= a0;
            o[t][2] *= a1; o[t][3] *= a1;
        }

#pragma unroll
        for (int g = 0; g < 4; g++) {
            uint32_t aph[4], apl[4];
            split2(sc[2*g][0],   sc[2*g][1],   aph[0], apl[0]);
            split2(sc[2*g][2],   sc[2*g][3],   aph[1], apl[1]);
            split2(sc[2*g+1][0], sc[2*g+1][1], aph[2], apl[2]);
            split2(sc[2*g+1][2], sc[2*g+1][3], aph[3], apl[3]);
#pragma unroll
            for (int n16 = 0; n16 < 8; n16++) {
                uint32_t vaddr = bbase + 2 * ATILE
                    + (uint32_t)((g * 16 + (l & 15)) * ASTRIDE
                                 + n16 * 32 + (l >> 4) * 16);
                uint32_t bvh[2][2], bvl[2][2];
                ldm4t(bvh[0][0], bvh[0][1], bvh[1][0], bvh[1][1], vaddr);
                ldm4t(bvl[0][0], bvl[0][1], bvl[1][0], bvl[1][1], vaddr + ATILE);
#pragma unroll
                for (int j = 0; j < 2; j++) {
                    int t = n16 * 2 + j;
                    mma16816(o[t], aph, bvh[j]);
                    mma16816(o[t], apl, bvh[j]);
                    mma16816(o[t], aph, bvl[j]);
                }
            }
        }
        __syncthreads();
        buf ^= 1;
    }

    float i0 = 1.f / l0, i1 = 1.f / l1;
    const int colb = h * HD + 2 * (l & 3);
#pragma unroll
    for (int t = 0; t < 16; t++) {
        float* p0 = O + (size_t)row0 * (NH * HD) + colb + t * 8;
        float* p1 = O + (size_t)(row0 + 8) * (NH * HD) + colb + t * 8;
        *(float2*)p0 = make_float2(o[t][0] * i0, o[t][1] * i0);
        *(float2*)p1 = make_float2(o[t][2] * i1, o[t][3] * i1);
    }
}

// ---------------- launch ----------------------------------------------------
extern "C" void kernel_launch(void* const* d_in, const int* in_sizes, int n_in,
                              void* d_out, int out_size)
{
    const float* x     = (const float*)d_in[0];
    const float* cosf_ = (const float*)d_in[1];
    const float* sinf_ = (const float*)d_in[2];
    const float* in_ck = (const float*)d_in[5];
    const float* in_cv = (const float*)d_in[6];
    const float* Wqkv  = (const float*)d_in[7];
    const float* Wo    = (const float*)d_in[8];

    float* out     = (float*)d_out;
    float* cache_k = out + (size_t)SEQLEN * DIM;
    float* cache_v = cache_k + (size_t)WIN * KV_ROW;

    float *xqkv_p, *q_p, *attn_p;
    __nv_bfloat16 *xh_p, *xl_p, *ah_p, *al_p, *wqh_p, *wql_p, *woh_p, *wol_p;
    __nv_bfloat16 *qhi_p, *qlo_p, *khi_p, *klo_p, *vhi_p, *vlo_p;
    cudaGetSymbolAddress((void**)&xqkv_p, g_xqkv);
    cudaGetSymbolAddress((void**)&q_p,    g_q);
    cudaGetSymbolAddress((void**)&attn_p, g_attn);
    cudaGetSymbolAddress((void**)&xh_p,   g_xh);
    cudaGetSymbolAddress((void**)&xl_p,   g_xl);
    cudaGetSymbolAddress((void**)&ah_p,   g_ah);
    cudaGetSymbolAddress((void**)&al_p,   g_al);
    cudaGetSymbolAddress((void**)&wqh_p,  g_wqh);
    cudaGetSymbolAddress((void**)&wql_p,  g_wql);
    cudaGetSymbolAddress((void**)&woh_p,  g_woh);
    cudaGetSymbolAddress((void**)&wol_p,  g_wol);
    cudaGetSymbolAddress((void**)&qhi_p,  g_qhi);
    cudaGetSymbolAddress((void**)&qlo_p,  g_qlo);
    cudaGetSymbolAddress((void**)&khi_p,  g_khi);
    cudaGetSymbolAddress((void**)&klo_p,  g_klo);
    cudaGetSymbolAddress((void**)&vhi_p,  g_vhi);
    cudaGetSymbolAddress((void**)&vlo_p,  g_vlo);

    size_t cache_bytes = (size_t)WIN * KV_ROW * sizeof(float);
    cudaMemcpyAsync(cache_k, in_ck, cache_bytes, cudaMemcpyDeviceToDevice, 0);
    cudaMemcpyAsync(cache_v, in_cv, cache_bytes, cudaMemcpyDeviceToDevice, 0);

    cudaFuncSetAttribute(gemm_mma, cudaFuncAttributeMaxDynamicSharedMemorySize,
                         GEMM_SMEM);
    cudaFuncSetAttribute(attn_tc, cudaFuncAttributeMaxDynamicSharedMemorySize,
                         ATTN_SMEM);

    {
        long long t4;
        t4 = (long long)SEQLEN * DIM / 4;
        convert_hilo<<<(unsigned)((t4 + 255) / 256), 256>>>(x, xh_p, xl_p, t4);
        t4 = (long long)QKV_N * DIM / 4;
        convert_hilo<<<(unsigned)((t4 + 255) / 256), 256>>>(Wqkv, wqh_p, wql_p, t4);
        t4 = (long long)DIM * DIM / 4;
        convert_hilo<<<(unsigned)((t4 + 255) / 256), 256>>>(Wo, woh_p, wol_p, t4);
    }

    // 1) QKV projection
    gemm_mma<<<dim3(QKV_N / 128, SEQLEN / 128), 256, GEMM_SMEM>>>(
        xh_p, xl_p, wqh_p, wql_p, xqkv_p, QKV_N);

    // 2) RoPE + cache writes
    rope_kernel<<<SEQLEN, 256>>>(xqkv_p, cosf_, sinf_, q_p, cache_k, cache_v);

    // 3) split q/k/v
    qsplit<<<SEQLEN, 256>>>(q_p, qhi_p, qlo_p);
    kvsplit<<<SEQLEN, 256>>>(cache_k, cache_v, khi_p, klo_p, vhi_p, vlo_p);

    // 4) tensor-core causal flash attention
    attn_tc<<<dim3(SEQLEN / 128, NH), 256, ATTN_SMEM>>>(
        qhi_p, qlo_p, khi_p, klo_p, vhi_p, vlo_p, attn_p);

    // 5) output projection
    {
        long long t4 = (long long)SEQLEN * DIM / 4;
        convert_hilo<<<(unsigned)((t4 + 255) / 256), 256>>>(attn_p, ah_p, al_p, t4);
    }
    gemm_mma<<<dim3(DIM / 128, SEQLEN / 128), 256, GEMM_SMEM>>>(
        ah_p, al_p, woh_p, wol_p, out, DIM);
}

// round 8
// speedup vs baseline: 1.8122x; 1.3415x over previous
#include <cuda_runtime.h>
#include <cuda_bf16.h>
#include <cuda_fp16.h>
#include <cstdint>
#include <math.h>

#define SEQLEN 2048
#define DIM    4096
#define NH     32
#define HD     128
#define NKV    8
#define QKV_N  6144
#define KV_ROW 1024
#define WIN    4096
#define SCALE  0.08838834764831845f

// ---------------- scratch (device globals) ----------------------------------
__device__ float g_xqkv[SEQLEN * QKV_N];
__device__ float g_q   [SEQLEN * NH * HD];
__device__ float g_attn[SEQLEN * NH * HD];
// fp16 GEMM operands: activations split hi/lo, weights single
__device__ __half g_xh [(size_t)SEQLEN * DIM];
__device__ __half g_xl [(size_t)SEQLEN * DIM];
__device__ __half g_ah [(size_t)SEQLEN * DIM];
__device__ __half g_al [(size_t)SEQLEN * DIM];
__device__ __half g_wq [(size_t)QKV_N * DIM];
__device__ __half g_wo [(size_t)DIM * DIM];
// attention split q/k/v (bf16 3-term, unchanged): [head][seq][HD]
__device__ __nv_bfloat16 g_qhi[(size_t)NH  * SEQLEN * HD];
__device__ __nv_bfloat16 g_qlo[(size_t)NH  * SEQLEN * HD];
__device__ __nv_bfloat16 g_khi[(size_t)NKV * SEQLEN * HD];
__device__ __nv_bfloat16 g_klo[(size_t)NKV * SEQLEN * HD];
__device__ __nv_bfloat16 g_vhi[(size_t)NKV * SEQLEN * HD];
__device__ __nv_bfloat16 g_vlo[(size_t)NKV * SEQLEN * HD];

// ---------------- common PTX helpers ----------------------------------------
__device__ __forceinline__ void cp16(uint32_t d, const void* g) {
    asm volatile("cp.async.cg.shared.global [%0], [%1], 16;\n"
                 :: "r"(d), "l"(__cvta_generic_to_global(g)) : "memory");
}
__device__ __forceinline__ void ldm4(uint32_t& r0, uint32_t& r1,
                                     uint32_t& r2, uint32_t& r3, uint32_t a) {
    asm volatile("ldmatrix.sync.aligned.m8n8.x4.shared.b16 {%0,%1,%2,%3}, [%4];"
                 : "=r"(r0), "=r"(r1), "=r"(r2), "=r"(r3) : "r"(a));
}
__device__ __forceinline__ void ldm4t(uint32_t& r0, uint32_t& r1,
                                      uint32_t& r2, uint32_t& r3, uint32_t a) {
    asm volatile("ldmatrix.sync.aligned.m8n8.x4.trans.shared.b16 {%0,%1,%2,%3}, [%4];"
                 : "=r"(r0), "=r"(r1), "=r"(r2), "=r"(r3) : "r"(a));
}
__device__ __forceinline__ void mma_bf16(float* c, const uint32_t* a,
                                         const uint32_t* b) {
    asm volatile(
        "mma.sync.aligned.m16n8k16.row.col.f32.bf16.bf16.f32 "
        "{%0,%1,%2,%3}, {%4,%5,%6,%7}, {%8,%9}, {%0,%1,%2,%3};"
        : "+f"(c[0]), "+f"(c[1]), "+f"(c[2]), "+f"(c[3])
        : "r"(a[0]), "r"(a[1]), "r"(a[2]), "r"(a[3]), "r"(b[0]), "r"(b[1]));
}
__device__ __forceinline__ void mma_f16(float* c, const uint32_t* a,
                                        const uint32_t* b) {
    asm volatile(
        "mma.sync.aligned.m16n8k16.row.col.f32.f16.f16.f32 "
        "{%0,%1,%2,%3}, {%4,%5,%6,%7}, {%8,%9}, {%0,%1,%2,%3};"
        : "+f"(c[0]), "+f"(c[1]), "+f"(c[2]), "+f"(c[3])
        : "r"(a[0]), "r"(a[1]), "r"(a[2]), "r"(a[3]), "r"(b[0]), "r"(b[1]));
}
__device__ __forceinline__ void split2(float x, float y, uint32_t& hi, uint32_t& lo) {
    __nv_bfloat162 h = __floats2bfloat162_rn(x, y);
    float rx = x - __bfloat162float(h.x);
    float ry = y - __bfloat162float(h.y);
    __nv_bfloat162 r = __floats2bfloat162_rn(rx, ry);
    hi = *(uint32_t*)&h; lo = *(uint32_t*)&r;
}

// ---------------- fp32 -> fp16 hi/lo, and fp32 -> fp16 ----------------------
__global__ __launch_bounds__(256) void convert_hilo_f16(
    const float* __restrict__ in, __half* __restrict__ hi,
    __half* __restrict__ lo, long long total4)
{
    long long i = (long long)blockIdx.x * 256 + threadIdx.x;
    if (i >= total4) return;
    float4 v = ((const float4*)in)[i];
    float vv[4] = {v.x, v.y, v.z, v.w};
    union { unsigned long long u; __half h[4]; } H, L;
#pragma unroll
    for (int j = 0; j < 4; j++) {
        __half h = __float2half_rn(vv[j]);
        H.h[j] = h;
        L.h[j] = __float2half_rn(vv[j] - __half2float(h));
    }
    ((unsigned long long*)hi)[i] = H.u;
    ((unsigned long long*)lo)[i] = L.u;
}
__global__ __launch_bounds__(256) void convert_f16(
    const float* __restrict__ in, __half* __restrict__ out, long long total4)
{
    long long i = (long long)blockIdx.x * 256 + threadIdx.x;
    if (i >= total4) return;
    float4 v = ((const float4*)in)[i];
    float vv[4] = {v.x, v.y, v.z, v.w};
    union { unsigned long long u; __half h[4]; } H;
#pragma unroll
    for (int j = 0; j < 4; j++) H.h[j] = __float2half_rn(vv[j]);
    ((unsigned long long*)out)[i] = H.u;
}

// ---------------- fp16 2-term mma.sync GEMM: C = A * B^T ---------------------
// CTA 128x128, 8 warps (2x4), warp 64x32. K = 4096, KC = 32.
// smem: tight 64B rows + XOR swizzle, 4 stages, parts {Ah, Al, Bh}.
#define GK       4096
#define NCHUNK   (GK / 32)               // 128
#define PTILEB   (128 * 64)              // 8192 per part-tile
#define STAGEB   (3 * PTILEB)            // 24576
#define GSTAGES  4
#define GEMM_SMEM (GSTAGES * STAGEB)     // 98304

__global__ __launch_bounds__(256, 2) void gemm_mma(
    const __half* __restrict__ Ah, const __half* __restrict__ Al,
    const __half* __restrict__ Bh, float* __restrict__ C, int N)
{
    extern __shared__ __align__(128) char smraw[];
    const uint32_t sb = (uint32_t)__cvta_generic_to_shared(smraw);

    const int tid = threadIdx.x;
    const int w   = tid >> 5;
    const int l   = tid & 31;
    const int wm  = w & 1;
    const int wn  = w >> 1;

    const size_t arow_g = (size_t)blockIdx.y * 128 * GK;
    const size_t brow_g = (size_t)blockIdx.x * 128 * GK;
    const char* gp[3] = { (const char*)(Ah + arow_g), (const char*)(Al + arow_g),
                          (const char*)(Bh + brow_g) };

    auto load_chunk = [&](int t, uint32_t st) {
        const size_t gk = (size_t)t * 64;
#pragma unroll
        for (int part = 0; part < 3; part++) {
#pragma unroll
            for (int j = 0; j < 2; j++) {
                int slot = tid + j * 256;
                int r = slot >> 2, c = slot & 3;
                uint32_t dc = (uint32_t)((c * 16) ^ (((r >> 1) & 3) * 16));
                cp16(st + part * PTILEB + r * 64 + dc,
                     gp[part] + (size_t)r * (GK * 2) + gk + c * 16);
            }
        }
    };

    const int arow = wm * 64 + (l & 15);
    const uint32_t arb  = (uint32_t)(arow * 64);
    const uint32_t axor = (uint32_t)(((arow >> 1) & 3) * 16);
    const int ac0 = (l >> 4);
    const int l2 = l & 7, sel = l >> 3;
    const int brow = wn * 32 + (sel >> 1) * 8 + l2;
    const uint32_t brb  = (uint32_t)(brow * 64);
    const uint32_t bxor = (uint32_t)(((brow >> 1) & 3) * 16);
    const int bc0 = (sel & 1);

    float acc[4][4][4];
#pragma unroll
    for (int mt = 0; mt < 4; mt++)
#pragma unroll
        for (int nt = 0; nt < 4; nt++)
#pragma unroll
            for (int i = 0; i < 4; i++) acc[mt][nt][i] = 0.f;

    // prefill stages 0..2
    load_chunk(0, sb);
    asm volatile("cp.async.commit_group;" ::: "memory");
    load_chunk(1, sb + STAGEB);
    asm volatile("cp.async.commit_group;" ::: "memory");
    load_chunk(2, sb + 2 * STAGEB);
    asm volatile("cp.async.commit_group;" ::: "memory");

    for (int k = 0; k < NCHUNK; k++) {
        if (k + 2 < NCHUNK)
            asm volatile("cp.async.wait_group 2;" ::: "memory");
        else if (k + 1 < NCHUNK)
            asm volatile("cp.async.wait_group 1;" ::: "memory");
        else
            asm volatile("cp.async.wait_group 0;" ::: "memory");
        __syncthreads();

        if (k + 3 < NCHUNK) {
            load_chunk(k + 3, sb + ((k + 3) & 3) * STAGEB);
            asm volatile("cp.async.commit_group;" ::: "memory");
        }

        const uint32_t st = sb + (k & 3) * STAGEB;
#pragma unroll
        for (int ks = 0; ks < 2; ks++) {
            const uint32_t ach = (uint32_t)(((ks * 2 + ac0) * 16)) ^ axor;
            const uint32_t bch = (uint32_t)(((ks * 2 + bc0) * 16)) ^ bxor;

            uint32_t ah[4][4], bh[4][2];
#pragma unroll
            for (int mt = 0; mt < 4; mt++)
                ldm4(ah[mt][0], ah[mt][1], ah[mt][2], ah[mt][3],
                     st + arb + mt * 1024 + ach);
#pragma unroll
            for (int np = 0; np < 2; np++)
                ldm4(bh[2*np][0], bh[2*np][1], bh[2*np+1][0], bh[2*np+1][1],
                     st + 2 * PTILEB + brb + np * 1024 + bch);
#pragma unroll
            for (int mt = 0; mt < 4; mt++)
#pragma unroll
                for (int nt = 0; nt < 4; nt++)
                    mma_f16(acc[mt][nt], ah[mt], bh[nt]);

            uint32_t al[4][4];
#pragma unroll
            for (int mt = 0; mt < 4; mt++)
                ldm4(al[mt][0], al[mt][1], al[mt][2], al[mt][3],
                     st + PTILEB + arb + mt * 1024 + ach);
#pragma unroll
            for (int mt = 0; mt < 4; mt++)
#pragma unroll
                for (int nt = 0; nt < 4; nt++)
                    mma_f16(acc[mt][nt], al[mt], bh[nt]);
        }
    }

    const int crow = blockIdx.y * 128 + wm * 64 + (l >> 2);
    const int ccol = blockIdx.x * 128 + wn * 32 + (l & 3) * 2;
#pragma unroll
    for (int mt = 0; mt < 4; mt++) {
#pragma unroll
        for (int nt = 0; nt < 4; nt++) {
            float* p0 = C + (size_t)(crow + mt * 16)     * N + ccol + nt * 8;
            float* p1 = C + (size_t)(crow + mt * 16 + 8) * N + ccol + nt * 8;
            *(float2*)p0 = make_float2(acc[mt][nt][0], acc[mt][nt][1]);
            *(float2*)p1 = make_float2(acc[mt][nt][2], acc[mt][nt][3]);
        }
    }
}

// ---------------- RoPE + scale-fold + cache write ---------------------------
__global__ __launch_bounds__(256) void rope_kernel(
    const float* __restrict__ xqkv,
    const float* __restrict__ cosf_, const float* __restrict__ sinf_,
    float* __restrict__ qout, float* __restrict__ kcache, float* __restrict__ vcache)
{
    const int s   = blockIdx.x;
    const int tid = threadIdx.x;
    const float* row = xqkv + (size_t)s * QKV_N;

    for (int p = tid; p < NH * 64; p += 256) {
        int h = p >> 6, f = p & 63;
        float c  = cosf_[s * 64 + f];
        float sn = sinf_[s * 64 + f];
        float x1 = row[h * HD + 2 * f];
        float x2 = row[h * HD + 2 * f + 1];
        qout[(size_t)s * (NH * HD) + h * HD + 2 * f]     = (x1 * c - x2 * sn) * SCALE;
        qout[(size_t)s * (NH * HD) + h * HD + 2 * f + 1] = (x1 * sn + x2 * c) * SCALE;
    }
    for (int p = tid; p < NKV * 64; p += 256) {
        int h = p >> 6, f = p & 63;
        float c  = cosf_[s * 64 + f];
        float sn = sinf_[s * 64 + f];
        float x1 = row[DIM + h * HD + 2 * f];
        float x2 = row[DIM + h * HD + 2 * f + 1];
        kcache[(size_t)s * KV_ROW + h * HD + 2 * f]     = x1 * c - x2 * sn;
        kcache[(size_t)s * KV_ROW + h * HD + 2 * f + 1] = x1 * sn + x2 * c;
    }
    for (int i = tid; i < KV_ROW; i += 256)
        vcache[(size_t)s * KV_ROW + i] = row[DIM + NKV * HD + i];
}

// ---------------- q / kv split-bf16 prep for attention ----------------------
__global__ __launch_bounds__(256) void qsplit(
    const float* __restrict__ q,
    __nv_bfloat16* __restrict__ qhi, __nv_bfloat16* __restrict__ qlo)
{
    const int s = blockIdx.x, tid = threadIdx.x;
    for (int i = tid; i < NH * HD; i += 256) {
        int h = i >> 7, d = i & 127;
        float v = q[(size_t)s * (NH * HD) + i];
        __nv_bfloat16 hv = __float2bfloat16(v);
        size_t o = ((size_t)h * SEQLEN + s) * HD + d;
        qhi[o] = hv;
        qlo[o] = __float2bfloat16(v - __bfloat162float(hv));
    }
}
__global__ __launch_bounds__(256) void kvsplit(
    const float* __restrict__ kc, const float* __restrict__ vc,
    __nv_bfloat16* __restrict__ khi, __nv_bfloat16* __restrict__ klo,
    __nv_bfloat16* __restrict__ vhi, __nv_bfloat16* __restrict__ vlo)
{
    const int s = blockIdx.x, tid = threadIdx.x;
    for (int i = tid; i < NKV * HD; i += 256) {
        int h = i >> 7, d = i & 127;
        size_t o = ((size_t)h * SEQLEN + s) * HD + d;
        float kv = kc[(size_t)s * KV_ROW + i];
        __nv_bfloat16 kh = __float2bfloat16(kv);
        khi[o] = kh;
        klo[o] = __float2bfloat16(kv - __bfloat162float(kh));
        float vv = vc[(size_t)s * KV_ROW + i];
        __nv_bfloat16 vh = __float2bfloat16(vv);
        vhi[o] = vh;
        vlo[o] = __float2bfloat16(vv - __bfloat162float(vh));
    }
}

// ---------------- tensor-core causal flash attention (double-buffered) ------
#define ASTRIDE 272
#define ATILE   (64 * ASTRIDE)
#define ABUF    (4 * ATILE)
#define ATTN_SMEM (2 * ABUF)

__global__ __launch_bounds__(256, 1) void attn_tc(
    const __nv_bfloat16* __restrict__ Qh, const __nv_bfloat16* __restrict__ Ql,
    const __nv_bfloat16* __restrict__ Kh, const __nv_bfloat16* __restrict__ Kl,
    const __nv_bfloat16* __restrict__ Vh, const __nv_bfloat16* __restrict__ Vl,
    float* __restrict__ O)
{
    extern __shared__ __align__(128) char smraw[];
    const uint32_t sb = (uint32_t)__cvta_generic_to_shared(smraw);
    const int tid = threadIdx.x, w = tid >> 5, l = tid & 31;
    const int qt  = (int)gridDim.x - 1 - (int)blockIdx.x;
    const int h   = blockIdx.y;
    const int kvh = h >> 2;

    uint32_t qh_[8][4], ql_[8][4];
    {
        const uint32_t aoff = sb + (uint32_t)((w * 16 + (l & 15)) * ASTRIDE
                                              + (l >> 4) * 16);
        for (int part = 0; part < 2; part++) {
            const __nv_bfloat16* src = part ? Ql : Qh;
            const char* g0 = (const char*)(src + ((size_t)h * SEQLEN + qt * 128) * HD);
            for (int i = tid; i < 2048; i += 256)
                cp16(sb + (uint32_t)((i >> 4) * ASTRIDE + (i & 15) * 16),
                     g0 + (size_t)i * 16);
            asm volatile("cp.async.commit_group;" ::: "memory");
            asm volatile("cp.async.wait_group 0;" ::: "memory");
            __syncthreads();
            uint32_t (*dst)[4] = part ? ql_ : qh_;
#pragma unroll
            for (int g = 0; g < 8; g++)
                ldm4(dst[g][0], dst[g][1], dst[g][2], dst[g][3], aoff + g * 32);
            __syncthreads();
        }
    }

    float o[16][4];
#pragma unroll
    for (int t = 0; t < 16; t++)
#pragma unroll
        for (int i = 0; i < 4; i++) o[t][i] = 0.f;
    float m0 = -1e30f, m1 = -1e30f, l0 = 0.f, l1 = 0.f;

    const int row0 = qt * 128 + w * 16 + (l >> 2);
    const int l2 = l & 7, sel = l >> 3;
    const int nkb = 2 * qt + 2;

    auto load_kv = [&](int kb, uint32_t bufbase) {
        const size_t gbase = (((size_t)kvh * SEQLEN + (size_t)kb * 64) * HD) * 2;
        for (int i = tid; i < 1024; i += 256) {
            uint32_t soff = (uint32_t)((i >> 4) * ASTRIDE + (i & 15) * 16);
            size_t goff = gbase + (size_t)i * 16;
            cp16(bufbase + 0 * ATILE + soff, (const char*)Kh + goff);
            cp16(bufbase + 1 * ATILE + soff, (const char*)Kl + goff);
            cp16(bufbase + 2 * ATILE + soff, (const char*)Vh + goff);
            cp16(bufbase + 3 * ATILE + soff, (const char*)Vl + goff);
        }
        asm volatile("cp.async.commit_group;" ::: "memory");
    };

    int buf = 0;
    load_kv(0, sb);

    for (int kb = 0; kb < nkb; kb++) {
        if (kb + 1 < nkb) {
            load_kv(kb + 1, sb + (buf ^ 1) * ABUF);
            asm volatile("cp.async.wait_group 1;" ::: "memory");
        } else {
            asm volatile("cp.async.wait_group 0;" ::: "memory");
        }
        __syncthreads();
        const uint32_t bbase = sb + buf * ABUF;

        float sc[8][4];
#pragma unroll
        for (int t = 0; t < 8; t++)
#pragma unroll
            for (int i = 0; i < 4; i++) sc[t][i] = 0.f;

#pragma unroll
        for (int g = 0; g < 8; g++) {
#pragma unroll
            for (int n16 = 0; n16 < 4; n16++) {
                uint32_t kaddr = bbase + (uint32_t)((n16 * 16 + (sel >> 1) * 8 + l2)
                                                    * ASTRIDE + (sel & 1) * 16 + g * 32);
                uint32_t bh[2][2], bl[2][2];
                ldm4(bh[0][0], bh[0][1], bh[1][0], bh[1][1], kaddr);
                ldm4(bl[0][0], bl[0][1], bl[1][0], bl[1][1], kaddr + ATILE);
#pragma unroll
                for (int j = 0; j < 2; j++) {
                    int t = n16 * 2 + j;
                    mma_bf16(sc[t], qh_[g], bh[j]);
                    mma_bf16(sc[t], ql_[g], bh[j]);
                    mma_bf16(sc[t], qh_[g], bl[j]);
                }
            }
        }

        if (kb >= 2 * qt) {
#pragma unroll
            for (int t = 0; t < 8; t++) {
                int col = kb * 64 + t * 8 + 2 * (l & 3);
                if (col     > row0)     sc[t][0] = -1e30f;
                if (col + 1 > row0)     sc[t][1] = -1e30f;
                if (col     > row0 + 8) sc[t][2] = -1e30f;
                if (col + 1 > row0 + 8) sc[t][3] = -1e30f;
            }
        }

        float r0m = -1e30f, r1m = -1e30f;
#pragma unroll
        for (int t = 0; t < 8; t++) {
            r0m = fmaxf(r0m, fmaxf(sc[t][0], sc[t][1]));
            r1m = fmaxf(r1m, fmaxf(sc[t][2], sc[t][3]));
        }
        r0m = fmaxf(r0m, __shfl_xor_sync(0xffffffffu, r0m, 1));
        r0m = fmaxf(r0m, __shfl_xor_sync(0xffffffffu, r0m, 2));
        r1m = fmaxf(r1m, __shfl_xor_sync(0xffffffffu, r1m, 1));
        r1m = fmaxf(r1m, __shfl_xor_sync(0xffffffffu, r1m, 2));
        float nm0 = fmaxf(m0, r0m), nm1 = fmaxf(m1, r1m);
        float a0 = __expf(m0 - nm0), a1 = __expf(m1 - nm1);

        float s0 = 0.f, s1 = 0.f;
#pragma unroll
        for (int t = 0; t < 8; t++) {
            sc[t][0] = __expf(sc[t][0] - nm0); s0 += sc[t][0];
            sc[t][1] = __expf(sc[t][1] - nm0); s0 += sc[t][1];
            sc[t][2] = __expf(sc[t][2] - nm1); s1 += sc[t][2];
            sc[t][3] = __expf(sc[t][3] - nm1); s1 += sc[t][3];
        }
        s0 += __shfl_xor_sync(0xffffffffu, s0, 1);
        s0 += __shfl_xor_sync(0xffffffffu, s0, 2);
        s1 += __shfl_xor_sync(0xffffffffu, s1, 1);
        s1 += __shfl_xor_sync(0xffffffffu, s1, 2);
        l0 = l0 * a0 + s0;
        l1 = l1 * a1 + s1;
        m0 = nm0; m1 = nm1;
#pragma unroll
        for (int t = 0; t < 16; t++) {
            o[t][0] *= a0; o[t][1] *= a0;
            o[t][2] *= a1; o[t][3] *= a1;
        }

#pragma unroll
        for (int g = 0; g < 4; g++) {
            uint32_t aph[4], apl[4];
            split2(sc[2*g][0],   sc[2*g][1],   aph[0], apl[0]);
            split2(sc[2*g][2],   sc[2*g][3],   aph[1], apl[1]);
            split2(sc[2*g+1][0], sc[2*g+1][1], aph[2], apl[2]);
            split2(sc[2*g+1][2], sc[2*g+1][3], aph[3], apl[3]);
#pragma unroll
            for (int n16 = 0; n16 < 8; n16++) {
                uint32_t vaddr = bbase + 2 * ATILE
                    + (uint32_t)((g * 16 + (l & 15)) * ASTRIDE
                                 + n16 * 32 + (l >> 4) * 16);
                uint32_t bvh[2][2], bvl[2][2];
                ldm4t(bvh[0][0], bvh[0][1], bvh[1][0], bvh[1][1], vaddr);
                ldm4t(bvl[0][0], bvl[0][1], bvl[1][0], bvl[1][1], vaddr + ATILE);
#pragma unroll
                for (int j = 0; j < 2; j++) {
                    int t = n16 * 2 + j;
                    mma_bf16(o[t], aph, bvh[j]);
                    mma_bf16(o[t], apl, bvh[j]);
                    mma_bf16(o[t], aph, bvl[j]);
                }
            }
        }
        __syncthreads();
        buf ^= 1;
    }

    float i0 = 1.f / l0, i1 = 1.f / l1;
    const int colb = h * HD + 2 * (l & 3);
#pragma unroll
    for (int t = 0; t < 16; t++) {
        float* p0 = O + (size_t)row0 * (NH * HD) + colb + t * 8;
        float* p1 = O + (size_t)(row0 + 8) * (NH * HD) + colb + t * 8;
        *(float2*)p0 = make_float2(o[t][0] * i0, o[t][1] * i0);
        *(float2*)p1 = make_float2(o[t][2] * i1, o[t][3] * i1);
    }
}

// ---------------- launch ----------------------------------------------------
extern "C" void kernel_launch(void* const* d_in, const int* in_sizes, int n_in,
                              void* d_out, int out_size)
{
    const float* x     = (const float*)d_in[0];
    const float* cosf_ = (const float*)d_in[1];
    const float* sinf_ = (const float*)d_in[2];
    const float* in_ck = (const float*)d_in[5];
    const float* in_cv = (const float*)d_in[6];
    const float* Wqkv  = (const float*)d_in[7];
    const float* Wo    = (const float*)d_in[8];

    float* out     = (float*)d_out;
    float* cache_k = out + (size_t)SEQLEN * DIM;
    float* cache_v = cache_k + (size_t)WIN * KV_ROW;

    float *xqkv_p, *q_p, *attn_p;
    __half *xh_p, *xl_p, *ah_p, *al_p, *wq_p, *wo_p;
    __nv_bfloat16 *qhi_p, *qlo_p, *khi_p, *klo_p, *vhi_p, *vlo_p;
    cudaGetSymbolAddress((void**)&xqkv_p, g_xqkv);
    cudaGetSymbolAddress((void**)&q_p,    g_q);
    cudaGetSymbolAddress((void**)&attn_p, g_attn);
    cudaGetSymbolAddress((void**)&xh_p,   g_xh);
    cudaGetSymbolAddress((void**)&xl_p,   g_xl);
    cudaGetSymbolAddress((void**)&ah_p,   g_ah);
    cudaGetSymbolAddress((void**)&al_p,   g_al);
    cudaGetSymbolAddress((void**)&wq_p,   g_wq);
    cudaGetSymbolAddress((void**)&wo_p,   g_wo);
    cudaGetSymbolAddress((void**)&qhi_p,  g_qhi);
    cudaGetSymbolAddress((void**)&qlo_p,  g_qlo);
    cudaGetSymbolAddress((void**)&khi_p,  g_khi);
    cudaGetSymbolAddress((void**)&klo_p,  g_klo);
    cudaGetSymbolAddress((void**)&vhi_p,  g_vhi);
    cudaGetSymbolAddress((void**)&vlo_p,  g_vlo);

    size_t cache_bytes = (size_t)WIN * KV_ROW * sizeof(float);
    cudaMemcpyAsync(cache_k, in_ck, cache_bytes, cudaMemcpyDeviceToDevice, 0);
    cudaMemcpyAsync(cache_v, in_cv, cache_bytes, cudaMemcpyDeviceToDevice, 0);

    cudaFuncSetAttribute(gemm_mma, cudaFuncAttributeMaxDynamicSharedMemorySize,
                         GEMM_SMEM);
    cudaFuncSetAttribute(attn_tc, cudaFuncAttributeMaxDynamicSharedMemorySize,
                         ATTN_SMEM);

    // conversions
    {
        long long t4;
        t4 = (long long)SEQLEN * DIM / 4;
        convert_hilo_f16<<<(unsigned)((t4 + 255) / 256), 256>>>(x, xh_p, xl_p, t4);
        t4 = (long long)QKV_N * DIM / 4;
        convert_f16<<<(unsigned)((t4 + 255) / 256), 256>>>(Wqkv, wq_p, t4);
        t4 = (long long)DIM * DIM / 4;
        convert_f16<<<(unsigned)((t4 + 255) / 256), 256>>>(Wo, wo_p, t4);
    }

    // 1) QKV projection (fp16 2-term)
    gemm_mma<<<dim3(QKV_N / 128, SEQLEN / 128), 256, GEMM_SMEM>>>(
        xh_p, xl_p, wq_p, xqkv_p, QKV_N);

    // 2) RoPE + cache writes
    rope_kernel<<<SEQLEN, 256>>>(xqkv_p, cosf_, sinf_, q_p, cache_k, cache_v);

    // 3) split q/k/v for attention (bf16 3-term)
    qsplit<<<SEQLEN, 256>>>(q_p, qhi_p, qlo_p);
    kvsplit<<<SEQLEN, 256>>>(cache_k, cache_v, khi_p, klo_p, vhi_p, vlo_p);

    // 4) tensor-core causal flash attention
    attn_tc<<<dim3(SEQLEN / 128, NH), 256, ATTN_SMEM>>>(
        qhi_p, qlo_p, khi_p, klo_p, vhi_p, vlo_p, attn_p);

    // 5) output projection (fp16 2-term)
    {
        long long t4 = (long long)SEQLEN * DIM / 4;
        convert_hilo_f16<<<(unsigned)((t4 + 255) / 256), 256>>>(attn_p, ah_p, al_p, t4);
    }
    gemm_mma<<<dim3(DIM / 128, SEQLEN / 128), 256, GEMM_SMEM>>>(
        ah_p, al_p, wo_p, out, DIM);
}

// round 9
// speedup vs baseline: 1.8501x; 1.0209x over previous
#include <cuda_runtime.h>
#include <cuda_bf16.h>
#include <cuda_fp16.h>
#include <cstdint>
#include <math.h>

#define SEQLEN 2048
#define DIM    4096
#define NH     32
#define HD     128
#define NKV    8
#define QKV_N  6144
#define KV_ROW 1024
#define WIN    4096
#define SCALE  0.08838834764831845f

// ---------------- scratch (device globals) ----------------------------------
__device__ float g_xqkv[SEQLEN * QKV_N];
// fp16 GEMM operands
__device__ __half g_xh [(size_t)SEQLEN * DIM];
__device__ __half g_xl [(size_t)SEQLEN * DIM];
__device__ __half g_ah [(size_t)SEQLEN * DIM];
__device__ __half g_al [(size_t)SEQLEN * DIM];
__device__ __half g_wq [(size_t)QKV_N * DIM];
__device__ __half g_wo [(size_t)DIM * DIM];
// attention split q/k/v (bf16 3-term): [head][seq][HD]
__device__ __nv_bfloat16 g_qhi[(size_t)NH  * SEQLEN * HD];
__device__ __nv_bfloat16 g_qlo[(size_t)NH  * SEQLEN * HD];
__device__ __nv_bfloat16 g_khi[(size_t)NKV * SEQLEN * HD];
__device__ __nv_bfloat16 g_klo[(size_t)NKV * SEQLEN * HD];
__device__ __nv_bfloat16 g_vhi[(size_t)NKV * SEQLEN * HD];
__device__ __nv_bfloat16 g_vlo[(size_t)NKV * SEQLEN * HD];

// ---------------- common PTX helpers ----------------------------------------
__device__ __forceinline__ void cp16(uint32_t d, const void* g) {
    asm volatile("cp.async.cg.shared.global [%0], [%1], 16;\n"
                 :: "r"(d), "l"(__cvta_generic_to_global(g)) : "memory");
}
__device__ __forceinline__ void ldm4(uint32_t& r0, uint32_t& r1,
                                     uint32_t& r2, uint32_t& r3, uint32_t a) {
    asm volatile("ldmatrix.sync.aligned.m8n8.x4.shared.b16 {%0,%1,%2,%3}, [%4];"
                 : "=r"(r0), "=r"(r1), "=r"(r2), "=r"(r3) : "r"(a));
}
__device__ __forceinline__ void ldm4t(uint32_t& r0, uint32_t& r1,
                                      uint32_t& r2, uint32_t& r3, uint32_t a) {
    asm volatile("ldmatrix.sync.aligned.m8n8.x4.trans.shared.b16 {%0,%1,%2,%3}, [%4];"
                 : "=r"(r0), "=r"(r1), "=r"(r2), "=r"(r3) : "r"(a));
}
__device__ __forceinline__ void mma_bf16(float* c, const uint32_t* a,
                                         const uint32_t* b) {
    asm volatile(
        "mma.sync.aligned.m16n8k16.row.col.f32.bf16.bf16.f32 "
        "{%0,%1,%2,%3}, {%4,%5,%6,%7}, {%8,%9}, {%0,%1,%2,%3};"
        : "+f"(c[0]), "+f"(c[1]), "+f"(c[2]), "+f"(c[3])
        : "r"(a[0]), "r"(a[1]), "r"(a[2]), "r"(a[3]), "r"(b[0]), "r"(b[1]));
}
__device__ __forceinline__ void mma_f16(float* c, const uint32_t* a,
                                        const uint32_t* b) {
    asm volatile(
        "mma.sync.aligned.m16n8k16.row.col.f32.f16.f16.f32 "
        "{%0,%1,%2,%3}, {%4,%5,%6,%7}, {%8,%9}, {%0,%1,%2,%3};"
        : "+f"(c[0]), "+f"(c[1]), "+f"(c[2]), "+f"(c[3])
        : "r"(a[0]), "r"(a[1]), "r"(a[2]), "r"(a[3]), "r"(b[0]), "r"(b[1]));
}
__device__ __forceinline__ void split2(float x, float y, uint32_t& hi, uint32_t& lo) {
    __nv_bfloat162 h = __floats2bfloat162_rn(x, y);
    float rx = x - __bfloat162float(h.x);
    float ry = y - __bfloat162float(h.y);
    __nv_bfloat162 r = __floats2bfloat162_rn(rx, ry);
    hi = *(uint32_t*)&h; lo = *(uint32_t*)&r;
}
__device__ __forceinline__ void splitbf(float v, __nv_bfloat16& h, __nv_bfloat16& l) {
    h = __float2bfloat16(v);
    l = __float2bfloat16(v - __bfloat162float(h));
}

// ---------------- fp32 -> fp16 hi/lo, and fp32 -> fp16 ----------------------
__global__ __launch_bounds__(256) void convert_hilo_f16(
    const float* __restrict__ in, __half* __restrict__ hi,
    __half* __restrict__ lo, long long total4)
{
    long long i = (long long)blockIdx.x * 256 + threadIdx.x;
    if (i >= total4) return;
    float4 v = ((const float4*)in)[i];
    float vv[4] = {v.x, v.y, v.z, v.w};
    union { unsigned long long u; __half h[4]; } H, L;
#pragma unroll
    for (int j = 0; j < 4; j++) {
        __half h = __float2half_rn(vv[j]);
        H.h[j] = h;
        L.h[j] = __float2half_rn(vv[j] - __half2float(h));
    }
    ((unsigned long long*)hi)[i] = H.u;
    ((unsigned long long*)lo)[i] = L.u;
}
__global__ __launch_bounds__(256) void convert_f16(
    const float* __restrict__ in, __half* __restrict__ out, long long total4)
{
    long long i = (long long)blockIdx.x * 256 + threadIdx.x;
    if (i >= total4) return;
    float4 v = ((const float4*)in)[i];
    float vv[4] = {v.x, v.y, v.z, v.w};
    union { unsigned long long u; __half h[4]; } H;
#pragma unroll
    for (int j = 0; j < 4; j++) H.h[j] = __float2half_rn(vv[j]);
    ((unsigned long long*)out)[i] = H.u;
}

// ---------------- fp16 2-term mma.sync GEMM: C = A * B^T ---------------------
#define GK       4096
#define NCHUNK   (GK / 32)               // 128
#define PTILEB   (128 * 64)              // 8192 per part-tile
#define STAGEB   (3 * PTILEB)            // 24576
#define GSTAGES  4
#define GEMM_SMEM (GSTAGES * STAGEB)     // 98304

__global__ __launch_bounds__(256, 2) void gemm_mma(
    const __half* __restrict__ Ah, const __half* __restrict__ Al,
    const __half* __restrict__ Bh, float* __restrict__ C, int N)
{
    extern __shared__ __align__(128) char smraw[];
    const uint32_t sb = (uint32_t)__cvta_generic_to_shared(smraw);

    const int tid = threadIdx.x;
    const int w   = tid >> 5;
    const int l   = tid & 31;
    const int wm  = w & 1;
    const int wn  = w >> 1;

    const size_t arow_g = (size_t)blockIdx.y * 128 * GK;
    const size_t brow_g = (size_t)blockIdx.x * 128 * GK;
    const char* gp[3] = { (const char*)(Ah + arow_g), (const char*)(Al + arow_g),
                          (const char*)(Bh + brow_g) };

    auto load_chunk = [&](int t, uint32_t st) {
        const size_t gk = (size_t)t * 64;
#pragma unroll
        for (int part = 0; part < 3; part++) {
#pragma unroll
            for (int j = 0; j < 2; j++) {
                int slot = tid + j * 256;
                int r = slot >> 2, c = slot & 3;
                uint32_t dc = (uint32_t)((c * 16) ^ (((r >> 1) & 3) * 16));
                cp16(st + part * PTILEB + r * 64 + dc,
                     gp[part] + (size_t)r * (GK * 2) + gk + c * 16);
            }
        }
    };

    const int arow = wm * 64 + (l & 15);
    const uint32_t arb  = (uint32_t)(arow * 64);
    const uint32_t axor = (uint32_t)(((arow >> 1) & 3) * 16);
    const int ac0 = (l >> 4);
    const int l2 = l & 7, sel = l >> 3;
    const int brow = wn * 32 + (sel >> 1) * 8 + l2;
    const uint32_t brb  = (uint32_t)(brow * 64);
    const uint32_t bxor = (uint32_t)(((brow >> 1) & 3) * 16);
    const int bc0 = (sel & 1);

    float acc[4][4][4];
#pragma unroll
    for (int mt = 0; mt < 4; mt++)
#pragma unroll
        for (int nt = 0; nt < 4; nt++)
#pragma unroll
            for (int i = 0; i < 4; i++) acc[mt][nt][i] = 0.f;

    load_chunk(0, sb);
    asm volatile("cp.async.commit_group;" ::: "memory");
    load_chunk(1, sb + STAGEB);
    asm volatile("cp.async.commit_group;" ::: "memory");
    load_chunk(2, sb + 2 * STAGEB);
    asm volatile("cp.async.commit_group;" ::: "memory");

    for (int k = 0; k < NCHUNK; k++) {
        if (k + 2 < NCHUNK)
            asm volatile("cp.async.wait_group 2;" ::: "memory");
        else if (k + 1 < NCHUNK)
            asm volatile("cp.async.wait_group 1;" ::: "memory");
        else
            asm volatile("cp.async.wait_group 0;" ::: "memory");
        __syncthreads();

        if (k + 3 < NCHUNK) {
            load_chunk(k + 3, sb + ((k + 3) & 3) * STAGEB);
            asm volatile("cp.async.commit_group;" ::: "memory");
        }

        const uint32_t st = sb + (k & 3) * STAGEB;
#pragma unroll
        for (int ks = 0; ks < 2; ks++) {
            const uint32_t ach = (uint32_t)(((ks * 2 + ac0) * 16)) ^ axor;
            const uint32_t bch = (uint32_t)(((ks * 2 + bc0) * 16)) ^ bxor;

            uint32_t ah[4][4], bh[4][2];
#pragma unroll
            for (int mt = 0; mt < 4; mt++)
                ldm4(ah[mt][0], ah[mt][1], ah[mt][2], ah[mt][3],
                     st + arb + mt * 1024 + ach);
#pragma unroll
            for (int np = 0; np < 2; np++)
                ldm4(bh[2*np][0], bh[2*np][1], bh[2*np+1][0], bh[2*np+1][1],
                     st + 2 * PTILEB + brb + np * 1024 + bch);
#pragma unroll
            for (int mt = 0; mt < 4; mt++)
#pragma unroll
                for (int nt = 0; nt < 4; nt++)
                    mma_f16(acc[mt][nt], ah[mt], bh[nt]);

            uint32_t al[4][4];
#pragma unroll
            for (int mt = 0; mt < 4; mt++)
                ldm4(al[mt][0], al[mt][1], al[mt][2], al[mt][3],
                     st + PTILEB + arb + mt * 1024 + ach);
#pragma unroll
            for (int mt = 0; mt < 4; mt++)
#pragma unroll
                for (int nt = 0; nt < 4; nt++)
                    mma_f16(acc[mt][nt], al[mt], bh[nt]);
        }
    }

    const int crow = blockIdx.y * 128 + wm * 64 + (l >> 2);
    const int ccol = blockIdx.x * 128 + wn * 32 + (l & 3) * 2;
#pragma unroll
    for (int mt = 0; mt < 4; mt++) {
#pragma unroll
        for (int nt = 0; nt < 4; nt++) {
            float* p0 = C + (size_t)(crow + mt * 16)     * N + ccol + nt * 8;
            float* p1 = C + (size_t)(crow + mt * 16 + 8) * N + ccol + nt * 8;
            *(float2*)p0 = make_float2(acc[mt][nt][0], acc[mt][nt][1]);
            *(float2*)p1 = make_float2(acc[mt][nt][2], acc[mt][nt][3]);
        }
    }
}

// ---------------- fused RoPE + scale + cache + attention-operand split ------
__global__ __launch_bounds__(256) void rope_fused(
    const float* __restrict__ xqkv,
    const float* __restrict__ cosf_, const float* __restrict__ sinf_,
    float* __restrict__ kcache, float* __restrict__ vcache,
    __nv_bfloat16* __restrict__ qhi, __nv_bfloat16* __restrict__ qlo,
    __nv_bfloat16* __restrict__ khi, __nv_bfloat16* __restrict__ klo,
    __nv_bfloat16* __restrict__ vhi, __nv_bfloat16* __restrict__ vlo)
{
    const int s   = blockIdx.x;
    const int tid = threadIdx.x;
    const float* row = xqkv + (size_t)s * QKV_N;

    // Q: rotate, fold SCALE, split -> qhi/qlo [h][s][d]
    for (int p = tid; p < NH * 64; p += 256) {
        int h = p >> 6, f = p & 63;
        float c  = cosf_[s * 64 + f];
        float sn = sinf_[s * 64 + f];
        float x1 = row[h * HD + 2 * f];
        float x2 = row[h * HD + 2 * f + 1];
        float o1 = (x1 * c - x2 * sn) * SCALE;
        float o2 = (x1 * sn + x2 * c) * SCALE;
        size_t o = ((size_t)h * SEQLEN + s) * HD + 2 * f;
        __nv_bfloat16 h1, l1, h2, l2;
        splitbf(o1, h1, l1); splitbf(o2, h2, l2);
        qhi[o] = h1; qhi[o + 1] = h2;
        qlo[o] = l1; qlo[o + 1] = l2;
    }
    // K: rotate -> fp32 cache + bf16 hi/lo split
    for (int p = tid; p < NKV * 64; p += 256) {
        int h = p >> 6, f = p & 63;
        float c  = cosf_[s * 64 + f];
        float sn = sinf_[s * 64 + f];
        float x1 = row[DIM + h * HD + 2 * f];
        float x2 = row[DIM + h * HD + 2 * f + 1];
        float o1 = x1 * c - x2 * sn;
        float o2 = x1 * sn + x2 * c;
        kcache[(size_t)s * KV_ROW + h * HD + 2 * f]     = o1;
        kcache[(size_t)s * KV_ROW + h * HD + 2 * f + 1] = o2;
        size_t o = ((size_t)h * SEQLEN + s) * HD + 2 * f;
        __nv_bfloat16 h1, l1, h2, l2;
        splitbf(o1, h1, l1); splitbf(o2, h2, l2);
        khi[o] = h1; khi[o + 1] = h2;
        klo[o] = l1; klo[o + 1] = l2;
    }
    // V: copy -> fp32 cache + bf16 hi/lo split
    for (int i = tid; i < KV_ROW; i += 256) {
        int h = i >> 7, d = i & 127;
        float v = row[DIM + NKV * HD + i];
        vcache[(size_t)s * KV_ROW + i] = v;
        size_t o = ((size_t)h * SEQLEN + s) * HD + d;
        __nv_bfloat16 hv, lv;
        splitbf(v, hv, lv);
        vhi[o] = hv; vlo[o] = lv;
    }
}

// ---------------- tensor-core causal flash attention (double-buffered) ------
// Epilogue writes fp16 hi/lo directly (feeds Wo GEMM).
#define ASTRIDE 272
#define ATILE   (64 * ASTRIDE)
#define ABUF    (4 * ATILE)
#define ATTN_SMEM (2 * ABUF)

__global__ __launch_bounds__(256, 1) void attn_tc(
    const __nv_bfloat16* __restrict__ Qh, const __nv_bfloat16* __restrict__ Ql,
    const __nv_bfloat16* __restrict__ Kh, const __nv_bfloat16* __restrict__ Kl,
    const __nv_bfloat16* __restrict__ Vh, const __nv_bfloat16* __restrict__ Vl,
    __half* __restrict__ OH, __half* __restrict__ OL)
{
    extern __shared__ __align__(128) char smraw[];
    const uint32_t sb = (uint32_t)__cvta_generic_to_shared(smraw);
    const int tid = threadIdx.x, w = tid >> 5, l = tid & 31;
    const int qt  = (int)gridDim.x - 1 - (int)blockIdx.x;
    const int h   = blockIdx.y;
    const int kvh = h >> 2;

    uint32_t qh_[8][4], ql_[8][4];
    {
        const uint32_t aoff = sb + (uint32_t)((w * 16 + (l & 15)) * ASTRIDE
                                              + (l >> 4) * 16);
        for (int part = 0; part < 2; part++) {
            const __nv_bfloat16* src = part ? Ql : Qh;
            const char* g0 = (const char*)(src + ((size_t)h * SEQLEN + qt * 128) * HD);
            for (int i = tid; i < 2048; i += 256)
                cp16(sb + (uint32_t)((i >> 4) * ASTRIDE + (i & 15) * 16),
                     g0 + (size_t)i * 16);
            asm volatile("cp.async.commit_group;" ::: "memory");
            asm volatile("cp.async.wait_group 0;" ::: "memory");
            __syncthreads();
            uint32_t (*dst)[4] = part ? ql_ : qh_;
#pragma unroll
            for (int g = 0; g < 8; g++)
                ldm4(dst[g][0], dst[g][1], dst[g][2], dst[g][3], aoff + g * 32);
            __syncthreads();
        }
    }

    float o[16][4];
#pragma unroll
    for (int t = 0; t < 16; t++)
#pragma unroll
        for (int i = 0; i < 4; i++) o[t][i] = 0.f;
    float m0 = -1e30f, m1 = -1e30f, l0 = 0.f, l1 = 0.f;

    const int row0 = qt * 128 + w * 16 + (l >> 2);
    const int l2 = l & 7, sel = l >> 3;
    const int nkb = 2 * qt + 2;

    auto load_kv = [&](int kb, uint32_t bufbase) {
        const size_t gbase = (((size_t)kvh * SEQLEN + (size_t)kb * 64) * HD) * 2;
        for (int i = tid; i < 1024; i += 256) {
            uint32_t soff = (uint32_t)((i >> 4) * ASTRIDE + (i & 15) * 16);
            size_t goff = gbase + (size_t)i * 16;
            cp16(bufbase + 0 * ATILE + soff, (const char*)Kh + goff);
            cp16(bufbase + 1 * ATILE + soff, (const char*)Kl + goff);
            cp16(bufbase + 2 * ATILE + soff, (const char*)Vh + goff);
            cp16(bufbase + 3 * ATILE + soff, (const char*)Vl + goff);
        }
        asm volatile("cp.async.commit_group;" ::: "memory");
    };

    int buf = 0;
    load_kv(0, sb);

    for (int kb = 0; kb < nkb; kb++) {
        if (kb + 1 < nkb) {
            load_kv(kb + 1, sb + (buf ^ 1) * ABUF);
            asm volatile("cp.async.wait_group 1;" ::: "memory");
        } else {
            asm volatile("cp.async.wait_group 0;" ::: "memory");
        }
        __syncthreads();
        const uint32_t bbase = sb + buf * ABUF;

        float sc[8][4];
#pragma unroll
        for (int t = 0; t < 8; t++)
#pragma unroll
            for (int i = 0; i < 4; i++) sc[t][i] = 0.f;

#pragma unroll
        for (int g = 0; g < 8; g++) {
#pragma unroll
            for (int n16 = 0; n16 < 4; n16++) {
                uint32_t kaddr = bbase + (uint32_t)((n16 * 16 + (sel >> 1) * 8 + l2)
                                                    * ASTRIDE + (sel & 1) * 16 + g * 32);
                uint32_t bh[2][2], bl[2][2];
                ldm4(bh[0][0], bh[0][1], bh[1][0], bh[1][1], kaddr);
                ldm4(bl[0][0], bl[0][1], bl[1][0], bl[1][1], kaddr + ATILE);
#pragma unroll
                for (int j = 0; j < 2; j++) {
                    int t = n16 * 2 + j;
                    mma_bf16(sc[t], qh_[g], bh[j]);
                    mma_bf16(sc[t], ql_[g], bh[j]);
                    mma_bf16(sc[t], qh_[g], bl[j]);
                }
            }
        }

        if (kb >= 2 * qt) {
#pragma unroll
            for (int t = 0; t < 8; t++) {
                int col = kb * 64 + t * 8 + 2 * (l & 3);
                if (col     > row0)     sc[t][0] = -1e30f;
                if (col + 1 > row0)     sc[t][1] = -1e30f;
                if (col     > row0 + 8) sc[t][2] = -1e30f;
                if (col + 1 > row0 + 8) sc[t][3] = -1e30f;
            }
        }

        float r0m = -1e30f, r1m = -1e30f;
#pragma unroll
        for (int t = 0; t < 8; t++) {
            r0m = fmaxf(r0m, fmaxf(sc[t][0], sc[t][1]));
            r1m = fmaxf(r1m, fmaxf(sc[t][2], sc[t][3]));
        }
        r0m = fmaxf(r0m, __shfl_xor_sync(0xffffffffu, r0m, 1));
        r0m = fmaxf(r0m, __shfl_xor_sync(0xffffffffu, r0m, 2));
        r1m = fmaxf(r1m, __shfl_xor_sync(0xffffffffu, r1m, 1));
        r1m = fmaxf(r1m, __shfl_xor_sync(0xffffffffu, r1m, 2));
        float nm0 = fmaxf(m0, r0m), nm1 = fmaxf(m1, r1m);
        float a0 = __expf(m0 - nm0), a1 = __expf(m1 - nm1);

        float s0 = 0.f, s1 = 0.f;
#pragma unroll
        for (int t = 0; t < 8; t++) {
            sc[t][0] = __expf(sc[t][0] - nm0); s0 += sc[t][0];
            sc[t][1] = __expf(sc[t][1] - nm0); s0 += sc[t][1];
            sc[t][2] = __expf(sc[t][2] - nm1); s1 += sc[t][2];
            sc[t][3] = __expf(sc[t][3] - nm1); s1 += sc[t][3];
        }
        s0 += __shfl_xor_sync(0xffffffffu, s0, 1);
        s0 += __shfl_xor_sync(0xffffffffu, s0, 2);
        s1 += __shfl_xor_sync(0xffffffffu, s1, 1);
        s1 += __shfl_xor_sync(0xffffffffu, s1, 2);
        l0 = l0 * a0 + s0;
        l1 = l1 * a1 + s1;
        m0 = nm0; m1 = nm1;
#pragma unroll
        for (int t = 0; t < 16; t++) {
            o[t][0] *= a0; o[t][1] *= a0;
            o[t][2] *= a1; o[t][3] *= a1;
        }

#pragma unroll
        for (int g = 0; g < 4; g++) {
            uint32_t aph[4], apl[4];
            split2(sc[2*g][0],   sc[2*g][1],   aph[0], apl[0]);
            split2(sc[2*g][2],   sc[2*g][3],   aph[1], apl[1]);
            split2(sc[2*g+1][0], sc[2*g+1][1], aph[2], apl[2]);
            split2(sc[2*g+1][2], sc[2*g+1][3], aph[3], apl[3]);
#pragma unroll
            for (int n16 = 0; n16 < 8; n16++) {
                uint32_t vaddr = bbase + 2 * ATILE
                    + (uint32_t)((g * 16 + (l & 15)) * ASTRIDE
                                 + n16 * 32 + (l >> 4) * 16);
                uint32_t bvh[2][2], bvl[2][2];
                ldm4t(bvh[0][0], bvh[0][1], bvh[1][0], bvh[1][1], vaddr);
                ldm4t(bvl[0][0], bvl[0][1], bvl[1][0], bvl[1][1], vaddr + ATILE);
#pragma unroll
                for (int j = 0; j < 2; j++) {
                    int t = n16 * 2 + j;
                    mma_bf16(o[t], aph, bvh[j]);
                    mma_bf16(o[t], apl, bvh[j]);
                    mma_bf16(o[t], aph, bvl[j]);
                }
            }
        }
        __syncthreads();
        buf ^= 1;
    }

    // epilogue: write fp16 hi/lo directly (A operand of Wo GEMM)
    float i0 = 1.f / l0, i1 = 1.f / l1;
    const int colb = h * HD + 2 * (l & 3);
#pragma unroll
    for (int t = 0; t < 16; t++) {
        {
            float v0 = o[t][0] * i0, v1 = o[t][1] * i0;
            __half h0 = __float2half_rn(v0), h1 = __float2half_rn(v1);
            __half e0 = __float2half_rn(v0 - __half2float(h0));
            __half e1 = __float2half_rn(v1 - __half2float(h1));
            size_t off = (size_t)row0 * DIM + colb + t * 8;
            *(__half2*)(OH + off) = __halves2half2(h0, h1);
            *(__half2*)(OL + off) = __halves2half2(e0, e1);
        }
        {
            float v0 = o[t][2] * i1, v1 = o[t][3] * i1;
            __half h0 = __float2half_rn(v0), h1 = __float2half_rn(v1);
            __half e0 = __float2half_rn(v0 - __half2float(h0));
            __half e1 = __float2half_rn(v1 - __half2float(h1));
            size_t off = (size_t)(row0 + 8) * DIM + colb + t * 8;
            *(__half2*)(OH + off) = __halves2half2(h0, h1);
            *(__half2*)(OL + off) = __halves2half2(e0, e1);
        }
    }
}

// ---------------- launch ----------------------------------------------------
extern "C" void kernel_launch(void* const* d_in, const int* in_sizes, int n_in,
                              void* d_out, int out_size)
{
    const float* x     = (const float*)d_in[0];
    const float* cosf_ = (const float*)d_in[1];
    const float* sinf_ = (const float*)d_in[2];
    const float* in_ck = (const float*)d_in[5];
    const float* in_cv = (const float*)d_in[6];
    const float* Wqkv  = (const float*)d_in[7];
    const float* Wo    = (const float*)d_in[8];

    float* out     = (float*)d_out;
    float* cache_k = out + (size_t)SEQLEN * DIM;
    float* cache_v = cache_k + (size_t)WIN * KV_ROW;

    float* xqkv_p;
    __half *xh_p, *xl_p, *ah_p, *al_p, *wq_p, *wo_p;
    __nv_bfloat16 *qhi_p, *qlo_p, *khi_p, *klo_p, *vhi_p, *vlo_p;
    cudaGetSymbolAddress((void**)&xqkv_p, g_xqkv);
    cudaGetSymbolAddress((void**)&xh_p,   g_xh);
    cudaGetSymbolAddress((void**)&xl_p,   g_xl);
    cudaGetSymbolAddress((void**)&ah_p,   g_ah);
    cudaGetSymbolAddress((void**)&al_p,   g_al);
    cudaGetSymbolAddress((void**)&wq_p,   g_wq);
    cudaGetSymbolAddress((void**)&wo_p,   g_wo);
    cudaGetSymbolAddress((void**)&qhi_p,  g_qhi);
    cudaGetSymbolAddress((void**)&qlo_p,  g_qlo);
    cudaGetSymbolAddress((void**)&khi_p,  g_khi);
    cudaGetSymbolAddress((void**)&klo_p,  g_klo);
    cudaGetSymbolAddress((void**)&vhi_p,  g_vhi);
    cudaGetSymbolAddress((void**)&vlo_p,  g_vlo);

    size_t cache_bytes = (size_t)WIN * KV_ROW * sizeof(float);
    cudaMemcpyAsync(cache_k, in_ck, cache_bytes, cudaMemcpyDeviceToDevice, 0);
    cudaMemcpyAsync(cache_v, in_cv, cache_bytes, cudaMemcpyDeviceToDevice, 0);

    cudaFuncSetAttribute(gemm_mma, cudaFuncAttributeMaxDynamicSharedMemorySize,
                         GEMM_SMEM);
    cudaFuncSetAttribute(attn_tc, cudaFuncAttributeMaxDynamicSharedMemorySize,
                         ATTN_SMEM);

    // conversions
    {
        long long t4;
        t4 = (long long)SEQLEN * DIM / 4;
        convert_hilo_f16<<<(unsigned)((t4 + 255) / 256), 256>>>(x, xh_p, xl_p, t4);
        t4 = (long long)QKV_N * DIM / 4;
        convert_f16<<<(unsigned)((t4 + 255) / 256), 256>>>(Wqkv, wq_p, t4);
        t4 = (long long)DIM * DIM / 4;
        convert_f16<<<(unsigned)((t4 + 255) / 256), 256>>>(Wo, wo_p, t4);
    }

    // 1) QKV projection (fp16 2-term)
    gemm_mma<<<dim3(QKV_N / 128, SEQLEN / 128), 256, GEMM_SMEM>>>(
        xh_p, xl_p, wq_p, xqkv_p, QKV_N);

    // 2) fused RoPE + caches + attention-operand splits
    rope_fused<<<SEQLEN, 256>>>(xqkv_p, cosf_, sinf_, cache_k, cache_v,
                                qhi_p, qlo_p, khi_p, klo_p, vhi_p, vlo_p);

    // 3) tensor-core causal flash attention, fp16 hi/lo epilogue
    attn_tc<<<dim3(SEQLEN / 128, NH), 256, ATTN_SMEM>>>(
        qhi_p, qlo_p, khi_p, klo_p, vhi_p, vlo_p, ah_p, al_p);

    // 4) output projection (fp16 2-term)
    gemm_mma<<<dim3(DIM / 128, SEQLEN / 128), 256, GEMM_SMEM>>>(
        ah_p, al_p, wo_p, out, DIM);
}

// round 10
// speedup vs baseline: 1.8876x; 1.0203x over previous
#include <cuda_runtime.h>
#include <cuda_bf16.h>
#include <cuda_fp16.h>
#include <cstdint>
#include <math.h>

#define SEQLEN 2048
#define DIM    4096
#define NH     32
#define HD     128
#define NKV    8
#define QKV_N  6144
#define KV_ROW 1024
#define WIN    4096
#define SCALE  0.08838834764831845f

// ---------------- scratch (device globals) ----------------------------------
__device__ float g_xqkv[SEQLEN * QKV_N];
__device__ __half g_xh [(size_t)SEQLEN * DIM];
__device__ __half g_xl [(size_t)SEQLEN * DIM];
__device__ __half g_ah [(size_t)SEQLEN * DIM];
__device__ __half g_al [(size_t)SEQLEN * DIM];
__device__ __half g_wq [(size_t)QKV_N * DIM];
__device__ __half g_wo [(size_t)DIM * DIM];
__device__ __nv_bfloat16 g_qhi[(size_t)NH  * SEQLEN * HD];
__device__ __nv_bfloat16 g_qlo[(size_t)NH  * SEQLEN * HD];
__device__ __nv_bfloat16 g_khi[(size_t)NKV * SEQLEN * HD];
__device__ __nv_bfloat16 g_klo[(size_t)NKV * SEQLEN * HD];
__device__ __nv_bfloat16 g_vhi[(size_t)NKV * SEQLEN * HD];
__device__ __nv_bfloat16 g_vlo[(size_t)NKV * SEQLEN * HD];

// ---------------- common PTX helpers ----------------------------------------
__device__ __forceinline__ void cp16(uint32_t d, const void* g) {
    asm volatile("cp.async.cg.shared.global [%0], [%1], 16;\n"
                 :: "r"(d), "l"(__cvta_generic_to_global(g)) : "memory");
}
__device__ __forceinline__ void ldm4(uint32_t& r0, uint32_t& r1,
                                     uint32_t& r2, uint32_t& r3, uint32_t a) {
    asm volatile("ldmatrix.sync.aligned.m8n8.x4.shared.b16 {%0,%1,%2,%3}, [%4];"
                 : "=r"(r0), "=r"(r1), "=r"(r2), "=r"(r3) : "r"(a));
}
__device__ __forceinline__ void ldm4t(uint32_t& r0, uint32_t& r1,
                                      uint32_t& r2, uint32_t& r3, uint32_t a) {
    asm volatile("ldmatrix.sync.aligned.m8n8.x4.trans.shared.b16 {%0,%1,%2,%3}, [%4];"
                 : "=r"(r0), "=r"(r1), "=r"(r2), "=r"(r3) : "r"(a));
}
__device__ __forceinline__ void mma_bf16(float* c, const uint32_t* a,
                                         const uint32_t* b) {
    asm volatile(
        "mma.sync.aligned.m16n8k16.row.col.f32.bf16.bf16.f32 "
        "{%0,%1,%2,%3}, {%4,%5,%6,%7}, {%8,%9}, {%0,%1,%2,%3};"
        : "+f"(c[0]), "+f"(c[1]), "+f"(c[2]), "+f"(c[3])
        : "r"(a[0]), "r"(a[1]), "r"(a[2]), "r"(a[3]), "r"(b[0]), "r"(b[1]));
}
__device__ __forceinline__ void mma_f16(float* c, const uint32_t* a,
                                        const uint32_t* b) {
    asm volatile(
        "mma.sync.aligned.m16n8k16.row.col.f32.f16.f16.f32 "
        "{%0,%1,%2,%3}, {%4,%5,%6,%7}, {%8,%9}, {%0,%1,%2,%3};"
        : "+f"(c[0]), "+f"(c[1]), "+f"(c[2]), "+f"(c[3])
        : "r"(a[0]), "r"(a[1]), "r"(a[2]), "r"(a[3]), "r"(b[0]), "r"(b[1]));
}
__device__ __forceinline__ void split2(float x, float y, uint32_t& hi, uint32_t& lo) {
    __nv_bfloat162 h = __floats2bfloat162_rn(x, y);
    float rx = x - __bfloat162float(h.x);
    float ry = y - __bfloat162float(h.y);
    __nv_bfloat162 r = __floats2bfloat162_rn(rx, ry);
    hi = *(uint32_t*)&h; lo = *(uint32_t*)&r;
}
__device__ __forceinline__ void splitbf(float v, __nv_bfloat16& h, __nv_bfloat16& l) {
    h = __float2bfloat16(v);
    l = __float2bfloat16(v - __bfloat162float(h));
}

// ---------------- fp32 -> fp16 hi/lo, and fp32 -> fp16 ----------------------
__global__ __launch_bounds__(256) void convert_hilo_f16(
    const float* __restrict__ in, __half* __restrict__ hi,
    __half* __restrict__ lo, long long total4)
{
    long long i = (long long)blockIdx.x * 256 + threadIdx.x;
    if (i >= total4) return;
    float4 v = ((const float4*)in)[i];
    float vv[4] = {v.x, v.y, v.z, v.w};
    union { unsigned long long u; __half h[4]; } H, L;
#pragma unroll
    for (int j = 0; j < 4; j++) {
        __half h = __float2half_rn(vv[j]);
        H.h[j] = h;
        L.h[j] = __float2half_rn(vv[j] - __half2float(h));
    }
    ((unsigned long long*)hi)[i] = H.u;
    ((unsigned long long*)lo)[i] = L.u;
}
__global__ __launch_bounds__(256) void convert_f16(
    const float* __restrict__ in, __half* __restrict__ out, long long total4)
{
    long long i = (long long)blockIdx.x * 256 + threadIdx.x;
    if (i >= total4) return;
    float4 v = ((const float4*)in)[i];
    float vv[4] = {v.x, v.y, v.z, v.w};
    union { unsigned long long u; __half h[4]; } H;
#pragma unroll
    for (int j = 0; j < 4; j++) H.h[j] = __float2half_rn(vv[j]);
    ((unsigned long long*)out)[i] = H.u;
}

// ---------------- fp16 2-term mma.sync GEMM: C = A * B^T ---------------------
// CTA 128x128, 4 warps (2x2), warp tile 64x64. K = 4096, KC = 32.
#define GK       4096
#define NCHUNK   (GK / 32)               // 128
#define PTILEB   (128 * 64)              // 8192 per part-tile
#define STAGEB   (3 * PTILEB)            // 24576
#define GSTAGES  4
#define GEMM_SMEM (GSTAGES * STAGEB)     // 98304

__global__ __launch_bounds__(128, 2) void gemm_mma(
    const __half* __restrict__ Ah, const __half* __restrict__ Al,
    const __half* __restrict__ Bh, float* __restrict__ C, int N)
{
    extern __shared__ __align__(128) char smraw[];
    const uint32_t sb = (uint32_t)__cvta_generic_to_shared(smraw);

    const int tid = threadIdx.x;
    const int w   = tid >> 5;
    const int l   = tid & 31;
    const int wm  = w & 1;          // 0-1 : 64-row slab
    const int wn  = w >> 1;         // 0-1 : 64-col slab

    const size_t arow_g = (size_t)blockIdx.y * 128 * GK;
    const size_t brow_g = (size_t)blockIdx.x * 128 * GK;
    const char* gp[3] = { (const char*)(Ah + arow_g), (const char*)(Al + arow_g),
                          (const char*)(Bh + brow_g) };

    auto load_chunk = [&](int t, uint32_t st) {
        const size_t gk = (size_t)t * 64;
#pragma unroll
        for (int part = 0; part < 3; part++) {
#pragma unroll
            for (int j = 0; j < 4; j++) {
                int slot = tid + j * 128;      // 512 slots = 128 rows x 4
                int r = slot >> 2, c = slot & 3;
                uint32_t dc = (uint32_t)((c * 16) ^ (((r >> 1) & 3) * 16));
                cp16(st + part * PTILEB + r * 64 + dc,
                     gp[part] + (size_t)r * (GK * 2) + gk + c * 16);
            }
        }
    };

    const int arow = wm * 64 + (l & 15);
    const uint32_t arb  = (uint32_t)(arow * 64);
    const uint32_t axor = (uint32_t)(((arow >> 1) & 3) * 16);
    const int ac0 = (l >> 4);
    const int l2 = l & 7, sel = l >> 3;
    const int brow = wn * 64 + (sel >> 1) * 8 + l2;
    const uint32_t brb  = (uint32_t)(brow * 64);
    const uint32_t bxor = (uint32_t)(((brow >> 1) & 3) * 16);
    const int bc0 = (sel & 1);

    float acc[4][8][4];
#pragma unroll
    for (int mt = 0; mt < 4; mt++)
#pragma unroll
        for (int nt = 0; nt < 8; nt++)
#pragma unroll
            for (int i = 0; i < 4; i++) acc[mt][nt][i] = 0.f;

    load_chunk(0, sb);
    asm volatile("cp.async.commit_group;" ::: "memory");
    load_chunk(1, sb + STAGEB);
    asm volatile("cp.async.commit_group;" ::: "memory");
    load_chunk(2, sb + 2 * STAGEB);
    asm volatile("cp.async.commit_group;" ::: "memory");

    for (int k = 0; k < NCHUNK; k++) {
        if (k + 2 < NCHUNK)
            asm volatile("cp.async.wait_group 2;" ::: "memory");
        else if (k + 1 < NCHUNK)
            asm volatile("cp.async.wait_group 1;" ::: "memory");
        else
            asm volatile("cp.async.wait_group 0;" ::: "memory");
        __syncthreads();

        if (k + 3 < NCHUNK) {
            load_chunk(k + 3, sb + ((k + 3) & 3) * STAGEB);
            asm volatile("cp.async.commit_group;" ::: "memory");
        }

        const uint32_t st = sb + (k & 3) * STAGEB;
#pragma unroll
        for (int ks = 0; ks < 2; ks++) {
            const uint32_t ach = (uint32_t)(((ks * 2 + ac0) * 16)) ^ axor;
            const uint32_t bch = (uint32_t)(((ks * 2 + bc0) * 16)) ^ bxor;

            uint32_t ah[4][4], bh[8][2];
#pragma unroll
            for (int mt = 0; mt < 4; mt++)
                ldm4(ah[mt][0], ah[mt][1], ah[mt][2], ah[mt][3],
                     st + arb + mt * 1024 + ach);
#pragma unroll
            for (int np = 0; np < 4; np++)
                ldm4(bh[2*np][0], bh[2*np][1], bh[2*np+1][0], bh[2*np+1][1],
                     st + 2 * PTILEB + brb + np * 1024 + bch);
#pragma unroll
            for (int mt = 0; mt < 4; mt++)
#pragma unroll
                for (int nt = 0; nt < 8; nt++)
                    mma_f16(acc[mt][nt], ah[mt], bh[nt]);

            uint32_t al[4][4];
#pragma unroll
            for (int mt = 0; mt < 4; mt++)
                ldm4(al[mt][0], al[mt][1], al[mt][2], al[mt][3],
                     st + PTILEB + arb + mt * 1024 + ach);
#pragma unroll
            for (int mt = 0; mt < 4; mt++)
#pragma unroll
                for (int nt = 0; nt < 8; nt++)
                    mma_f16(acc[mt][nt], al[mt], bh[nt]);
        }
    }

    const int crow = blockIdx.y * 128 + wm * 64 + (l >> 2);
    const int ccol = blockIdx.x * 128 + wn * 64 + (l & 3) * 2;
#pragma unroll
    for (int mt = 0; mt < 4; mt++) {
#pragma unroll
        for (int nt = 0; nt < 8; nt++) {
            float* p0 = C + (size_t)(crow + mt * 16)     * N + ccol + nt * 8;
            float* p1 = C + (size_t)(crow + mt * 16 + 8) * N + ccol + nt * 8;
            *(float2*)p0 = make_float2(acc[mt][nt][0], acc[mt][nt][1]);
            *(float2*)p1 = make_float2(acc[mt][nt][2], acc[mt][nt][3]);
        }
    }
}

// ---------------- fused RoPE + scale + cache + attention-operand split ------
__global__ __launch_bounds__(256) void rope_fused(
    const float* __restrict__ xqkv,
    const float* __restrict__ cosf_, const float* __restrict__ sinf_,
    float* __restrict__ kcache, float* __restrict__ vcache,
    __nv_bfloat16* __restrict__ qhi, __nv_bfloat16* __restrict__ qlo,
    __nv_bfloat16* __restrict__ khi, __nv_bfloat16* __restrict__ klo,
    __nv_bfloat16* __restrict__ vhi, __nv_bfloat16* __restrict__ vlo)
{
    const int s   = blockIdx.x;
    const int tid = threadIdx.x;
    const float* row = xqkv + (size_t)s * QKV_N;

    for (int p = tid; p < NH * 64; p += 256) {
        int h = p >> 6, f = p & 63;
        float c  = cosf_[s * 64 + f];
        float sn = sinf_[s * 64 + f];
        float x1 = row[h * HD + 2 * f];
        float x2 = row[h * HD + 2 * f + 1];
        float o1 = (x1 * c - x2 * sn) * SCALE;
        float o2 = (x1 * sn + x2 * c) * SCALE;
        size_t o = ((size_t)h * SEQLEN + s) * HD + 2 * f;
        __nv_bfloat16 h1, l1, h2, l2;
        splitbf(o1, h1, l1); splitbf(o2, h2, l2);
        qhi[o] = h1; qhi[o + 1] = h2;
        qlo[o] = l1; qlo[o + 1] = l2;
    }
    for (int p = tid; p < NKV * 64; p += 256) {
        int h = p >> 6, f = p & 63;
        float c  = cosf_[s * 64 + f];
        float sn = sinf_[s * 64 + f];
        float x1 = row[DIM + h * HD + 2 * f];
        float x2 = row[DIM + h * HD + 2 * f + 1];
        float o1 = x1 * c - x2 * sn;
        float o2 = x1 * sn + x2 * c;
        kcache[(size_t)s * KV_ROW + h * HD + 2 * f]     = o1;
        kcache[(size_t)s * KV_ROW + h * HD + 2 * f + 1] = o2;
        size_t o = ((size_t)h * SEQLEN + s) * HD + 2 * f;
        __nv_bfloat16 h1, l1, h2, l2;
        splitbf(o1, h1, l1); splitbf(o2, h2, l2);
        khi[o] = h1; khi[o + 1] = h2;
        klo[o] = l1; klo[o + 1] = l2;
    }
    for (int i = tid; i < KV_ROW; i += 256) {
        int h = i >> 7, d = i & 127;
        float v = row[DIM + NKV * HD + i];
        vcache[(size_t)s * KV_ROW + i] = v;
        size_t o = ((size_t)h * SEQLEN + s) * HD + d;
        __nv_bfloat16 hv, lv;
        splitbf(v, hv, lv);
        vhi[o] = hv; vlo[o] = lv;
    }
}

// ---------------- tensor-core causal flash attention (double-buffered) ------
#define ASTRIDE 272
#define ATILE   (64 * ASTRIDE)
#define ABUF    (4 * ATILE)
#define ATTN_SMEM (2 * ABUF)

__global__ __launch_bounds__(256, 1) void attn_tc(
    const __nv_bfloat16* __restrict__ Qh, const __nv_bfloat16* __restrict__ Ql,
    const __nv_bfloat16* __restrict__ Kh, const __nv_bfloat16* __restrict__ Kl,
    const __nv_bfloat16* __restrict__ Vh, const __nv_bfloat16* __restrict__ Vl,
    __half* __restrict__ OH, __half* __restrict__ OL)
{
    extern __shared__ __align__(128) char smraw[];
    const uint32_t sb = (uint32_t)__cvta_generic_to_shared(smraw);
    const int tid = threadIdx.x, w = tid >> 5, l = tid & 31;
    const int qt  = (int)gridDim.x - 1 - (int)blockIdx.x;
    const int h   = blockIdx.y;
    const int kvh = h >> 2;

    uint32_t qh_[8][4], ql_[8][4];
    {
        const uint32_t aoff = sb + (uint32_t)((w * 16 + (l & 15)) * ASTRIDE
                                              + (l >> 4) * 16);
        for (int part = 0; part < 2; part++) {
            const __nv_bfloat16* src = part ? Ql : Qh;
            const char* g0 = (const char*)(src + ((size_t)h * SEQLEN + qt * 128) * HD);
            for (int i = tid; i < 2048; i += 256)
                cp16(sb + (uint32_t)((i >> 4) * ASTRIDE + (i & 15) * 16),
                     g0 + (size_t)i * 16);
            asm volatile("cp.async.commit_group;" ::: "memory");
            asm volatile("cp.async.wait_group 0;" ::: "memory");
            __syncthreads();
            uint32_t (*dst)[4] = part ? ql_ : qh_;
#pragma unroll
            for (int g = 0; g < 8; g++)
                ldm4(dst[g][0], dst[g][1], dst[g][2], dst[g][3], aoff + g * 32);
            __syncthreads();
        }
    }

    float o[16][4];
#pragma unroll
    for (int t = 0; t < 16; t++)
#pragma unroll
        for (int i = 0; i < 4; i++) o[t][i] = 0.f;
    float m0 = -1e30f, m1 = -1e30f, l0 = 0.f, l1 = 0.f;

    const int row0 = qt * 128 + w * 16 + (l >> 2);
    const int l2 = l & 7, sel = l >> 3;
    const int nkb = 2 * qt + 2;

    auto load_kv = [&](int kb, uint32_t bufbase) {
        const size_t gbase = (((size_t)kvh * SEQLEN + (size_t)kb * 64) * HD) * 2;
        for (int i = tid; i < 1024; i += 256) {
            uint32_t soff = (uint32_t)((i >> 4) * ASTRIDE + (i & 15) * 16);
            size_t goff = gbase + (size_t)i * 16;
            cp16(bufbase + 0 * ATILE + soff, (const char*)Kh + goff);
            cp16(bufbase + 1 * ATILE + soff, (const char*)Kl + goff);
            cp16(bufbase + 2 * ATILE + soff, (const char*)Vh + goff);
            cp16(bufbase + 3 * ATILE + soff, (const char*)Vl + goff);
        }
        asm volatile("cp.async.commit_group;" ::: "memory");
    };

    int buf = 0;
    load_kv(0, sb);

    for (int kb = 0; kb < nkb; kb++) {
        if (kb + 1 < nkb) {
            load_kv(kb + 1, sb + (buf ^ 1) * ABUF);
            asm volatile("cp.async.wait_group 1;" ::: "memory");
        } else {
            asm volatile("cp.async.wait_group 0;" ::: "memory");
        }
        __syncthreads();
        const uint32_t bbase = sb + buf * ABUF;

        float sc[8][4];
#pragma unroll
        for (int t = 0; t < 8; t++)
#pragma unroll
            for (int i = 0; i < 4; i++) sc[t][i] = 0.f;

#pragma unroll
        for (int g = 0; g < 8; g++) {
#pragma unroll
            for (int n16 = 0; n16 < 4; n16++) {
                uint32_t kaddr = bbase + (uint32_t)((n16 * 16 + (sel >> 1) * 8 + l2)
                                                    * ASTRIDE + (sel & 1) * 16 + g * 32);
                uint32_t bh[2][2], bl[2][2];
                ldm4(bh[0][0], bh[0][1], bh[1][0], bh[1][1], kaddr);
                ldm4(bl[0][0], bl[0][1], bl[1][0], bl[1][1], kaddr + ATILE);
#pragma unroll
                for (int j = 0; j < 2; j++) {
                    int t = n16 * 2 + j;
                    mma_bf16(sc[t], qh_[g], bh[j]);
                    mma_bf16(sc[t], ql_[g], bh[j]);
                    mma_bf16(sc[t], qh_[g], bl[j]);
                }
            }
        }

        if (kb >= 2 * qt) {
#pragma unroll
            for (int t = 0; t < 8; t++) {
                int col = kb * 64 + t * 8 + 2 * (l & 3);
                if (col     > row0)     sc[t][0] = -1e30f;
                if (col + 1 > row0)     sc[t][1] = -1e30f;
                if (col     > row0 + 8) sc[t][2] = -1e30f;
                if (col + 1 > row0 + 8) sc[t][3] = -1e30f;
            }
        }

        float r0m = -1e30f, r1m = -1e30f;
#pragma unroll
        for (int t = 0; t < 8; t++) {
            r0m = fmaxf(r0m, fmaxf(sc[t][0], sc[t][1]));
            r1m = fmaxf(r1m, fmaxf(sc[t][2], sc[t][3]));
        }
        r0m = fmaxf(r0m, __shfl_xor_sync(0xffffffffu, r0m, 1));
        r0m = fmaxf(r0m, __shfl_xor_sync(0xffffffffu, r0m, 2));
        r1m = fmaxf(r1m, __shfl_xor_sync(0xffffffffu, r1m, 1));
        r1m = fmaxf(r1m, __shfl_xor_sync(0xffffffffu, r1m, 2));
        float nm0 = fmaxf(m0, r0m), nm1 = fmaxf(m1, r1m);
        float a0 = __expf(m0 - nm0), a1 = __expf(m1 - nm1);

        float s0 = 0.f, s1 = 0.f;
#pragma unroll
        for (int t = 0; t < 8; t++) {
            sc[t][0] = __expf(sc[t][0] - nm0); s0 += sc[t][0];
            sc[t][1] = __expf(sc[t][1] - nm0); s0 += sc[t][1];
            sc[t][2] = __expf(sc[t][2] - nm1); s1 += sc[t][2];
            sc[t][3] = __expf(sc[t][3] - nm1); s1 += sc[t][3];
        }
        s0 += __shfl_xor_sync(0xffffffffu, s0, 1);
        s0 += __shfl_xor_sync(0xffffffffu, s0, 2);
        s1 += __shfl_xor_sync(0xffffffffu, s1, 1);
        s1 += __shfl_xor_sync(0xffffffffu, s1, 2);
        l0 = l0 * a0 + s0;
        l1 = l1 * a1 + s1;
        m0 = nm0; m1 = nm1;
#pragma unroll
        for (int t = 0; t < 16; t++) {
            o[t][0] *= a0; o[t][1] *= a0;
            o[t][2] *= a1; o[t][3] *= a1;
        }

#pragma unroll
        for (int g = 0; g < 4; g++) {
            uint32_t aph[4], apl[4];
            split2(sc[2*g][0],   sc[2*g][1],   aph[0], apl[0]);
            split2(sc[2*g][2],   sc[2*g][3],   aph[1], apl[1]);
            split2(sc[2*g+1][0], sc[2*g+1][1], aph[2], apl[2]);
            split2(sc[2*g+1][2], sc[2*g+1][3], aph[3], apl[3]);
#pragma unroll
            for (int n16 = 0; n16 < 8; n16++) {
                uint32_t vaddr = bbase + 2 * ATILE
                    + (uint32_t)((g * 16 + (l & 15)) * ASTRIDE
                                 + n16 * 32 + (l >> 4) * 16);
                uint32_t bvh[2][2], bvl[2][2];
                ldm4t(bvh[0][0], bvh[0][1], bvh[1][0], bvh[1][1], vaddr);
                ldm4t(bvl[0][0], bvl[0][1], bvl[1][0], bvl[1][1], vaddr + ATILE);
#pragma unroll
                for (int j = 0; j < 2; j++) {
                    int t = n16 * 2 + j;
                    mma_bf16(o[t], aph, bvh[j]);
                    mma_bf16(o[t], apl, bvh[j]);
                    mma_bf16(o[t], aph, bvl[j]);
                }
            }
        }
        __syncthreads();
        buf ^= 1;
    }

    float i0 = 1.f / l0, i1 = 1.f / l1;
    const int colb = h * HD + 2 * (l & 3);
#pragma unroll
    for (int t = 0; t < 16; t++) {
        {
            float v0 = o[t][0] * i0, v1 = o[t][1] * i0;
            __half h0 = __float2half_rn(v0), h1 = __float2half_rn(v1);
            __half e0 = __float2half_rn(v0 - __half2float(h0));
            __half e1 = __float2half_rn(v1 - __half2float(h1));
            size_t off = (size_t)row0 * DIM + colb + t * 8;
            *(__half2*)(OH + off) = __halves2half2(h0, h1);
            *(__half2*)(OL + off) = __halves2half2(e0, e1);
        }
        {
            float v0 = o[t][2] * i1, v1 = o[t][3] * i1;
            __half h0 = __float2half_rn(v0), h1 = __float2half_rn(v1);
            __half e0 = __float2half_rn(v0 - __half2float(h0));
            __half e1 = __float2half_rn(v1 - __half2float(h1));
            size_t off = (size_t)(row0 + 8) * DIM + colb + t * 8;
            *(__half2*)(OH + off) = __halves2half2(h0, h1);
            *(__half2*)(OL + off) = __halves2half2(e0, e1);
        }
    }
}

// ---------------- launch ----------------------------------------------------
extern "C" void kernel_launch(void* const* d_in, const int* in_sizes, int n_in,
                              void* d_out, int out_size)
{
    const float* x     = (const float*)d_in[0];
    const float* cosf_ = (const float*)d_in[1];
    const float* sinf_ = (const float*)d_in[2];
    const float* in_ck = (const float*)d_in[5];
    const float* in_cv = (const float*)d_in[6];
    const float* Wqkv  = (const float*)d_in[7];
    const float* Wo    = (const float*)d_in[8];

    float* out     = (float*)d_out;
    float* cache_k = out + (size_t)SEQLEN * DIM;
    float* cache_v = cache_k + (size_t)WIN * KV_ROW;

    float* xqkv_p;
    __half *xh_p, *xl_p, *ah_p, *al_p, *wq_p, *wo_p;
    __nv_bfloat16 *qhi_p, *qlo_p, *khi_p, *klo_p, *vhi_p, *vlo_p;
    cudaGetSymbolAddress((void**)&xqkv_p, g_xqkv);
    cudaGetSymbolAddress((void**)&xh_p,   g_xh);
    cudaGetSymbolAddress((void**)&xl_p,   g_xl);
    cudaGetSymbolAddress((void**)&ah_p,   g_ah);
    cudaGetSymbolAddress((void**)&al_p,   g_al);
    cudaGetSymbolAddress((void**)&wq_p,   g_wq);
    cudaGetSymbolAddress((void**)&wo_p,   g_wo);
    cudaGetSymbolAddress((void**)&qhi_p,  g_qhi);
    cudaGetSymbolAddress((void**)&qlo_p,  g_qlo);
    cudaGetSymbolAddress((void**)&khi_p,  g_khi);
    cudaGetSymbolAddress((void**)&klo_p,  g_klo);
    cudaGetSymbolAddress((void**)&vhi_p,  g_vhi);
    cudaGetSymbolAddress((void**)&vlo_p,  g_vlo);

    size_t cache_bytes = (size_t)WIN * KV_ROW * sizeof(float);
    cudaMemcpyAsync(cache_k, in_ck, cache_bytes, cudaMemcpyDeviceToDevice, 0);
    cudaMemcpyAsync(cache_v, in_cv, cache_bytes, cudaMemcpyDeviceToDevice, 0);

    cudaFuncSetAttribute(gemm_mma, cudaFuncAttributeMaxDynamicSharedMemorySize,
                         GEMM_SMEM);
    cudaFuncSetAttribute(attn_tc, cudaFuncAttributeMaxDynamicSharedMemorySize,
                         ATTN_SMEM);

    {
        long long t4;
        t4 = (long long)SEQLEN * DIM / 4;
        convert_hilo_f16<<<(unsigned)((t4 + 255) / 256), 256>>>(x, xh_p, xl_p, t4);
        t4 = (long long)QKV_N * DIM / 4;
        convert_f16<<<(unsigned)((t4 + 255) / 256), 256>>>(Wqkv, wq_p, t4);
        t4 = (long long)DIM * DIM / 4;
        convert_f16<<<(unsigned)((t4 + 255) / 256), 256>>>(Wo, wo_p, t4);
    }

    // 1) QKV projection (fp16 2-term, 4-warp CTA)
    gemm_mma<<<dim3(QKV_N / 128, SEQLEN / 128), 128, GEMM_SMEM>>>(
        xh_p, xl_p, wq_p, xqkv_p, QKV_N);

    // 2) fused RoPE + caches + attention-operand splits
    rope_fused<<<SEQLEN, 256>>>(xqkv_p, cosf_, sinf_, cache_k, cache_v,
                                qhi_p, qlo_p, khi_p, klo_p, vhi_p, vlo_p);

    // 3) tensor-core causal flash attention, fp16 hi/lo epilogue
    attn_tc<<<dim3(SEQLEN / 128, NH), 256, ATTN_SMEM>>>(
        qhi_p, qlo_p, khi_p, klo_p, vhi_p, vlo_p, ah_p, al_p);

    // 4) output projection (fp16 2-term, 4-warp CTA)
    gemm_mma<<<dim3(DIM / 128, SEQLEN / 128), 128, GEMM_SMEM>>>(
        ah_p, al_p, wo_p, out, DIM);
}

// round 11
// speedup vs baseline: 2.0190x; 1.0696x over previous
#include <cuda_runtime.h>
#include <cuda_bf16.h>
#include <cuda_fp16.h>
#include <cstdint>
#include <math.h>

#define SEQLEN 2048
#define DIM    4096
#define NH     32
#define HD     128
#define NKV    8
#define QKV_N  6144
#define KV_ROW 1024
#define WIN    4096
#define SCALE  0.08838834764831845f

// ---------------- scratch (device globals) ----------------------------------
__device__ float g_xqkv[SEQLEN * QKV_N];
__device__ __half g_xh [(size_t)SEQLEN * DIM];
__device__ __half g_xl [(size_t)SEQLEN * DIM];
__device__ __half g_ah [(size_t)SEQLEN * DIM];
__device__ __half g_al [(size_t)SEQLEN * DIM];
__device__ __half g_wq [(size_t)QKV_N * DIM];
__device__ __half g_wo [(size_t)DIM * DIM];
__device__ __nv_bfloat16 g_qhi[(size_t)NH  * SEQLEN * HD];
__device__ __nv_bfloat16 g_qlo[(size_t)NH  * SEQLEN * HD];
__device__ __nv_bfloat16 g_khi[(size_t)NKV * SEQLEN * HD];
__device__ __nv_bfloat16 g_klo[(size_t)NKV * SEQLEN * HD];
__device__ __nv_bfloat16 g_vhi[(size_t)NKV * SEQLEN * HD];
__device__ __nv_bfloat16 g_vlo[(size_t)NKV * SEQLEN * HD];

// ---------------- common PTX helpers ----------------------------------------
__device__ __forceinline__ void cp16(uint32_t d, const void* g) {
    asm volatile("cp.async.cg.shared.global [%0], [%1], 16;\n"
                 :: "r"(d), "l"(__cvta_generic_to_global(g)) : "memory");
}
__device__ __forceinline__ void ldm4(uint32_t& r0, uint32_t& r1,
                                     uint32_t& r2, uint32_t& r3, uint32_t a) {
    asm volatile("ldmatrix.sync.aligned.m8n8.x4.shared.b16 {%0,%1,%2,%3}, [%4];"
                 : "=r"(r0), "=r"(r1), "=r"(r2), "=r"(r3) : "r"(a));
}
__device__ __forceinline__ void ldm4t(uint32_t& r0, uint32_t& r1,
                                      uint32_t& r2, uint32_t& r3, uint32_t a) {
    asm volatile("ldmatrix.sync.aligned.m8n8.x4.trans.shared.b16 {%0,%1,%2,%3}, [%4];"
                 : "=r"(r0), "=r"(r1), "=r"(r2), "=r"(r3) : "r"(a));
}
__device__ __forceinline__ void mma_bf16(float* c, const uint32_t* a,
                                         const uint32_t* b) {
    asm volatile(
        "mma.sync.aligned.m16n8k16.row.col.f32.bf16.bf16.f32 "
        "{%0,%1,%2,%3}, {%4,%5,%6,%7}, {%8,%9}, {%0,%1,%2,%3};"
        : "+f"(c[0]), "+f"(c[1]), "+f"(c[2]), "+f"(c[3])
        : "r"(a[0]), "r"(a[1]), "r"(a[2]), "r"(a[3]), "r"(b[0]), "r"(b[1]));
}
__device__ __forceinline__ void mma_f16(float* c, const uint32_t* a,
                                        const uint32_t* b) {
    asm volatile(
        "mma.sync.aligned.m16n8k16.row.col.f32.f16.f16.f32 "
        "{%0,%1,%2,%3}, {%4,%5,%6,%7}, {%8,%9}, {%0,%1,%2,%3};"
        : "+f"(c[0]), "+f"(c[1]), "+f"(c[2]), "+f"(c[3])
        : "r"(a[0]), "r"(a[1]), "r"(a[2]), "r"(a[3]), "r"(b[0]), "r"(b[1]));
}
__device__ __forceinline__ void split2(float x, float y, uint32_t& hi, uint32_t& lo) {
    __nv_bfloat162 h = __floats2bfloat162_rn(x, y);
    float rx = x - __bfloat162float(h.x);
    float ry = y - __bfloat162float(h.y);
    __nv_bfloat162 r = __floats2bfloat162_rn(rx, ry);
    hi = *(uint32_t*)&h; lo = *(uint32_t*)&r;
}
__device__ __forceinline__ void splitbf(float v, __nv_bfloat16& h, __nv_bfloat16& l) {
    h = __float2bfloat16(v);
    l = __float2bfloat16(v - __bfloat162float(h));
}

// ---------------- fp32 -> fp16 hi/lo, and fp32 -> fp16 ----------------------
__global__ __launch_bounds__(256) void convert_hilo_f16(
    const float* __restrict__ in, __half* __restrict__ hi,
    __half* __restrict__ lo, long long total4)
{
    long long i = (long long)blockIdx.x * 256 + threadIdx.x;
    if (i >= total4) return;
    float4 v = ((const float4*)in)[i];
    float vv[4] = {v.x, v.y, v.z, v.w};
    union { unsigned long long u; __half h[4]; } H, L;
#pragma unroll
    for (int j = 0; j < 4; j++) {
        __half h = __float2half_rn(vv[j]);
        H.h[j] = h;
        L.h[j] = __float2half_rn(vv[j] - __half2float(h));
    }
    ((unsigned long long*)hi)[i] = H.u;
    ((unsigned long long*)lo)[i] = L.u;
}
__global__ __launch_bounds__(256) void convert_f16(
    const float* __restrict__ in, __half* __restrict__ out, long long total4)
{
    long long i = (long long)blockIdx.x * 256 + threadIdx.x;
    if (i >= total4) return;
    float4 v = ((const float4*)in)[i];
    float vv[4] = {v.x, v.y, v.z, v.w};
    union { unsigned long long u; __half h[4]; } H;
#pragma unroll
    for (int j = 0; j < 4; j++) H.h[j] = __float2half_rn(vv[j]);
    ((unsigned long long*)out)[i] = H.u;
}

// ---------------- fp16 2-term mma.sync GEMM: C = A * B^T ---------------------
// CTA 128x128, 4 warps (2x2), warp tile 64x64. K = 4096, KC = 64.
// smem: 128B rows, XOR swizzle (chunk ^= row&7), 2 stages, 1 barrier/chunk.
#define GK       4096
#define NCHUNK   (GK / 64)               // 64
#define PTILEB   (128 * 128)             // 16384 per part-tile
#define STAGEB   (3 * PTILEB)            // 49152
#define GEMM_SMEM (2 * STAGEB)           // 98304

__global__ __launch_bounds__(128, 2) void gemm_mma(
    const __half* __restrict__ Ah, const __half* __restrict__ Al,
    const __half* __restrict__ Bh, float* __restrict__ C, int N)
{
    extern __shared__ __align__(128) char smraw[];
    const uint32_t sb = (uint32_t)__cvta_generic_to_shared(smraw);

    const int tid = threadIdx.x;
    const int w   = tid >> 5;
    const int l   = tid & 31;
    const int wm  = w & 1;          // 0-1 : 64-row slab
    const int wn  = w >> 1;         // 0-1 : 64-col slab

    const size_t arow_g = (size_t)blockIdx.y * 128 * GK;
    const size_t brow_g = (size_t)blockIdx.x * 128 * GK;
    const char* gp[3] = { (const char*)(Ah + arow_g), (const char*)(Al + arow_g),
                          (const char*)(Bh + brow_g) };

    // each part: 128 rows x 8 chunks(16B) = 1024 slots; 128 thr x 8 iters
    auto load_chunk = [&](int t, uint32_t st) {
        const size_t gk = (size_t)t * 128;   // byte offset along K
#pragma unroll
        for (int part = 0; part < 3; part++) {
#pragma unroll
            for (int j = 0; j < 8; j++) {
                int slot = tid + j * 128;
                int r = slot >> 3, c = slot & 7;
                uint32_t dc = (uint32_t)((c ^ (r & 7)) * 16);
                cp16(st + part * PTILEB + r * 128 + dc,
                     gp[part] + (size_t)r * (GK * 2) + gk + c * 16);
            }
        }
    };

    const int arow = wm * 64 + (l & 15);
    const uint32_t arb  = (uint32_t)(arow * 128);
    const int axor = arow & 7;
    const int ac0 = (l >> 4);
    const int l2 = l & 7, sel = l >> 3;
    const int brow = wn * 64 + (sel >> 1) * 8 + l2;
    const uint32_t brb  = (uint32_t)(brow * 128);
    const int bxor = brow & 7;
    const int bc0 = (sel & 1);

    float acc[4][8][4];
#pragma unroll
    for (int mt = 0; mt < 4; mt++)
#pragma unroll
        for (int nt = 0; nt < 8; nt++)
#pragma unroll
            for (int i = 0; i < 4; i++) acc[mt][nt][i] = 0.f;

    load_chunk(0, sb);
    asm volatile("cp.async.commit_group;" ::: "memory");

    for (int k = 0; k < NCHUNK; k++) {
        asm volatile("cp.async.wait_group 0;" ::: "memory");
        __syncthreads();
        if (k + 1 < NCHUNK) {
            load_chunk(k + 1, sb + ((k + 1) & 1) * STAGEB);
            asm volatile("cp.async.commit_group;" ::: "memory");
        }

        const uint32_t st = sb + (k & 1) * STAGEB;
#pragma unroll
        for (int ks = 0; ks < 4; ks++) {
            const uint32_t ach = (uint32_t)(((ks * 2 + ac0) ^ axor) * 16);
            const uint32_t bch = (uint32_t)(((ks * 2 + bc0) ^ bxor) * 16);

            uint32_t ah[4][4], bh[8][2];
#pragma unroll
            for (int mt = 0; mt < 4; mt++)
                ldm4(ah[mt][0], ah[mt][1], ah[mt][2], ah[mt][3],
                     st + arb + mt * 2048 + ach);
#pragma unroll
            for (int np = 0; np < 4; np++)
                ldm4(bh[2*np][0], bh[2*np][1], bh[2*np+1][0], bh[2*np+1][1],
                     st + 2 * PTILEB + brb + np * 2048 + bch);
#pragma unroll
            for (int mt = 0; mt < 4; mt++)
#pragma unroll
                for (int nt = 0; nt < 8; nt++)
                    mma_f16(acc[mt][nt], ah[mt], bh[nt]);

            uint32_t al[4][4];
#pragma unroll
            for (int mt = 0; mt < 4; mt++)
                ldm4(al[mt][0], al[mt][1], al[mt][2], al[mt][3],
                     st + PTILEB + arb + mt * 2048 + ach);
#pragma unroll
            for (int mt = 0; mt < 4; mt++)
#pragma unroll
                for (int nt = 0; nt < 8; nt++)
                    mma_f16(acc[mt][nt], al[mt], bh[nt]);
        }
    }

    const int crow = blockIdx.y * 128 + wm * 64 + (l >> 2);
    const int ccol = blockIdx.x * 128 + wn * 64 + (l & 3) * 2;
#pragma unroll
    for (int mt = 0; mt < 4; mt++) {
#pragma unroll
        for (int nt = 0; nt < 8; nt++) {
            float* p0 = C + (size_t)(crow + mt * 16)     * N + ccol + nt * 8;
            float* p1 = C + (size_t)(crow + mt * 16 + 8) * N + ccol + nt * 8;
            *(float2*)p0 = make_float2(acc[mt][nt][0], acc[mt][nt][1]);
            *(float2*)p1 = make_float2(acc[mt][nt][2], acc[mt][nt][3]);
        }
    }
}

// ---------------- fused RoPE + scale + cache + attention-operand split ------
__global__ __launch_bounds__(256) void rope_fused(
    const float* __restrict__ xqkv,
    const float* __restrict__ cosf_, const float* __restrict__ sinf_,
    float* __restrict__ kcache, float* __restrict__ vcache,
    __nv_bfloat16* __restrict__ qhi, __nv_bfloat16* __restrict__ qlo,
    __nv_bfloat16* __restrict__ khi, __nv_bfloat16* __restrict__ klo,
    __nv_bfloat16* __restrict__ vhi, __nv_bfloat16* __restrict__ vlo)
{
    const int s   = blockIdx.x;
    const int tid = threadIdx.x;
    const float* row = xqkv + (size_t)s * QKV_N;

    for (int p = tid; p < NH * 64; p += 256) {
        int h = p >> 6, f = p & 63;
        float c  = cosf_[s * 64 + f];
        float sn = sinf_[s * 64 + f];
        float x1 = row[h * HD + 2 * f];
        float x2 = row[h * HD + 2 * f + 1];
        float o1 = (x1 * c - x2 * sn) * SCALE;
        float o2 = (x1 * sn + x2 * c) * SCALE;
        size_t o = ((size_t)h * SEQLEN + s) * HD + 2 * f;
        __nv_bfloat16 h1, l1, h2, l2;
        splitbf(o1, h1, l1); splitbf(o2, h2, l2);
        qhi[o] = h1; qhi[o + 1] = h2;
        qlo[o] = l1; qlo[o + 1] = l2;
    }
    for (int p = tid; p < NKV * 64; p += 256) {
        int h = p >> 6, f = p & 63;
        float c  = cosf_[s * 64 + f];
        float sn = sinf_[s * 64 + f];
        float x1 = row[DIM + h * HD + 2 * f];
        float x2 = row[DIM + h * HD + 2 * f + 1];
        float o1 = x1 * c - x2 * sn;
        float o2 = x1 * sn + x2 * c;
        kcache[(size_t)s * KV_ROW + h * HD + 2 * f]     = o1;
        kcache[(size_t)s * KV_ROW + h * HD + 2 * f + 1] = o2;
        size_t o = ((size_t)h * SEQLEN + s) * HD + 2 * f;
        __nv_bfloat16 h1, l1, h2, l2;
        splitbf(o1, h1, l1); splitbf(o2, h2, l2);
        khi[o] = h1; khi[o + 1] = h2;
        klo[o] = l1; klo[o + 1] = l2;
    }
    for (int i = tid; i < KV_ROW; i += 256) {
        int h = i >> 7, d = i & 127;
        float v = row[DIM + NKV * HD + i];
        vcache[(size_t)s * KV_ROW + i] = v;
        size_t o = ((size_t)h * SEQLEN + s) * HD + d;
        __nv_bfloat16 hv, lv;
        splitbf(v, hv, lv);
        vhi[o] = hv; vlo[o] = lv;
    }
}

// ---------------- tensor-core causal flash attention (double-buffered) ------
#define ASTRIDE 272
#define ATILE   (64 * ASTRIDE)
#define ABUF    (4 * ATILE)
#define ATTN_SMEM (2 * ABUF)

__global__ __launch_bounds__(256, 1) void attn_tc(
    const __nv_bfloat16* __restrict__ Qh, const __nv_bfloat16* __restrict__ Ql,
    const __nv_bfloat16* __restrict__ Kh, const __nv_bfloat16* __restrict__ Kl,
    const __nv_bfloat16* __restrict__ Vh, const __nv_bfloat16* __restrict__ Vl,
    __half* __restrict__ OH, __half* __restrict__ OL)
{
    extern __shared__ __align__(128) char smraw[];
    const uint32_t sb = (uint32_t)__cvta_generic_to_shared(smraw);
    const int tid = threadIdx.x, w = tid >> 5, l = tid & 31;
    const int qt  = (int)gridDim.x - 1 - (int)blockIdx.x;
    const int h   = blockIdx.y;
    const int kvh = h >> 2;

    uint32_t qh_[8][4], ql_[8][4];
    {
        const uint32_t aoff = sb + (uint32_t)((w * 16 + (l & 15)) * ASTRIDE
                                              + (l >> 4) * 16);
        for (int part = 0; part < 2; part++) {
            const __nv_bfloat16* src = part ? Ql : Qh;
            const char* g0 = (const char*)(src + ((size_t)h * SEQLEN + qt * 128) * HD);
            for (int i = tid; i < 2048; i += 256)
                cp16(sb + (uint32_t)((i >> 4) * ASTRIDE + (i & 15) * 16),
                     g0 + (size_t)i * 16);
            asm volatile("cp.async.commit_group;" ::: "memory");
            asm volatile("cp.async.wait_group 0;" ::: "memory");
            __syncthreads();
            uint32_t (*dst)[4] = part ? ql_ : qh_;
#pragma unroll
            for (int g = 0; g < 8; g++)
                ldm4(dst[g][0], dst[g][1], dst[g][2], dst[g][3], aoff + g * 32);
            __syncthreads();
        }
    }

    float o[16][4];
#pragma unroll
    for (int t = 0; t < 16; t++)
#pragma unroll
        for (int i = 0; i < 4; i++) o[t][i] = 0.f;
    float m0 = -1e30f, m1 = -1e30f, l0 = 0.f, l1 = 0.f;

    const int row0 = qt * 128 + w * 16 + (l >> 2);
    const int l2 = l & 7, sel = l >> 3;
    const int nkb = 2 * qt + 2;

    auto load_kv = [&](int kb, uint32_t bufbase) {
        const size_t gbase = (((size_t)kvh * SEQLEN + (size_t)kb * 64) * HD) * 2;
        for (int i = tid; i < 1024; i += 256) {
            uint32_t soff = (uint32_t)((i >> 4) * ASTRIDE + (i & 15) * 16);
            size_t goff = gbase + (size_t)i * 16;
            cp16(bufbase + 0 * ATILE + soff, (const char*)Kh + goff);
            cp16(bufbase + 1 * ATILE + soff, (const char*)Kl + goff);
            cp16(bufbase + 2 * ATILE + soff, (const char*)Vh + goff);
            cp16(bufbase + 3 * ATILE + soff, (const char*)Vl + goff);
        }
        asm volatile("cp.async.commit_group;" ::: "memory");
    };

    int buf = 0;
    load_kv(0, sb);

    for (int kb = 0; kb < nkb; kb++) {
        if (kb + 1 < nkb) {
            load_kv(kb + 1, sb + (buf ^ 1) * ABUF);
            asm volatile("cp.async.wait_group 1;" ::: "memory");
        } else {
            asm volatile("cp.async.wait_group 0;" ::: "memory");
        }
        __syncthreads();
        const uint32_t bbase = sb + buf * ABUF;

        float sc[8][4];
#pragma unroll
        for (int t = 0; t < 8; t++)
#pragma unroll
            for (int i = 0; i < 4; i++) sc[t][i] = 0.f;

#pragma unroll
        for (int g = 0; g < 8; g++) {
#pragma unroll
            for (int n16 = 0; n16 < 4; n16++) {
                uint32_t kaddr = bbase + (uint32_t)((n16 * 16 + (sel >> 1) * 8 + l2)
                                                    * ASTRIDE + (sel & 1) * 16 + g * 32);
                uint32_t bh[2][2], bl[2][2];
                ldm4(bh[0][0], bh[0][1], bh[1][0], bh[1][1], kaddr);
                ldm4(bl[0][0], bl[0][1], bl[1][0], bl[1][1], kaddr + ATILE);
#pragma unroll
                for (int j = 0; j < 2; j++) {
                    int t = n16 * 2 + j;
                    mma_bf16(sc[t], qh_[g], bh[j]);
                    mma_bf16(sc[t], ql_[g], bh[j]);
                    mma_bf16(sc[t], qh_[g], bl[j]);
                }
            }
        }

        if (kb >= 2 * qt) {
#pragma unroll
            for (int t = 0; t < 8; t++) {
                int col = kb * 64 + t * 8 + 2 * (l & 3);
                if (col     > row0)     sc[t][0] = -1e30f;
                if (col + 1 > row0)     sc[t][1] = -1e30f;
                if (col     > row0 + 8) sc[t][2] = -1e30f;
                if (col + 1 > row0 + 8) sc[t][3] = -1e30f;
            }
        }

        float r0m = -1e30f, r1m = -1e30f;
#pragma unroll
        for (int t = 0; t < 8; t++) {
            r0m = fmaxf(r0m, fmaxf(sc[t][0], sc[t][1]));
            r1m = fmaxf(r1m, fmaxf(sc[t][2], sc[t][3]));
        }
        r0m = fmaxf(r0m, __shfl_xor_sync(0xffffffffu, r0m, 1));
        r0m = fmaxf(r0m, __shfl_xor_sync(0xffffffffu, r0m, 2));
        r1m = fmaxf(r1m, __shfl_xor_sync(0xffffffffu, r1m, 1));
        r1m = fmaxf(r1m, __shfl_xor_sync(0xffffffffu, r1m, 2));
        float nm0 = fmaxf(m0, r0m), nm1 = fmaxf(m1, r1m);
        float a0 = __expf(m0 - nm0), a1 = __expf(m1 - nm1);

        float s0 = 0.f, s1 = 0.f;
#pragma unroll
        for (int t = 0; t < 8; t++) {
            sc[t][0] = __expf(sc[t][0] - nm0); s0 += sc[t][0];
            sc[t][1] = __expf(sc[t][1] - nm0); s0 += sc[t][1];
            sc[t][2] = __expf(sc[t][2] - nm1); s1 += sc[t][2];
            sc[t][3] = __expf(sc[t][3] - nm1); s1 += sc[t][3];
        }
        s0 += __shfl_xor_sync(0xffffffffu, s0, 1);
        s0 += __shfl_xor_sync(0xffffffffu, s0, 2);
        s1 += __shfl_xor_sync(0xffffffffu, s1, 1);
        s1 += __shfl_xor_sync(0xffffffffu, s1, 2);
        l0 = l0 * a0 + s0;
        l1 = l1 * a1 + s1;
        m0 = nm0; m1 = nm1;
#pragma unroll
        for (int t = 0; t < 16; t++) {
            o[t][0] *= a0; o[t][1] *= a0;
            o[t][2] *= a1; o[t][3] *= a1;
        }

#pragma unroll
        for (int g = 0; g < 4; g++) {
            uint32_t aph[4], apl[4];
            split2(sc[2*g][0],   sc[2*g][1],   aph[0], apl[0]);
            split2(sc[2*g][2],   sc[2*g][3],   aph[1], apl[1]);
            split2(sc[2*g+1][0], sc[2*g+1][1], aph[2], apl[2]);
            split2(sc[2*g+1][2], sc[2*g+1][3], aph[3], apl[3]);
#pragma unroll
            for (int n16 = 0; n16 < 8; n16++) {
                uint32_t vaddr = bbase + 2 * ATILE
                    + (uint32_t)((g * 16 + (l & 15)) * ASTRIDE
                                 + n16 * 32 + (l >> 4) * 16);
                uint32_t bvh[2][2], bvl[2][2];
                ldm4t(bvh[0][0], bvh[0][1], bvh[1][0], bvh[1][1], vaddr);
                ldm4t(bvl[0][0], bvl[0][1], bvl[1][0], bvl[1][1], vaddr + ATILE);
#pragma unroll
                for (int j = 0; j < 2; j++) {
                    int t = n16 * 2 + j;
                    mma_bf16(o[t], aph, bvh[j]);
                    mma_bf16(o[t], apl, bvh[j]);
                    mma_bf16(o[t], aph, bvl[j]);
                }
            }
        }
        __syncthreads();
        buf ^= 1;
    }

    float i0 = 1.f / l0, i1 = 1.f / l1;
    const int colb = h * HD + 2 * (l & 3);
#pragma unroll
    for (int t = 0; t < 16; t++) {
        {
            float v0 = o[t][0] * i0, v1 = o[t][1] * i0;
            __half h0 = __float2half_rn(v0), h1 = __float2half_rn(v1);
            __half e0 = __float2half_rn(v0 - __half2float(h0));
            __half e1 = __float2half_rn(v1 - __half2float(h1));
            size_t off = (size_t)row0 * DIM + colb + t * 8;
            *(__half2*)(OH + off) = __halves2half2(h0, h1);
            *(__half2*)(OL + off) = __halves2half2(e0, e1);
        }
        {
            float v0 = o[t][2] * i1, v1 = o[t][3] * i1;
            __half h0 = __float2half_rn(v0), h1 = __float2half_rn(v1);
            __half e0 = __float2half_rn(v0 - __half2float(h0));
            __half e1 = __float2half_rn(v1 - __half2float(h1));
            size_t off = (size_t)(row0 + 8) * DIM + colb + t * 8;
            *(__half2*)(OH + off) = __halves2half2(h0, h1);
            *(__half2*)(OL + off) = __halves2half2(e0, e1);
        }
    }
}

// ---------------- launch ----------------------------------------------------
extern "C" void kernel_launch(void* const* d_in, const int* in_sizes, int n_in,
                              void* d_out, int out_size)
{
    const float* x     = (const float*)d_in[0];
    const float* cosf_ = (const float*)d_in[1];
    const float* sinf_ = (const float*)d_in[2];
    const float* in_ck = (const float*)d_in[5];
    const float* in_cv = (const float*)d_in[6];
    const float* Wqkv  = (const float*)d_in[7];
    const float* Wo    = (const float*)d_in[8];

    float* out     = (float*)d_out;
    float* cache_k = out + (size_t)SEQLEN * DIM;
    float* cache_v = cache_k + (size_t)WIN * KV_ROW;

    float* xqkv_p;
    __half *xh_p, *xl_p, *ah_p, *al_p, *wq_p, *wo_p;
    __nv_bfloat16 *qhi_p, *qlo_p, *khi_p, *klo_p, *vhi_p, *vlo_p;
    cudaGetSymbolAddress((void**)&xqkv_p, g_xqkv);
    cudaGetSymbolAddress((void**)&xh_p,   g_xh);
    cudaGetSymbolAddress((void**)&xl_p,   g_xl);
    cudaGetSymbolAddress((void**)&ah_p,   g_ah);
    cudaGetSymbolAddress((void**)&al_p,   g_al);
    cudaGetSymbolAddress((void**)&wq_p,   g_wq);
    cudaGetSymbolAddress((void**)&wo_p,   g_wo);
    cudaGetSymbolAddress((void**)&qhi_p,  g_qhi);
    cudaGetSymbolAddress((void**)&qlo_p,  g_qlo);
    cudaGetSymbolAddress((void**)&khi_p,  g_khi);
    cudaGetSymbolAddress((void**)&klo_p,  g_klo);
    cudaGetSymbolAddress((void**)&vhi_p,  g_vhi);
    cudaGetSymbolAddress((void**)&vlo_p,  g_vlo);

    // rope writes cache rows [0, SEQLEN); only rows [SEQLEN, WIN) need copying
    size_t half_elems = (size_t)SEQLEN * KV_ROW;
    size_t half_bytes = half_elems * sizeof(float);
    cudaMemcpyAsync(cache_k + half_elems, in_ck + half_elems, half_bytes,
                    cudaMemcpyDeviceToDevice, 0);
    cudaMemcpyAsync(cache_v + half_elems, in_cv + half_elems, half_bytes,
                    cudaMemcpyDeviceToDevice, 0);

    cudaFuncSetAttribute(gemm_mma, cudaFuncAttributeMaxDynamicSharedMemorySize,
                         GEMM_SMEM);
    cudaFuncSetAttribute(attn_tc, cudaFuncAttributeMaxDynamicSharedMemorySize,
                         ATTN_SMEM);

    {
        long long t4;
        t4 = (long long)SEQLEN * DIM / 4;
        convert_hilo_f16<<<(unsigned)((t4 + 255) / 256), 256>>>(x, xh_p, xl_p, t4);
        t4 = (long long)QKV_N * DIM / 4;
        convert_f16<<<(unsigned)((t4 + 255) / 256), 256>>>(Wqkv, wq_p, t4);
        t4 = (long long)DIM * DIM / 4;
        convert_f16<<<(unsigned)((t4 + 255) / 256), 256>>>(Wo, wo_p, t4);
    }

    // 1) QKV projection (fp16 2-term, KC=64 2-stage)
    gemm_mma<<<dim3(QKV_N / 128, SEQLEN / 128), 128, GEMM_SMEM>>>(
        xh_p, xl_p, wq_p, xqkv_p, QKV_N);

    // 2) fused RoPE + caches + attention-operand splits
    rope_fused<<<SEQLEN, 256>>>(xqkv_p, cosf_, sinf_, cache_k, cache_v,
                                qhi_p, qlo_p, khi_p, klo_p, vhi_p, vlo_p);

    // 3) tensor-core causal flash attention, fp16 hi/lo epilogue
    attn_tc<<<dim3(SEQLEN / 128, NH), 256, ATTN_SMEM>>>(
        qhi_p, qlo_p, khi_p, klo_p, vhi_p, vlo_p, ah_p, al_p);

    // 4) output projection (fp16 2-term, KC=64 2-stage)
    gemm_mma<<<dim3(DIM / 128, SEQLEN / 128), 128, GEMM_SMEM>>>(
        ah_p, al_p, wo_p, out, DIM);
}

// round 12
// speedup vs baseline: 2.0462x; 1.0135x over previous
#include <cuda_runtime.h>
#include <cuda_bf16.h>
#include <cuda_fp16.h>
#include <cstdint>
#include <math.h>

#define SEQLEN 2048
#define DIM    4096
#define NH     32
#define HD     128
#define NKV    8
#define QKV_N  6144
#define KV_ROW 1024
#define WIN    4096
#define SCALE  0.08838834764831845f

// ---------------- scratch (device globals) ----------------------------------
__device__ __half g_xh [(size_t)SEQLEN * DIM];
__device__ __half g_xl [(size_t)SEQLEN * DIM];
__device__ __half g_ah [(size_t)SEQLEN * DIM];
__device__ __half g_al [(size_t)SEQLEN * DIM];
__device__ __half g_wq [(size_t)QKV_N * DIM];
__device__ __half g_wo [(size_t)DIM * DIM];
__device__ __nv_bfloat16 g_qhi[(size_t)NH  * SEQLEN * HD];
__device__ __nv_bfloat16 g_qlo[(size_t)NH  * SEQLEN * HD];
__device__ __nv_bfloat16 g_khi[(size_t)NKV * SEQLEN * HD];
__device__ __nv_bfloat16 g_klo[(size_t)NKV * SEQLEN * HD];
__device__ __nv_bfloat16 g_vhi[(size_t)NKV * SEQLEN * HD];
__device__ __nv_bfloat16 g_vlo[(size_t)NKV * SEQLEN * HD];

// ---------------- common PTX helpers ----------------------------------------
__device__ __forceinline__ void cp16(uint32_t d, const void* g) {
    asm volatile("cp.async.cg.shared.global [%0], [%1], 16;\n"
                 :: "r"(d), "l"(__cvta_generic_to_global(g)) : "memory");
}
__device__ __forceinline__ void ldm4(uint32_t& r0, uint32_t& r1,
                                     uint32_t& r2, uint32_t& r3, uint32_t a) {
    asm volatile("ldmatrix.sync.aligned.m8n8.x4.shared.b16 {%0,%1,%2,%3}, [%4];"
                 : "=r"(r0), "=r"(r1), "=r"(r2), "=r"(r3) : "r"(a));
}
__device__ __forceinline__ void ldm4t(uint32_t& r0, uint32_t& r1,
                                      uint32_t& r2, uint32_t& r3, uint32_t a) {
    asm volatile("ldmatrix.sync.aligned.m8n8.x4.trans.shared.b16 {%0,%1,%2,%3}, [%4];"
                 : "=r"(r0), "=r"(r1), "=r"(r2), "=r"(r3) : "r"(a));
}
__device__ __forceinline__ void mma_bf16(float* c, const uint32_t* a,
                                         const uint32_t* b) {
    asm volatile(
        "mma.sync.aligned.m16n8k16.row.col.f32.bf16.bf16.f32 "
        "{%0,%1,%2,%3}, {%4,%5,%6,%7}, {%8,%9}, {%0,%1,%2,%3};"
        : "+f"(c[0]), "+f"(c[1]), "+f"(c[2]), "+f"(c[3])
        : "r"(a[0]), "r"(a[1]), "r"(a[2]), "r"(a[3]), "r"(b[0]), "r"(b[1]));
}
__device__ __forceinline__ void mma_f16(float* c, const uint32_t* a,
                                        const uint32_t* b) {
    asm volatile(
        "mma.sync.aligned.m16n8k16.row.col.f32.f16.f16.f32 "
        "{%0,%1,%2,%3}, {%4,%5,%6,%7}, {%8,%9}, {%0,%1,%2,%3};"
        : "+f"(c[0]), "+f"(c[1]), "+f"(c[2]), "+f"(c[3])
        : "r"(a[0]), "r"(a[1]), "r"(a[2]), "r"(a[3]), "r"(b[0]), "r"(b[1]));
}
__device__ __forceinline__ void split2(float x, float y, uint32_t& hi, uint32_t& lo) {
    __nv_bfloat162 h = __floats2bfloat162_rn(x, y);
    float rx = x - __bfloat162float(h.x);
    float ry = y - __bfloat162float(h.y);
    __nv_bfloat162 r = __floats2bfloat162_rn(rx, ry);
    hi = *(uint32_t*)&h; lo = *(uint32_t*)&r;
}
__device__ __forceinline__ void split2bf(float x, float y,
                                         __nv_bfloat162& h2, __nv_bfloat162& l2) {
    h2 = __floats2bfloat162_rn(x, y);
    float rx = x - __bfloat162float(h2.x);
    float ry = y - __bfloat162float(h2.y);
    l2 = __floats2bfloat162_rn(rx, ry);
}

// ---------------- fp32 -> fp16 hi/lo, and fp32 -> fp16 ----------------------
__global__ __launch_bounds__(256) void convert_hilo_f16(
    const float* __restrict__ in, __half* __restrict__ hi,
    __half* __restrict__ lo, long long total4)
{
    long long i = (long long)blockIdx.x * 256 + threadIdx.x;
    if (i >= total4) return;
    float4 v = ((const float4*)in)[i];
    float vv[4] = {v.x, v.y, v.z, v.w};
    union { unsigned long long u; __half h[4]; } H, L;
#pragma unroll
    for (int j = 0; j < 4; j++) {
        __half h = __float2half_rn(vv[j]);
        H.h[j] = h;
        L.h[j] = __float2half_rn(vv[j] - __half2float(h));
    }
    ((unsigned long long*)hi)[i] = H.u;
    ((unsigned long long*)lo)[i] = L.u;
}
__global__ __launch_bounds__(256) void convert_f16(
    const float* __restrict__ in, __half* __restrict__ out, long long total4)
{
    long long i = (long long)blockIdx.x * 256 + threadIdx.x;
    if (i >= total4) return;
    float4 v = ((const float4*)in)[i];
    float vv[4] = {v.x, v.y, v.z, v.w};
    union { unsigned long long u; __half h[4]; } H;
#pragma unroll
    for (int j = 0; j < 4; j++) H.h[j] = __float2half_rn(vv[j]);
    ((unsigned long long*)out)[i] = H.u;
}

// ---------------- fp16 2-term mma.sync GEMM: C = A * B^T ---------------------
// CTA 128x128, 4 warps (2x2), warp tile 64x64. K = 4096, KC = 64.
// mode 0: plain fp32 store to C. mode 1: fused RoPE/scale/split QKV epilogue.
#define GK       4096
#define NCHUNK   (GK / 64)               // 64
#define PTILEB   (128 * 128)             // 16384 per part-tile
#define STAGEB   (3 * PTILEB)            // 49152
#define GEMM_SMEM (2 * STAGEB)           // 98304

__global__ __launch_bounds__(128, 2) void gemm_mma(
    const __half* __restrict__ Ah, const __half* __restrict__ Al,
    const __half* __restrict__ Bh, float* __restrict__ C, int N, int mode,
    const float* __restrict__ cosf_, const float* __restrict__ sinf_,
    float* __restrict__ kcache, float* __restrict__ vcache,
    __nv_bfloat16* __restrict__ qhi, __nv_bfloat16* __restrict__ qlo,
    __nv_bfloat16* __restrict__ khi, __nv_bfloat16* __restrict__ klo,
    __nv_bfloat16* __restrict__ vhi, __nv_bfloat16* __restrict__ vlo)
{
    extern __shared__ __align__(128) char smraw[];
    const uint32_t sb = (uint32_t)__cvta_generic_to_shared(smraw);

    const int tid = threadIdx.x;
    const int w   = tid >> 5;
    const int l   = tid & 31;
    const int wm  = w & 1;          // 0-1 : 64-row slab
    const int wn  = w >> 1;         // 0-1 : 64-col slab

    const size_t arow_g = (size_t)blockIdx.y * 128 * GK;
    const size_t brow_g = (size_t)blockIdx.x * 128 * GK;
    const char* gp[3] = { (const char*)(Ah + arow_g), (const char*)(Al + arow_g),
                          (const char*)(Bh + brow_g) };

    auto load_chunk = [&](int t, uint32_t st) {
        const size_t gk = (size_t)t * 128;
#pragma unroll
        for (int part = 0; part < 3; part++) {
#pragma unroll
            for (int j = 0; j < 8; j++) {
                int slot = tid + j * 128;
                int r = slot >> 3, c = slot & 7;
                uint32_t dc = (uint32_t)((c ^ (r & 7)) * 16);
                cp16(st + part * PTILEB + r * 128 + dc,
                     gp[part] + (size_t)r * (GK * 2) + gk + c * 16);
            }
        }
    };

    const int arow = wm * 64 + (l & 15);
    const uint32_t arb  = (uint32_t)(arow * 128);
    const int axor = arow & 7;
    const int ac0 = (l >> 4);
    const int l2 = l & 7, sel = l >> 3;
    const int brow = wn * 64 + (sel >> 1) * 8 + l2;
    const uint32_t brb  = (uint32_t)(brow * 128);
    const int bxor = brow & 7;
    const int bc0 = (sel & 1);

    float acc[4][8][4];
#pragma unroll
    for (int mt = 0; mt < 4; mt++)
#pragma unroll
        for (int nt = 0; nt < 8; nt++)
#pragma unroll
            for (int i = 0; i < 4; i++) acc[mt][nt][i] = 0.f;

    load_chunk(0, sb);
    asm volatile("cp.async.commit_group;" ::: "memory");

    for (int k = 0; k < NCHUNK; k++) {
        asm volatile("cp.async.wait_group 0;" ::: "memory");
        __syncthreads();
        if (k + 1 < NCHUNK) {
            load_chunk(k + 1, sb + ((k + 1) & 1) * STAGEB);
            asm volatile("cp.async.commit_group;" ::: "memory");
        }

        const uint32_t st = sb + (k & 1) * STAGEB;
#pragma unroll
        for (int ks = 0; ks < 4; ks++) {
            const uint32_t ach = (uint32_t)(((ks * 2 + ac0) ^ axor) * 16);
            const uint32_t bch = (uint32_t)(((ks * 2 + bc0) ^ bxor) * 16);

            uint32_t ah[4][4], bh[8][2];
#pragma unroll
            for (int mt = 0; mt < 4; mt++)
                ldm4(ah[mt][0], ah[mt][1], ah[mt][2], ah[mt][3],
                     st + arb + mt * 2048 + ach);
#pragma unroll
            for (int np = 0; np < 4; np++)
                ldm4(bh[2*np][0], bh[2*np][1], bh[2*np+1][0], bh[2*np+1][1],
                     st + 2 * PTILEB + brb + np * 2048 + bch);
#pragma unroll
            for (int mt = 0; mt < 4; mt++)
#pragma unroll
                for (int nt = 0; nt < 8; nt++)
                    mma_f16(acc[mt][nt], ah[mt], bh[nt]);

            uint32_t al[4][4];
#pragma unroll
            for (int mt = 0; mt < 4; mt++)
                ldm4(al[mt][0], al[mt][1], al[mt][2], al[mt][3],
                     st + PTILEB + arb + mt * 2048 + ach);
#pragma unroll
            for (int mt = 0; mt < 4; mt++)
#pragma unroll
                for (int nt = 0; nt < 8; nt++)
                    mma_f16(acc[mt][nt], al[mt], bh[nt]);
        }
    }

    const int crow = blockIdx.y * 128 + wm * 64 + (l >> 2);
    const int ccolbase = wn * 64 + (l & 3) * 2;   // col within 128-wide block

    if (mode == 0) {
        const int ccol = blockIdx.x * 128 + ccolbase;
#pragma unroll
        for (int mt = 0; mt < 4; mt++) {
#pragma unroll
            for (int nt = 0; nt < 8; nt++) {
                float* p0 = C + (size_t)(crow + mt * 16)     * N + ccol + nt * 8;
                float* p1 = C + (size_t)(crow + mt * 16 + 8) * N + ccol + nt * 8;
                *(float2*)p0 = make_float2(acc[mt][nt][0], acc[mt][nt][1]);
                *(float2*)p1 = make_float2(acc[mt][nt][2], acc[mt][nt][3]);
            }
        }
        return;
    }

    // ---- mode 1: fused QKV epilogue (one head per CTA column block) --------
    const int bx = blockIdx.x;
#pragma unroll
    for (int mt = 0; mt < 4; mt++) {
#pragma unroll
        for (int j = 0; j < 2; j++) {
            const int s = crow + mt * 16 + j * 8;
#pragma unroll
            for (int nt = 0; nt < 8; nt++) {
                float v0 = acc[mt][nt][j * 2 + 0];
                float v1 = acc[mt][nt][j * 2 + 1];
                const int d = ccolbase + nt * 8;
                if (bx < NH) {                      // Q head bx: rope + scale
                    const int f = d >> 1;
                    float c  = __ldg(cosf_ + s * 64 + f);
                    float sn = __ldg(sinf_ + s * 64 + f);
                    float o1 = (v0 * c - v1 * sn) * SCALE;
                    float o2 = (v0 * sn + v1 * c) * SCALE;
                    size_t o = ((size_t)bx * SEQLEN + s) * HD + d;
                    __nv_bfloat162 h2, l2v;
                    split2bf(o1, o2, h2, l2v);
                    *(__nv_bfloat162*)(qhi + o) = h2;
                    *(__nv_bfloat162*)(qlo + o) = l2v;
                } else if (bx < NH + NKV) {          // K head bx-32: rope+cache
                    const int kvh = bx - NH;
                    const int f = d >> 1;
                    float c  = __ldg(cosf_ + s * 64 + f);
                    float sn = __ldg(sinf_ + s * 64 + f);
                    float o1 = v0 * c - v1 * sn;
                    float o2 = v0 * sn + v1 * c;
                    *(float2*)(kcache + (size_t)s * KV_ROW + kvh * HD + d) =
                        make_float2(o1, o2);
                    size_t o = ((size_t)kvh * SEQLEN + s) * HD + d;
                    __nv_bfloat162 h2, l2v;
                    split2bf(o1, o2, h2, l2v);
                    *(__nv_bfloat162*)(khi + o) = h2;
                    *(__nv_bfloat162*)(klo + o) = l2v;
                } else {                             // V head bx-40: copy+cache
                    const int kvh = bx - NH - NKV;
                    *(float2*)(vcache + (size_t)s * KV_ROW + kvh * HD + d) =
                        make_float2(v0, v1);
                    size_t o = ((size_t)kvh * SEQLEN + s) * HD + d;
                    __nv_bfloat162 h2, l2v;
                    split2bf(v0, v1, h2, l2v);
                    *(__nv_bfloat162*)(vhi + o) = h2;
                    *(__nv_bfloat162*)(vlo + o) = l2v;
                }
            }
        }
    }
}

// ---------------- tensor-core causal flash attention (double-buffered) ------
#define ASTRIDE 272
#define ATILE   (64 * ASTRIDE)
#define ABUF    (4 * ATILE)
#define ATTN_SMEM (2 * ABUF)

__global__ __launch_bounds__(256, 1) void attn_tc(
    const __nv_bfloat16* __restrict__ Qh, const __nv_bfloat16* __restrict__ Ql,
    const __nv_bfloat16* __restrict__ Kh, const __nv_bfloat16* __restrict__ Kl,
    const __nv_bfloat16* __restrict__ Vh, const __nv_bfloat16* __restrict__ Vl,
    __half* __restrict__ OH, __half* __restrict__ OL)
{
    extern __shared__ __align__(128) char smraw[];
    const uint32_t sb = (uint32_t)__cvta_generic_to_shared(smraw);
    const int tid = threadIdx.x, w = tid >> 5, l = tid & 31;
    const int qt  = (int)gridDim.x - 1 - (int)blockIdx.x;
    const int h   = blockIdx.y;
    const int kvh = h >> 2;

    uint32_t qh_[8][4], ql_[8][4];
    {
        const uint32_t aoff = sb + (uint32_t)((w * 16 + (l & 15)) * ASTRIDE
                                              + (l >> 4) * 16);
        for (int part = 0; part < 2; part++) {
            const __nv_bfloat16* src = part ? Ql : Qh;
            const char* g0 = (const char*)(src + ((size_t)h * SEQLEN + qt * 128) * HD);
            for (int i = tid; i < 2048; i += 256)
                cp16(sb + (uint32_t)((i >> 4) * ASTRIDE + (i & 15) * 16),
                     g0 + (size_t)i * 16);
            asm volatile("cp.async.commit_group;" ::: "memory");
            asm volatile("cp.async.wait_group 0;" ::: "memory");
            __syncthreads();
            uint32_t (*dst)[4] = part ? ql_ : qh_;
#pragma unroll
            for (int g = 0; g < 8; g++)
                ldm4(dst[g][0], dst[g][1], dst[g][2], dst[g][3], aoff + g * 32);
            __syncthreads();
        }
    }

    float o[16][4];
#pragma unroll
    for (int t = 0; t < 16; t++)
#pragma unroll
        for (int i = 0; i < 4; i++) o[t][i] = 0.f;
    float m0 = -1e30f, m1 = -1e30f, l0 = 0.f, l1 = 0.f;

    const int row0 = qt * 128 + w * 16 + (l >> 2);
    const int l2 = l & 7, sel = l >> 3;
    const int nkb = 2 * qt + 2;

    auto load_kv = [&](int kb, uint32_t bufbase) {
        const size_t gbase = (((size_t)kvh * SEQLEN + (size_t)kb * 64) * HD) * 2;
        for (int i = tid; i < 1024; i += 256) {
            uint32_t soff = (uint32_t)((i >> 4) * ASTRIDE + (i & 15) * 16);
            size_t goff = gbase + (size_t)i * 16;
            cp16(bufbase + 0 * ATILE + soff, (const char*)Kh + goff);
            cp16(bufbase + 1 * ATILE + soff, (const char*)Kl + goff);
            cp16(bufbase + 2 * ATILE + soff, (const char*)Vh + goff);
            cp16(bufbase + 3 * ATILE + soff, (const char*)Vl + goff);
        }
        asm volatile("cp.async.commit_group;" ::: "memory");
    };

    int buf = 0;
    load_kv(0, sb);

    for (int kb = 0; kb < nkb; kb++) {
        if (kb + 1 < nkb) {
            load_kv(kb + 1, sb + (buf ^ 1) * ABUF);
            asm volatile("cp.async.wait_group 1;" ::: "memory");
        } else {
            asm volatile("cp.async.wait_group 0;" ::: "memory");
        }
        __syncthreads();
        const uint32_t bbase = sb + buf * ABUF;

        float sc[8][4];
#pragma unroll
        for (int t = 0; t < 8; t++)
#pragma unroll
            for (int i = 0; i < 4; i++) sc[t][i] = 0.f;

#pragma unroll
        for (int g = 0; g < 8; g++) {
#pragma unroll
            for (int n16 = 0; n16 < 4; n16++) {
                uint32_t kaddr = bbase + (uint32_t)((n16 * 16 + (sel >> 1) * 8 + l2)
                                                    * ASTRIDE + (sel & 1) * 16 + g * 32);
                uint32_t bh[2][2], bl[2][2];
                ldm4(bh[0][0], bh[0][1], bh[1][0], bh[1][1], kaddr);
                ldm4(bl[0][0], bl[0][1], bl[1][0], bl[1][1], kaddr + ATILE);
#pragma unroll
                for (int j = 0; j < 2; j++) {
                    int t = n16 * 2 + j;
                    mma_bf16(sc[t], qh_[g], bh[j]);
                    mma_bf16(sc[t], ql_[g], bh[j]);
                    mma_bf16(sc[t], qh_[g], bl[j]);
                }
            }
        }

        if (kb >= 2 * qt) {
#pragma unroll
            for (int t = 0; t < 8; t++) {
                int col = kb * 64 + t * 8 + 2 * (l & 3);
                if (col     > row0)     sc[t][0] = -1e30f;
                if (col + 1 > row0)     sc[t][1] = -1e30f;
                if (col     > row0 + 8) sc[t][2] = -1e30f;
                if (col + 1 > row0 + 8) sc[t][3] = -1e30f;
            }
        }

        float r0m = -1e30f, r1m = -1e30f;
#pragma unroll
        for (int t = 0; t < 8; t++) {
            r0m = fmaxf(r0m, fmaxf(sc[t][0], sc[t][1]));
            r1m = fmaxf(r1m, fmaxf(sc[t][2], sc[t][3]));
        }
        r0m = fmaxf(r0m, __shfl_xor_sync(0xffffffffu, r0m, 1));
        r0m = fmaxf(r0m, __shfl_xor_sync(0xffffffffu, r0m, 2));
        r1m = fmaxf(r1m, __shfl_xor_sync(0xffffffffu, r1m, 1));
        r1m = fmaxf(r1m, __shfl_xor_sync(0xffffffffu, r1m, 2));
        float nm0 = fmaxf(m0, r0m), nm1 = fmaxf(m1, r1m);
        float a0 = __expf(m0 - nm0), a1 = __expf(m1 - nm1);

        float s0 = 0.f, s1 = 0.f;
#pragma unroll
        for (int t = 0; t < 8; t++) {
            sc[t][0] = __expf(sc[t][0] - nm0); s0 += sc[t][0];
            sc[t][1] = __expf(sc[t][1] - nm0); s0 += sc[t][1];
            sc[t][2] = __expf(sc[t][2] - nm1); s1 += sc[t][2];
            sc[t][3] = __expf(sc[t][3] - nm1); s1 += sc[t][3];
        }
        s0 += __shfl_xor_sync(0xffffffffu, s0, 1);
        s0 += __shfl_xor_sync(0xffffffffu, s0, 2);
        s1 += __shfl_xor_sync(0xffffffffu, s1, 1);
        s1 += __shfl_xor_sync(0xffffffffu, s1, 2);
        l0 = l0 * a0 + s0;
        l1 = l1 * a1 + s1;
        m0 = nm0; m1 = nm1;
#pragma unroll
        for (int t = 0; t < 16; t++) {
            o[t][0] *= a0; o[t][1] *= a0;
            o[t][2] *= a1; o[t][3] *= a1;
        }

#pragma unroll
        for (int g = 0; g < 4; g++) {
            uint32_t aph[4], apl[4];
            split2(sc[2*g][0],   sc[2*g][1],   aph[0], apl[0]);
            split2(sc[2*g][2],   sc[2*g][3],   aph[1], apl[1]);
            split2(sc[2*g+1][0], sc[2*g+1][1], aph[2], apl[2]);
            split2(sc[2*g+1][2], sc[2*g+1][3], aph[3], apl[3]);
#pragma unroll
            for (int n16 = 0; n16 < 8; n16++) {
                uint32_t vaddr = bbase + 2 * ATILE
                    + (uint32_t)((g * 16 + (l & 15)) * ASTRIDE
                                 + n16 * 32 + (l >> 4) * 16);
                uint32_t bvh[2][2], bvl[2][2];
                ldm4t(bvh[0][0], bvh[0][1], bvh[1][0], bvh[1][1], vaddr);
                ldm4t(bvl[0][0], bvl[0][1], bvl[1][0], bvl[1][1], vaddr + ATILE);
#pragma unroll
                for (int j = 0; j < 2; j++) {
                    int t = n16 * 2 + j;
                    mma_bf16(o[t], aph, bvh[j]);
                    mma_bf16(o[t], apl, bvh[j]);
                    mma_bf16(o[t], aph, bvl[j]);
                }
            }
        }
        __syncthreads();
        buf ^= 1;
    }

    float i0 = 1.f / l0, i1 = 1.f / l1;
    const int colb = h * HD + 2 * (l & 3);
#pragma unroll
    for (int t = 0; t < 16; t++) {
        {
            float v0 = o[t][0] * i0, v1 = o[t][1] * i0;
            __half h0 = __float2half_rn(v0), h1 = __float2half_rn(v1);
            __half e0 = __float2half_rn(v0 - __half2float(h0));
            __half e1 = __float2half_rn(v1 - __half2float(h1));
            size_t off = (size_t)row0 * DIM + colb + t * 8;
            *(__half2*)(OH + off) = __halves2half2(h0, h1);
            *(__half2*)(OL + off) = __halves2half2(e0, e1);
        }
        {
            float v0 = o[t][2] * i1, v1 = o[t][3] * i1;
            __half h0 = __float2half_rn(v0), h1 = __float2half_rn(v1);
            __half e0 = __float2half_rn(v0 - __half2float(h0));
            __half e1 = __float2half_rn(v1 - __half2float(h1));
            size_t off = (size_t)(row0 + 8) * DIM + colb + t * 8;
            *(__half2*)(OH + off) = __halves2half2(h0, h1);
            *(__half2*)(OL + off) = __halves2half2(e0, e1);
        }
    }
}

// ---------------- launch ----------------------------------------------------
extern "C" void kernel_launch(void* const* d_in, const int* in_sizes, int n_in,
                              void* d_out, int out_size)
{
    const float* x     = (const float*)d_in[0];
    const float* cosf_ = (const float*)d_in[1];
    const float* sinf_ = (const float*)d_in[2];
    const float* in_ck = (const float*)d_in[5];
    const float* in_cv = (const float*)d_in[6];
    const float* Wqkv  = (const float*)d_in[7];
    const float* Wo    = (const float*)d_in[8];

    float* out     = (float*)d_out;
    float* cache_k = out + (size_t)SEQLEN * DIM;
    float* cache_v = cache_k + (size_t)WIN * KV_ROW;

    __half *xh_p, *xl_p, *ah_p, *al_p, *wq_p, *wo_p;
    __nv_bfloat16 *qhi_p, *qlo_p, *khi_p, *klo_p, *vhi_p, *vlo_p;
    cudaGetSymbolAddress((void**)&xh_p,   g_xh);
    cudaGetSymbolAddress((void**)&xl_p,   g_xl);
    cudaGetSymbolAddress((void**)&ah_p,   g_ah);
    cudaGetSymbolAddress((void**)&al_p,   g_al);
    cudaGetSymbolAddress((void**)&wq_p,   g_wq);
    cudaGetSymbolAddress((void**)&wo_p,   g_wo);
    cudaGetSymbolAddress((void**)&qhi_p,  g_qhi);
    cudaGetSymbolAddress((void**)&qlo_p,  g_qlo);
    cudaGetSymbolAddress((void**)&khi_p,  g_khi);
    cudaGetSymbolAddress((void**)&klo_p,  g_klo);
    cudaGetSymbolAddress((void**)&vhi_p,  g_vhi);
    cudaGetSymbolAddress((void**)&vlo_p,  g_vlo);

    // rope/epilogue writes cache rows [0, SEQLEN); copy only [SEQLEN, WIN)
    size_t half_elems = (size_t)SEQLEN * KV_ROW;
    size_t half_bytes = half_elems * sizeof(float);
    cudaMemcpyAsync(cache_k + half_elems, in_ck + half_elems, half_bytes,
                    cudaMemcpyDeviceToDevice, 0);
    cudaMemcpyAsync(cache_v + half_elems, in_cv + half_elems, half_bytes,
                    cudaMemcpyDeviceToDevice, 0);

    cudaFuncSetAttribute(gemm_mma, cudaFuncAttributeMaxDynamicSharedMemorySize,
                         GEMM_SMEM);
    cudaFuncSetAttribute(attn_tc, cudaFuncAttributeMaxDynamicSharedMemorySize,
                         ATTN_SMEM);

    {
        long long t4;
        t4 = (long long)SEQLEN * DIM / 4;
        convert_hilo_f16<<<(unsigned)((t4 + 255) / 256), 256>>>(x, xh_p, xl_p, t4);
        t4 = (long long)QKV_N * DIM / 4;
        convert_f16<<<(unsigned)((t4 + 255) / 256), 256>>>(Wqkv, wq_p, t4);
        t4 = (long long)DIM * DIM / 4;
        convert_f16<<<(unsigned)((t4 + 255) / 256), 256>>>(Wo, wo_p, t4);
    }

    // 1) QKV projection with fused RoPE/scale/cache/split epilogue (mode 1)
    gemm_mma<<<dim3(QKV_N / 128, SEQLEN / 128), 128, GEMM_SMEM>>>(
        xh_p, xl_p, wq_p, nullptr, QKV_N, 1,
        cosf_, sinf_, cache_k, cache_v,
        qhi_p, qlo_p, khi_p, klo_p, vhi_p, vlo_p);

    // 2) tensor-core causal flash attention, fp16 hi/lo epilogue
    attn_tc<<<dim3(SEQLEN / 128, NH), 256, ATTN_SMEM>>>(
        qhi_p, qlo_p, khi_p, klo_p, vhi_p, vlo_p, ah_p, al_p);

    // 3) output projection (mode 0, plain fp32 store)
    gemm_mma<<<dim3(DIM / 128, SEQLEN / 128), 128, GEMM_SMEM>>>(
        ah_p, al_p, wo_p, out, DIM, 0,
        nullptr, nullptr, nullptr, nullptr,
        nullptr, nullptr, nullptr, nullptr, nullptr, nullptr);
}